// round 7
// baseline (speedup 1.0000x reference)
#include <cuda_runtime.h>
#include <math.h>
#include <stdint.h>
#include <stddef.h>

// Problem dims (fixed by the dataset)
#define NS   4096      // batch
#define TS   64        // timesteps
#define FI   32        // input features
#define HD   128       // hidden
#define GD   384       // 3*H
#define NK   20        // top-k
#define SLOPE_F 0.2f
#define GRROWS 28      // batch rows per GRU CTA (147 CTAs -> all 148 SMs)

typedef unsigned long long ull;

// ---------------- f32x2 packed helpers (Blackwell FFMA2) --------------------
__device__ __forceinline__ ull pack2(float lo, float hi) {
    ull r;
    asm("mov.b64 %0, {%1, %2};" : "=l"(r) : "f"(lo), "f"(hi));
    return r;
}
__device__ __forceinline__ float2 unpack2(ull v) {
    float2 r;
    asm("mov.b64 {%0, %1}, %2;" : "=f"(r.x), "=f"(r.y) : "l"(v));
    return r;
}
__device__ __forceinline__ void ffma2(ull& d, ull a, ull b) {
    asm("fma.rn.f32x2 %0, %1, %2, %0;" : "+l"(d) : "l"(a), "l"(b));
}

// ---------------- cp.async helpers -----------------------------------------
__device__ __forceinline__ void cp16(float* dst_sh, const float* src_g) {
    uint32_t d = (uint32_t)__cvta_generic_to_shared(dst_sh);
    asm volatile("cp.async.ca.shared.global [%0], [%1], 16;" :: "r"(d), "l"(src_g));
}
__device__ __forceinline__ void cp_commit() {
    asm volatile("cp.async.commit_group;");
}
__device__ __forceinline__ void cp_wait_all() {
    asm volatile("cp.async.wait_all;");
}

// ---------------- scratch (device globals; no runtime allocation) ----------
__device__ float d_gi[(size_t)NS * TS * GD];
__device__ float d_h0[(size_t)NS * TS * HD];
__device__ float d_g  [NS * HD];
__device__ float d_gn [NS * HD];
__device__ float d_sim[(size_t)NS * NS];
__device__ int   d_tidx[NS * NK];
__device__ float d_tval[NS * NK];
__device__ float d_colsum[NS];
__device__ float d_colZ[NS];
__device__ float d_valid[NS];
__device__ float d_concept[NS * HD];
__device__ float d_cf [NS * HD];
__device__ float d_cfn[NS * HD];
__device__ float d_hsb[NS * HD];
__device__ float d_t1 [NS * HD];
__device__ float d_t2 [NS * HD];
__device__ float d_t3 [NS * HD];
__device__ float d_t4 [NS * HD];

// ---------------- fp32 GEMM: 128x64 tile, 256 thr, 8x4 micro, FFMA2 ---------
template<bool TRANSB, bool ACT>
__global__ __launch_bounds__(256) void k_gemm(
    const float* __restrict__ A, const float* __restrict__ B,
    const float* __restrict__ bias, const float* __restrict__ rs,
    float* __restrict__ C, int M, int N, int K, int ksplit)
{
    __shared__ alignas(16) float As[16][132];
    __shared__ alignas(16) float Bs[16][68];
    const int bm = blockIdx.y * 128, bn = blockIdx.x * 64;
    const int tid = threadIdx.x;
    const int kbase = blockIdx.z * ksplit;

    const int a_m = tid >> 1, a_k = (tid & 1) * 8;
    const int ty = tid >> 4, tx = tid & 15;
    const int m0 = ty * 8, n0 = tx * 4;

    ull acc2[4][4];
    #pragma unroll
    for (int p = 0; p < 4; p++)
        #pragma unroll
        for (int j = 0; j < 4; j++) acc2[p][j] = 0ull;

    for (int k0 = kbase; k0 < kbase + ksplit; k0 += 16) {
        const float* Ap = A + (size_t)(bm + a_m) * K + k0 + a_k;
        float4 av0 = *(const float4*)(Ap);
        float4 av1 = *(const float4*)(Ap + 4);
        As[a_k + 0][a_m] = av0.x; As[a_k + 1][a_m] = av0.y;
        As[a_k + 2][a_m] = av0.z; As[a_k + 3][a_m] = av0.w;
        As[a_k + 4][a_m] = av1.x; As[a_k + 5][a_m] = av1.y;
        As[a_k + 6][a_m] = av1.z; As[a_k + 7][a_m] = av1.w;
        if (TRANSB) {
            const int b_n = tid >> 2, b_k = (tid & 3) * 4;
            float4 bv = *(const float4*)(B + (size_t)(bn + b_n) * K + k0 + b_k);
            Bs[b_k + 0][b_n] = bv.x; Bs[b_k + 1][b_n] = bv.y;
            Bs[b_k + 2][b_n] = bv.z; Bs[b_k + 3][b_n] = bv.w;
        } else {
            const int b_k = tid >> 4, b_n4 = (tid & 15) * 4;
            *(float4*)&Bs[b_k][b_n4] =
                *(const float4*)(B + (size_t)(k0 + b_k) * N + bn + b_n4);
        }
        __syncthreads();
        #pragma unroll
        for (int kk = 0; kk < 16; kk++) {
            ulonglong2 aP01 = *(const ulonglong2*)&As[kk][m0];
            ulonglong2 aP23 = *(const ulonglong2*)&As[kk][m0 + 4];
            float4 b = *(const float4*)&Bs[kk][n0];
            ull bd0 = pack2(b.x, b.x), bd1 = pack2(b.y, b.y);
            ull bd2 = pack2(b.z, b.z), bd3 = pack2(b.w, b.w);
            ffma2(acc2[0][0], aP01.x, bd0); ffma2(acc2[0][1], aP01.x, bd1);
            ffma2(acc2[0][2], aP01.x, bd2); ffma2(acc2[0][3], aP01.x, bd3);
            ffma2(acc2[1][0], aP01.y, bd0); ffma2(acc2[1][1], aP01.y, bd1);
            ffma2(acc2[1][2], aP01.y, bd2); ffma2(acc2[1][3], aP01.y, bd3);
            ffma2(acc2[2][0], aP23.x, bd0); ffma2(acc2[2][1], aP23.x, bd1);
            ffma2(acc2[2][2], aP23.x, bd2); ffma2(acc2[2][3], aP23.x, bd3);
            ffma2(acc2[3][0], aP23.y, bd0); ffma2(acc2[3][1], aP23.y, bd1);
            ffma2(acc2[3][2], aP23.y, bd2); ffma2(acc2[3][3], aP23.y, bd3);
        }
        __syncthreads();
    }

    float* Cw = C + (size_t)blockIdx.z * ((size_t)M * N);
    #pragma unroll
    for (int p = 0; p < 4; p++) {
        int rowA = bm + m0 + 2 * p;
        int rowB = rowA + 1;
        float rsA = rs ? rs[rowA] : 1.f;
        float rsB = rs ? rs[rowB] : 1.f;
        float va[4], vb[4];
        #pragma unroll
        for (int j = 0; j < 4; j++) {
            float2 v = unpack2(acc2[p][j]);
            float a = v.x, b = v.y;
            if (bias) { float bj = bias[bn + n0 + j]; a += bj; b += bj; }
            if (ACT) {
                a = a > 0.f ? a : SLOPE_F * a;
                b = b > 0.f ? b : SLOPE_F * b;
            }
            va[j] = a * rsA; vb[j] = b * rsB;
        }
        *(float4*)(Cw + (size_t)rowA * N + bn + n0) =
            make_float4(va[0], va[1], va[2], va[3]);
        *(float4*)(Cw + (size_t)rowB * N + bn + n0) =
            make_float4(vb[0], vb[1], vb[2], vb[3]);
    }
}

// ---------------- fp32 GEMM: 64x64 tile (for NS x 128 x 128 head GEMMs) -----
template<bool ACT, bool SUBPRE>
__global__ __launch_bounds__(256) void k_gemm64(
    const float* __restrict__ A, const float* __restrict__ B,
    const float* __restrict__ bias, const float* __restrict__ rs,
    const float* __restrict__ pre, float* __restrict__ C,
    int M, int N, int K)
{
    __shared__ alignas(16) float As[16][68];
    __shared__ alignas(16) float Bs[16][68];
    const int bm = blockIdx.y * 64, bn = blockIdx.x * 64;
    const int tid = threadIdx.x;
    const int a_m = tid >> 2, a_k = (tid & 3) * 4;
    const int ty = tid >> 4, tx = tid & 15;
    const int m0 = ty * 4, n0 = tx * 4;

    ull acc2[2][4];
    #pragma unroll
    for (int p = 0; p < 2; p++)
        #pragma unroll
        for (int j = 0; j < 4; j++) acc2[p][j] = 0ull;

    for (int k0 = 0; k0 < K; k0 += 16) {
        float4 av = *(const float4*)(A + (size_t)(bm + a_m) * K + k0 + a_k);
        As[a_k + 0][a_m] = av.x; As[a_k + 1][a_m] = av.y;
        As[a_k + 2][a_m] = av.z; As[a_k + 3][a_m] = av.w;
        float4 bv = *(const float4*)(B + (size_t)(bn + a_m) * K + k0 + a_k);
        Bs[a_k + 0][a_m] = bv.x; Bs[a_k + 1][a_m] = bv.y;
        Bs[a_k + 2][a_m] = bv.z; Bs[a_k + 3][a_m] = bv.w;
        __syncthreads();
        #pragma unroll
        for (int kk = 0; kk < 16; kk++) {
            ulonglong2 aP = *(const ulonglong2*)&As[kk][m0];
            float4 b = *(const float4*)&Bs[kk][n0];
            ull bd0 = pack2(b.x, b.x), bd1 = pack2(b.y, b.y);
            ull bd2 = pack2(b.z, b.z), bd3 = pack2(b.w, b.w);
            ffma2(acc2[0][0], aP.x, bd0); ffma2(acc2[0][1], aP.x, bd1);
            ffma2(acc2[0][2], aP.x, bd2); ffma2(acc2[0][3], aP.x, bd3);
            ffma2(acc2[1][0], aP.y, bd0); ffma2(acc2[1][1], aP.y, bd1);
            ffma2(acc2[1][2], aP.y, bd2); ffma2(acc2[1][3], aP.y, bd3);
        }
        __syncthreads();
    }

    #pragma unroll
    for (int p = 0; p < 2; p++) {
        int rowA = bm + m0 + 2 * p;
        int rowB = rowA + 1;
        float rsA = rs ? rs[rowA] : 1.f;
        float rsB = rs ? rs[rowB] : 1.f;
        float va[4], vb[4];
        #pragma unroll
        for (int j = 0; j < 4; j++) {
            float2 v = unpack2(acc2[p][j]);
            float a = v.x, b = v.y;
            if (bias) { float bj = bias[bn + n0 + j]; a += bj; b += bj; }
            if (ACT) {
                a = a > 0.f ? a : SLOPE_F * a;
                b = b > 0.f ? b : SLOPE_F * b;
            }
            a *= rsA; b *= rsB;
            if (SUBPRE) {
                a = pre[(size_t)rowA * N + bn + n0 + j] - a;
                b = pre[(size_t)rowB * N + bn + n0 + j] - b;
            }
            va[j] = a; vb[j] = b;
        }
        *(float4*)(C + (size_t)rowA * N + bn + n0) =
            make_float4(va[0], va[1], va[2], va[3]);
        *(float4*)(C + (size_t)rowB * N + bn + n0) =
            make_float4(vb[0], vb[1], vb[2], vb[3]);
    }
}

// reduce over split-K partial slices: C = sum_z P[z]
__global__ void k_reduce(const float* __restrict__ P, float* __restrict__ C,
                         int nslice, int total4)
{
    int i = blockIdx.x * blockDim.x + threadIdx.x;
    if (i >= total4) return;
    size_t b = (size_t)i * 4;
    float4 s = make_float4(0.f, 0.f, 0.f, 0.f);
    for (int z = 0; z < nslice; z++) {
        float4 v = *(const float4*)(P + (size_t)z * total4 * 4 + b);
        s.x += v.x; s.y += v.y; s.z += v.z; s.w += v.w;
    }
    *(float4*)(C + b) = s;
}

// ---------------- persistent GRU recurrent kernel: 768 thr, k-split ---------
// Thread (o, half): output unit o in [0,384), k-half in {0,1}. Each thread
// owns HALF of Whh row o (64 floats = 32 packed pairs) in registers.
// Partial dots go to ghA (half 0, +bias) / ghB (half 1); gate phase sums them.
// 24 warps/SM for latency hiding; gi prefetched via cp.async.
template<bool WRITE_SEQ>
__global__ __launch_bounds__(768, 1) void k_gru(
    const float* __restrict__ gi, const float* __restrict__ Whh,
    const float* __restrict__ bhh, float* __restrict__ hout)
{
    extern __shared__ float sm[];
    float* h_sh = sm;                          // GRROWS*128
    float* ghA  = sm + GRROWS * HD;            // GRROWS*384
    float* ghB  = ghA + GRROWS * GD;           // GRROWS*384
    float* gi_sh = ghB + GRROWS * GD;          // GRROWS*384
    const int tid = threadIdx.x;
    const int half = (tid >= 384) ? 1 : 0;
    const int o = tid - half * 384;
    const int base = blockIdx.x * GRROWS;
    const int rows = (NS - base < GRROWS) ? (NS - base) : GRROWS;
    float* ghOut = half ? ghB : ghA;

    // thread's half of Whh row o: 64 floats = 16 ulonglong2 = 32 packed pairs
    ull wq[32];
    {
        const ulonglong2* wg =
            (const ulonglong2*)(Whh + (size_t)o * HD + half * 64);
        #pragma unroll
        for (int q = 0; q < 16; q++) {
            ulonglong2 tv = wg[q];
            wq[2 * q] = tv.x; wq[2 * q + 1] = tv.y;
        }
    }
    const float bo = half ? 0.f : bhh[o];
    for (int idx = tid; idx < rows * HD; idx += 768) h_sh[idx] = 0.f;

    // gi prefetch: 28*96 float4 slots, 4 strided chunks per thread
    #define GI_SLOTS (GRROWS * 96)
    {
        #pragma unroll
        for (int i = 0; i < 4; i++) {
            int s = tid + i * 768;
            if (s < GI_SLOTS) {
                int pr = s / 96, f = s % 96;
                if (pr < rows)
                    cp16(gi_sh + pr * GD + f * 4,
                         gi + ((size_t)(base + pr) * TS + 0) * GD + f * 4);
            }
        }
        cp_commit();
    }
    __syncthreads();

    for (int t = 0; t < TS; t++) {
        // partial matvec: ghOut[r,o] = h[r, 64h:64h+64] . wq (+bias on half 0)
        #pragma unroll 1
        for (int r = 0; r < rows; r++) {
            const ulonglong2* hp =
                (const ulonglong2*)(h_sh + r * HD + half * 64);
            ull a0 = 0ull, a1 = 0ull;
            #pragma unroll
            for (int q = 0; q < 16; q += 2) {
                ulonglong2 x0 = hp[q], x1 = hp[q + 1];
                ffma2(a0, x0.x, wq[2 * q]);
                ffma2(a1, x0.y, wq[2 * q + 1]);
                ffma2(a0, x1.x, wq[2 * q + 2]);
                ffma2(a1, x1.y, wq[2 * q + 3]);
            }
            float2 p0 = unpack2(a0), p1 = unpack2(a1);
            ghOut[r * GD + o] = ((p0.x + p0.y) + (p1.x + p1.y)) + bo;
        }
        cp_wait_all();
        __syncthreads();
        // gate update (sum the two partial buffers)
        #pragma unroll 1
        for (int idx = tid; idx < rows * HD; idx += 768) {
            int r = idx >> 7, j = idx & 127;
            float gir = gi_sh[r * GD + j];
            float giz = gi_sh[r * GD + j + 128];
            float gin = gi_sh[r * GD + j + 256];
            float ghr = ghA[r * GD + j]       + ghB[r * GD + j];
            float ghz = ghA[r * GD + j + 128] + ghB[r * GD + j + 128];
            float ghn = ghA[r * GD + j + 256] + ghB[r * GD + j + 256];
            float rg = __fdividef(1.f, 1.f + __expf(-(gir + ghr)));
            float zg = __fdividef(1.f, 1.f + __expf(-(giz + ghz)));
            float a2 = gin + rg * ghn;
            float ng = 1.f - __fdividef(2.f, __expf(2.f * a2) + 1.f);
            float hprev = h_sh[idx];
            float hn = (1.f - zg) * ng + zg * hprev;
            h_sh[idx] = hn;
            if (WRITE_SEQ)
                hout[((size_t)(base + r) * TS + t) * HD + j] = hn;
            else if (t == TS - 1)
                hout[(size_t)(base + r) * HD + j] = hn;
        }
        __syncthreads();
        // prefetch gi for t+1
        if (t + 1 < TS) {
            #pragma unroll
            for (int i = 0; i < 4; i++) {
                int s = tid + i * 768;
                if (s < GI_SLOTS) {
                    int pr = s / 96, f = s % 96;
                    if (pr < rows)
                        cp16(gi_sh + pr * GD + f * 4,
                             gi + ((size_t)(base + pr) * TS + (t + 1)) * GD + f * 4);
                }
            }
            cp_commit();
        }
    }
    #undef GI_SLOTS
}

// ---------------- small helpers --------------------------------------------
__global__ void k_zero(float* p, int n) {
    int i = blockIdx.x * blockDim.x + threadIdx.x;
    if (i < n) p[i] = 0.f;
}

__global__ void k_rownorm(const float* __restrict__ src, float* __restrict__ dst) {
    int row = blockIdx.x * 8 + (threadIdx.x >> 5);
    int lane = threadIdx.x & 31;
    const float4* s4 = (const float4*)(src + (size_t)row * HD);
    float4 v = s4[lane];
    float ss = v.x*v.x + v.y*v.y + v.z*v.z + v.w*v.w;
    #pragma unroll
    for (int off = 16; off; off >>= 1) ss += __shfl_xor_sync(0xffffffffu, ss, off);
    float n = sqrtf(ss);
    float inv = (n > 0.f) ? 1.f / n : 0.f;
    ((float4*)(dst + (size_t)row * HD))[lane] =
        make_float4(v.x*inv, v.y*inv, v.z*inv, v.w*inv);
}

// top-K=20 per row of |sim| (diag excluded), jax-stable ties (lowest index).
__global__ __launch_bounds__(256) void k_topk(
    const float* __restrict__ sim, int* __restrict__ tidx,
    float* __restrict__ tval, float* __restrict__ colsum)
{
    int i = blockIdx.x;
    __shared__ float sabs[NS];
    __shared__ float wv[8];
    __shared__ int   wi[8];
    const float* row = sim + (size_t)i * NS;
    for (int c = threadIdx.x; c < NS; c += 256)
        sabs[c] = (c == i) ? -1.f : fabsf(row[c]);
    __syncthreads();
    for (int k = 0; k < NK; k++) {
        float bv = -2.f; int bi = 0;
        for (int c = threadIdx.x; c < NS; c += 256) {
            float v = sabs[c];
            if (v > bv) { bv = v; bi = c; }
        }
        #pragma unroll
        for (int off = 16; off; off >>= 1) {
            float ov = __shfl_down_sync(0xffffffffu, bv, off);
            int   oi = __shfl_down_sync(0xffffffffu, bi, off);
            if (ov > bv || (ov == bv && oi < bi)) { bv = ov; bi = oi; }
        }
        if ((threadIdx.x & 31) == 0) { wv[threadIdx.x >> 5] = bv; wi[threadIdx.x >> 5] = bi; }
        __syncthreads();
        if (threadIdx.x == 0) {
            for (int wd = 1; wd < 8; wd++)
                if (wv[wd] > bv || (wv[wd] == bv && wi[wd] < bi)) { bv = wv[wd]; bi = wi[wd]; }
            tidx[i * NK + k] = bi;
            float sv = row[bi];
            tval[i * NK + k] = sv;
            atomicAdd(&colsum[bi], sv);
            sabs[bi] = -2.f;
        }
        __syncthreads();
    }
}

__global__ void k_scatter(const int* __restrict__ tidx, const float* __restrict__ tval,
                          const float* __restrict__ g, float* __restrict__ concept)
{
    int i = blockIdx.x, d = threadIdx.x;
    float gv = g[(size_t)i * HD + d];
    #pragma unroll
    for (int k = 0; k < NK; k++) {
        int c = __ldg(&tidx[i * NK + k]);
        float v = __ldg(&tval[i * NK + k]);
        atomicAdd(&concept[(size_t)c * HD + d], v * gv);
    }
}

__global__ void k_diag_valid(const float* __restrict__ colsum, const float* __restrict__ sim,
                             const float* __restrict__ g, float* __restrict__ concept,
                             float* __restrict__ valid)
{
    int j = blockIdx.x, t = threadIdx.x;
    float cs = colsum[j];
    float v = concept[(size_t)j * HD + t];
    if (cs != 0.f) {
        float dg = sim[(size_t)j * NS + j];
        v += dg * g[(size_t)j * HD + t];
        concept[(size_t)j * HD + t] = v;
    }
    float s = v;
    #pragma unroll
    for (int off = 16; off; off >>= 1) s += __shfl_xor_sync(0xffffffffu, s, off);
    __shared__ float ws[4];
    if ((t & 31) == 0) ws[t >> 5] = s;
    __syncthreads();
    if (t == 0) {
        float tot = ws[0] + ws[1] + ws[2] + ws[3];
        valid[j] = (tot != 0.f) ? 1.f : 0.f;
    }
}

__global__ void k_colz(const float* __restrict__ S, float* __restrict__ colZ) {
    int col = blockIdx.x * 128 + threadIdx.x;
    int r0 = blockIdx.y * 128;
    float s = 0.f;
    for (int r = r0; r < r0 + 128; r++) s += __expf(S[(size_t)r * NS + col]);
    atomicAdd(&colZ[col], s);
}

__global__ void k_recip(float* __restrict__ colZ) {
    int i = blockIdx.x * blockDim.x + threadIdx.x;
    if (i < NS) colZ[i] = __fdividef(1.f, colZ[i]);
}

__global__ void k_scale(float* __restrict__ S, const float* __restrict__ colZ) {
    size_t q = (size_t)blockIdx.x * blockDim.x + threadIdx.x;
    size_t b = q * 4;
    float4 v = *(float4*)(S + b);
    int c = (int)(b & (NS - 1));
    float4 z = *(const float4*)(colZ + c);
    v.x = __expf(v.x) * z.x; v.y = __expf(v.y) * z.y;
    v.z = __expf(v.z) * z.z; v.w = __expf(v.w) * z.w;
    *(float4*)(S + b) = v;
}

__global__ void k_final(const float* __restrict__ fore, const float* __restrict__ indi,
                        const float* __restrict__ Wout, const float* __restrict__ bout,
                        float* __restrict__ out)
{
    int row = blockIdx.x * 8 + (threadIdx.x >> 5);
    int lane = threadIdx.x & 31;
    float4 a = ((const float4*)(fore + (size_t)row * HD))[lane];
    float4 b = ((const float4*)(indi + (size_t)row * HD))[lane];
    float4 w = ((const float4*)Wout)[lane];
    float s = (a.x+b.x)*w.x + (a.y+b.y)*w.y + (a.z+b.z)*w.z + (a.w+b.w)*w.w;
    #pragma unroll
    for (int off = 16; off; off >>= 1) s += __shfl_xor_sync(0xffffffffu, s, off);
    if (lane == 0) out[row] = s + bout[0];
}

// ---------------- driver -----------------------------------------------------
extern "C" void kernel_launch(void* const* d_in, const int* in_sizes, int n_in,
                              void* d_out, int out_size)
{
    const float* x     = (const float*)d_in[0];
    const float* Wih0  = (const float*)d_in[1];
    const float* Whh0  = (const float*)d_in[2];
    const float* bih0  = (const float*)d_in[3];
    const float* bhh0  = (const float*)d_in[4];
    const float* Wih1  = (const float*)d_in[5];
    const float* Whh1  = (const float*)d_in[6];
    const float* bih1  = (const float*)d_in[7];
    const float* bhh1  = (const float*)d_in[8];
    const float* W_hc  = (const float*)d_in[9];
    const float* b_hc  = (const float*)d_in[10];
    const float* W_hs  = (const float*)d_in[11];
    const float* b_hs  = (const float*)d_in[12];
    const float* W_fore= (const float*)d_in[13];
    const float* b_fore= (const float*)d_in[14];
    const float* W_back= (const float*)d_in[15];
    const float* b_back= (const float*)d_in[16];
    const float* W_indi= (const float*)d_in[17];
    const float* b_indi= (const float*)d_in[18];
    const float* W_out = (const float*)d_in[19];
    const float* b_out = (const float*)d_in[20];
    float* out = (float*)d_out;

    float *gi, *h0, *g, *gn, *sim, *colsum, *colZ, *valid, *concept;
    float *cf, *cfn, *hs, *t1, *t2, *t3, *t4, *tval;
    int* tidx;
    cudaGetSymbolAddress((void**)&gi,      d_gi);
    cudaGetSymbolAddress((void**)&h0,      d_h0);
    cudaGetSymbolAddress((void**)&g,       d_g);
    cudaGetSymbolAddress((void**)&gn,      d_gn);
    cudaGetSymbolAddress((void**)&sim,     d_sim);
    cudaGetSymbolAddress((void**)&tidx,    d_tidx);
    cudaGetSymbolAddress((void**)&tval,    d_tval);
    cudaGetSymbolAddress((void**)&colsum,  d_colsum);
    cudaGetSymbolAddress((void**)&colZ,    d_colZ);
    cudaGetSymbolAddress((void**)&valid,   d_valid);
    cudaGetSymbolAddress((void**)&concept, d_concept);
    cudaGetSymbolAddress((void**)&cf,      d_cf);
    cudaGetSymbolAddress((void**)&cfn,     d_cfn);
    cudaGetSymbolAddress((void**)&hs,      d_hsb);
    cudaGetSymbolAddress((void**)&t1,      d_t1);
    cudaGetSymbolAddress((void**)&t2,      d_t2);
    cudaGetSymbolAddress((void**)&t3,      d_t3);
    cudaGetSymbolAddress((void**)&t4,      d_t4);

    // h 28*128 + ghA/ghB 2*28*384 + gi 28*384 floats
    const int GRU_SMEM = (GRROWS * HD + 3 * GRROWS * GD) * 4;  // 143360 B
    cudaFuncSetAttribute((const void*)k_gru<true>,
                         cudaFuncAttributeMaxDynamicSharedMemorySize, GRU_SMEM);
    cudaFuncSetAttribute((const void*)k_gru<false>,
                         cudaFuncAttributeMaxDynamicSharedMemorySize, GRU_SMEM);

    const int MT = NS * TS;         // 262144
    const int GRU_GRID = (NS + GRROWS - 1) / GRROWS;  // 147

    // Launch order: gru0 is our 4th launch so ncu (-s 5 -c 1, one harness
    // pre-launch) captures the GRU kernel.
    // #1 gi0 = x @ Wih0^T + bih0
    k_gemm<true, false><<<dim3(GD / 64, MT / 128, 1), 256>>>(
        x, Wih0, bih0, nullptr, gi, MT, GD, FI, FI);
    // #2, #3 tiny zeros (needed later)
    k_zero<<<(NS + 255) / 256, 256>>>(colsum, NS);
    k_zero<<<(NS + 255) / 256, 256>>>(colZ, NS);
    // #4 GRU layer 0 (writes full sequence)  <- ncu capture target
    k_gru<true><<<GRU_GRID, 768, GRU_SMEM>>>(gi, Whh0, bhh0, h0);
    // gi1 = h0 @ Wih1^T + bih1
    k_gemm<true, false><<<dim3(GD / 64, MT / 128, 1), 256>>>(
        h0, Wih1, bih1, nullptr, gi, MT, GD, HD, HD);
    // GRU layer 1 (writes final hidden only -> g)
    k_gru<false><<<GRU_GRID, 768, GRU_SMEM>>>(gi, Whh1, bhh1, g);

    // concept accumulator zero (before scatter)
    k_zero<<<(NS * HD + 255) / 256, 256>>>(concept, NS * HD);

    // normalized g, sim = gn @ gn^T
    k_rownorm<<<NS / 8, 256>>>(g, gn);
    k_gemm<true, false><<<dim3(NS / 64, NS / 128, 1), 256>>>(
        gn, gn, nullptr, nullptr, sim, NS, NS, HD, HD);

    // top-K selection + concept aggregation
    k_topk<<<NS, 256>>>(sim, tidx, tval, colsum);
    k_scatter<<<NS, 128>>>(tidx, tval, g, concept);
    k_diag_valid<<<NS, 128>>>(colsum, sim, g, concept, valid);

    // cf = lrelu(concept @ W_hc^T + b_hc) * valid
    k_gemm64<true, false><<<dim3(HD / 64, NS / 64), 256>>>(
        concept, W_hc, b_hc, valid, nullptr, cf, NS, HD, HD);
    k_rownorm<<<NS / 8, 256>>>(cf, cfn);

    // S = gn @ cfn^T ; attn = softmax over axis 0
    k_gemm<true, false><<<dim3(NS / 64, NS / 128, 1), 256>>>(
        gn, cfn, nullptr, nullptr, sim, NS, NS, HD, HD);
    k_colz<<<dim3(NS / 128, NS / 128), 128>>>(sim, colZ);
    k_recip<<<NS / 256, 256>>>(colZ);
    k_scale<<<(int)(((size_t)NS * NS / 4) / 256), 256>>>(sim, colZ);

    // t1 = attn @ cf  (K=4096, split-K=8 into gi scratch, then reduce)
    k_gemm<false, false><<<dim3(HD / 64, NS / 128, 8), 256>>>(
        sim, cf, nullptr, nullptr, gi, NS, HD, NS, NS / 8);
    k_reduce<<<(NS * HD / 4 + 255) / 256, 256>>>(gi, t1, 8, NS * HD / 4);

    // hs = lrelu(t1 @ W_hs^T + b_hs)
    k_gemm64<true, false><<<dim3(HD / 64, NS / 64), 256>>>(
        t1, W_hs, b_hs, nullptr, nullptr, hs, NS, HD, HD);

    // t3 = g - lrelu(hs @ W_back^T + b_back)   (fused subtract)
    k_gemm64<true, true><<<dim3(HD / 64, NS / 64), 256>>>(
        hs, W_back, b_back, nullptr, g, t3, NS, HD, HD);
    // t2 = lrelu(hs @ W_fore^T + b_fore)
    k_gemm64<true, false><<<dim3(HD / 64, NS / 64), 256>>>(
        hs, W_fore, b_fore, nullptr, nullptr, t2, NS, HD, HD);
    // t4 = lrelu(t3 @ W_indi^T + b_indi)
    k_gemm64<true, false><<<dim3(HD / 64, NS / 64), 256>>>(
        t3, W_indi, b_indi, nullptr, nullptr, t4, NS, HD, HD);
    k_final<<<NS / 8, 256>>>(t2, t4, W_out, b_out, out);
}

// round 8
// speedup vs baseline: 1.1518x; 1.1518x over previous
#include <cuda_runtime.h>
#include <math.h>
#include <stdint.h>
#include <stddef.h>

// Problem dims (fixed by the dataset)
#define NS   4096      // batch
#define TS   64        // timesteps
#define FI   32        // input features
#define HD   128       // hidden
#define GD   384       // 3*H
#define NK   20        // top-k
#define SLOPE_F 0.2f
#define GRROWS 28      // batch rows per GRU CTA (147 CTAs -> all 148 SMs)

typedef unsigned long long ull;

// ---------------- f32x2 packed helpers (Blackwell FFMA2) --------------------
__device__ __forceinline__ ull pack2(float lo, float hi) {
    ull r;
    asm("mov.b64 %0, {%1, %2};" : "=l"(r) : "f"(lo), "f"(hi));
    return r;
}
__device__ __forceinline__ float2 unpack2(ull v) {
    float2 r;
    asm("mov.b64 {%0, %1}, %2;" : "=f"(r.x), "=f"(r.y) : "l"(v));
    return r;
}
__device__ __forceinline__ void ffma2(ull& d, ull a, ull b) {
    asm("fma.rn.f32x2 %0, %1, %2, %0;" : "+l"(d) : "l"(a), "l"(b));
}

// ---------------- cp.async helpers -----------------------------------------
__device__ __forceinline__ void cp16(float* dst_sh, const float* src_g) {
    uint32_t d = (uint32_t)__cvta_generic_to_shared(dst_sh);
    asm volatile("cp.async.ca.shared.global [%0], [%1], 16;" :: "r"(d), "l"(src_g));
}
__device__ __forceinline__ void cp_commit() {
    asm volatile("cp.async.commit_group;");
}
__device__ __forceinline__ void cp_wait_all() {
    asm volatile("cp.async.wait_all;");
}

// ---------------- scratch (device globals; no runtime allocation) ----------
__device__ float d_gi[(size_t)NS * TS * GD];
__device__ float d_h0[(size_t)NS * TS * HD];
__device__ float d_g  [NS * HD];
__device__ float d_gn [NS * HD];
__device__ float d_sim[(size_t)NS * NS];
__device__ int   d_tidx[NS * NK];
__device__ float d_tval[NS * NK];
__device__ float d_colsum[NS];
__device__ float d_colZ[NS];
__device__ float d_valid[NS];
__device__ float d_concept[NS * HD];
__device__ float d_cf [NS * HD];
__device__ float d_cfn[NS * HD];
__device__ float d_hsb[NS * HD];
__device__ float d_t1 [NS * HD];
__device__ float d_t2 [NS * HD];
__device__ float d_t3 [NS * HD];
__device__ float d_t4 [NS * HD];

// ---------------- fp32 GEMM: 128x64 tile, 256 thr, 8x4 micro, FFMA2 ---------
// EXPOUT: write __expf(result) (for fused softmax numerator)
template<bool TRANSB, bool ACT, bool EXPOUT>
__global__ __launch_bounds__(256) void k_gemm(
    const float* __restrict__ A, const float* __restrict__ B,
    const float* __restrict__ bias, const float* __restrict__ rs,
    float* __restrict__ C, int M, int N, int K, int ksplit)
{
    __shared__ alignas(16) float As[16][132];
    __shared__ alignas(16) float Bs[16][68];
    const int bm = blockIdx.y * 128, bn = blockIdx.x * 64;
    const int tid = threadIdx.x;
    const int kbase = blockIdx.z * ksplit;

    const int a_m = tid >> 1, a_k = (tid & 1) * 8;
    const int ty = tid >> 4, tx = tid & 15;
    const int m0 = ty * 8, n0 = tx * 4;

    ull acc2[4][4];
    #pragma unroll
    for (int p = 0; p < 4; p++)
        #pragma unroll
        for (int j = 0; j < 4; j++) acc2[p][j] = 0ull;

    for (int k0 = kbase; k0 < kbase + ksplit; k0 += 16) {
        const float* Ap = A + (size_t)(bm + a_m) * K + k0 + a_k;
        float4 av0 = *(const float4*)(Ap);
        float4 av1 = *(const float4*)(Ap + 4);
        As[a_k + 0][a_m] = av0.x; As[a_k + 1][a_m] = av0.y;
        As[a_k + 2][a_m] = av0.z; As[a_k + 3][a_m] = av0.w;
        As[a_k + 4][a_m] = av1.x; As[a_k + 5][a_m] = av1.y;
        As[a_k + 6][a_m] = av1.z; As[a_k + 7][a_m] = av1.w;
        if (TRANSB) {
            const int b_n = tid >> 2, b_k = (tid & 3) * 4;
            float4 bv = *(const float4*)(B + (size_t)(bn + b_n) * K + k0 + b_k);
            Bs[b_k + 0][b_n] = bv.x; Bs[b_k + 1][b_n] = bv.y;
            Bs[b_k + 2][b_n] = bv.z; Bs[b_k + 3][b_n] = bv.w;
        } else {
            const int b_k = tid >> 4, b_n4 = (tid & 15) * 4;
            *(float4*)&Bs[b_k][b_n4] =
                *(const float4*)(B + (size_t)(k0 + b_k) * N + bn + b_n4);
        }
        __syncthreads();
        #pragma unroll
        for (int kk = 0; kk < 16; kk++) {
            ulonglong2 aP01 = *(const ulonglong2*)&As[kk][m0];
            ulonglong2 aP23 = *(const ulonglong2*)&As[kk][m0 + 4];
            float4 b = *(const float4*)&Bs[kk][n0];
            ull bd0 = pack2(b.x, b.x), bd1 = pack2(b.y, b.y);
            ull bd2 = pack2(b.z, b.z), bd3 = pack2(b.w, b.w);
            ffma2(acc2[0][0], aP01.x, bd0); ffma2(acc2[0][1], aP01.x, bd1);
            ffma2(acc2[0][2], aP01.x, bd2); ffma2(acc2[0][3], aP01.x, bd3);
            ffma2(acc2[1][0], aP01.y, bd0); ffma2(acc2[1][1], aP01.y, bd1);
            ffma2(acc2[1][2], aP01.y, bd2); ffma2(acc2[1][3], aP01.y, bd3);
            ffma2(acc2[2][0], aP23.x, bd0); ffma2(acc2[2][1], aP23.x, bd1);
            ffma2(acc2[2][2], aP23.x, bd2); ffma2(acc2[2][3], aP23.x, bd3);
            ffma2(acc2[3][0], aP23.y, bd0); ffma2(acc2[3][1], aP23.y, bd1);
            ffma2(acc2[3][2], aP23.y, bd2); ffma2(acc2[3][3], aP23.y, bd3);
        }
        __syncthreads();
    }

    float* Cw = C + (size_t)blockIdx.z * ((size_t)M * N);
    #pragma unroll
    for (int p = 0; p < 4; p++) {
        int rowA = bm + m0 + 2 * p;
        int rowB = rowA + 1;
        float rsA = rs ? rs[rowA] : 1.f;
        float rsB = rs ? rs[rowB] : 1.f;
        float va[4], vb[4];
        #pragma unroll
        for (int j = 0; j < 4; j++) {
            float2 v = unpack2(acc2[p][j]);
            float a = v.x, b = v.y;
            if (bias) { float bj = bias[bn + n0 + j]; a += bj; b += bj; }
            if (ACT) {
                a = a > 0.f ? a : SLOPE_F * a;
                b = b > 0.f ? b : SLOPE_F * b;
            }
            if (EXPOUT) { a = __expf(a); b = __expf(b); }
            va[j] = a * rsA; vb[j] = b * rsB;
        }
        *(float4*)(Cw + (size_t)rowA * N + bn + n0) =
            make_float4(va[0], va[1], va[2], va[3]);
        *(float4*)(Cw + (size_t)rowB * N + bn + n0) =
            make_float4(vb[0], vb[1], vb[2], vb[3]);
    }
}

// ---------------- fp32 GEMM: 64x64 tile (for NS x 128 x 128 head GEMMs) -----
template<bool ACT, bool SUBPRE>
__global__ __launch_bounds__(256) void k_gemm64(
    const float* __restrict__ A, const float* __restrict__ B,
    const float* __restrict__ bias, const float* __restrict__ rs,
    const float* __restrict__ pre, float* __restrict__ C,
    int M, int N, int K)
{
    __shared__ alignas(16) float As[16][68];
    __shared__ alignas(16) float Bs[16][68];
    const int bm = blockIdx.y * 64, bn = blockIdx.x * 64;
    const int tid = threadIdx.x;
    const int a_m = tid >> 2, a_k = (tid & 3) * 4;
    const int ty = tid >> 4, tx = tid & 15;
    const int m0 = ty * 4, n0 = tx * 4;

    ull acc2[2][4];
    #pragma unroll
    for (int p = 0; p < 2; p++)
        #pragma unroll
        for (int j = 0; j < 4; j++) acc2[p][j] = 0ull;

    for (int k0 = 0; k0 < K; k0 += 16) {
        float4 av = *(const float4*)(A + (size_t)(bm + a_m) * K + k0 + a_k);
        As[a_k + 0][a_m] = av.x; As[a_k + 1][a_m] = av.y;
        As[a_k + 2][a_m] = av.z; As[a_k + 3][a_m] = av.w;
        float4 bv = *(const float4*)(B + (size_t)(bn + a_m) * K + k0 + a_k);
        Bs[a_k + 0][a_m] = bv.x; Bs[a_k + 1][a_m] = bv.y;
        Bs[a_k + 2][a_m] = bv.z; Bs[a_k + 3][a_m] = bv.w;
        __syncthreads();
        #pragma unroll
        for (int kk = 0; kk < 16; kk++) {
            ulonglong2 aP = *(const ulonglong2*)&As[kk][m0];
            float4 b = *(const float4*)&Bs[kk][n0];
            ull bd0 = pack2(b.x, b.x), bd1 = pack2(b.y, b.y);
            ull bd2 = pack2(b.z, b.z), bd3 = pack2(b.w, b.w);
            ffma2(acc2[0][0], aP.x, bd0); ffma2(acc2[0][1], aP.x, bd1);
            ffma2(acc2[0][2], aP.x, bd2); ffma2(acc2[0][3], aP.x, bd3);
            ffma2(acc2[1][0], aP.y, bd0); ffma2(acc2[1][1], aP.y, bd1);
            ffma2(acc2[1][2], aP.y, bd2); ffma2(acc2[1][3], aP.y, bd3);
        }
        __syncthreads();
    }

    #pragma unroll
    for (int p = 0; p < 2; p++) {
        int rowA = bm + m0 + 2 * p;
        int rowB = rowA + 1;
        float rsA = rs ? rs[rowA] : 1.f;
        float rsB = rs ? rs[rowB] : 1.f;
        float va[4], vb[4];
        #pragma unroll
        for (int j = 0; j < 4; j++) {
            float2 v = unpack2(acc2[p][j]);
            float a = v.x, b = v.y;
            if (bias) { float bj = bias[bn + n0 + j]; a += bj; b += bj; }
            if (ACT) {
                a = a > 0.f ? a : SLOPE_F * a;
                b = b > 0.f ? b : SLOPE_F * b;
            }
            a *= rsA; b *= rsB;
            if (SUBPRE) {
                a = pre[(size_t)rowA * N + bn + n0 + j] - a;
                b = pre[(size_t)rowB * N + bn + n0 + j] - b;
            }
            va[j] = a; vb[j] = b;
        }
        *(float4*)(C + (size_t)rowA * N + bn + n0) =
            make_float4(va[0], va[1], va[2], va[3]);
        *(float4*)(C + (size_t)rowB * N + bn + n0) =
            make_float4(vb[0], vb[1], vb[2], vb[3]);
    }
}

// reduce over split-K partial slices: C = sum_z P[z]
__global__ void k_reduce(const float* __restrict__ P, float* __restrict__ C,
                         int nslice, int total4)
{
    int i = blockIdx.x * blockDim.x + threadIdx.x;
    if (i >= total4) return;
    size_t b = (size_t)i * 4;
    float4 s = make_float4(0.f, 0.f, 0.f, 0.f);
    for (int z = 0; z < nslice; z++) {
        float4 v = *(const float4*)(P + (size_t)z * total4 * 4 + b);
        s.x += v.x; s.y += v.y; s.z += v.z; s.w += v.w;
    }
    *(float4*)(C + b) = s;
}

// ---------------- persistent GRU recurrent kernel ---------------------------
// 384 threads, mapping (2 outputs, half-k): o = tid%192, half = tid/192.
// Thread owns Whh rows o and o+192 restricted to its 64-element k-half
// (128 floats = 64 packed pairs in registers). Each h-half LDS feeds BOTH
// outputs -> LDS wavefronts halved vs one-output layouts (L1 was the wall).
// Partial dots: ghA (half 0, +biases) / ghB (half 1); gate phase sums.
template<bool WRITE_SEQ>
__global__ __launch_bounds__(384, 1) void k_gru(
    const float* __restrict__ gi, const float* __restrict__ Whh,
    const float* __restrict__ bhh, float* __restrict__ hout)
{
    extern __shared__ float sm[];
    float* h_sh = sm;                          // GRROWS*128
    float* ghA  = sm + GRROWS * HD;            // GRROWS*384
    float* ghB  = ghA + GRROWS * GD;           // GRROWS*384
    float* gi_sh = ghB + GRROWS * GD;          // GRROWS*384
    const int tid = threadIdx.x;
    const int o = tid % 192;
    const int half = tid / 192;                 // 0 or 1
    const int o2 = o + 192;
    const int base = blockIdx.x * GRROWS;
    const int rows = (NS - base < GRROWS) ? (NS - base) : GRROWS;
    float* ghOut = half ? ghB : ghA;

    // weights: rows o and o+192, k in [64*half, 64*half+64)
    ull wq[64];
    {
        const ulonglong2* wg0 =
            (const ulonglong2*)(Whh + (size_t)o * HD + half * 64);
        const ulonglong2* wg1 =
            (const ulonglong2*)(Whh + (size_t)o2 * HD + half * 64);
        #pragma unroll
        for (int q = 0; q < 16; q++) {
            ulonglong2 t0 = wg0[q];
            wq[2 * q] = t0.x; wq[2 * q + 1] = t0.y;
        }
        #pragma unroll
        for (int q = 0; q < 16; q++) {
            ulonglong2 t1 = wg1[q];
            wq[32 + 2 * q] = t1.x; wq[32 + 2 * q + 1] = t1.y;
        }
    }
    const float bo0 = half ? 0.f : bhh[o];
    const float bo1 = half ? 0.f : bhh[o2];
    for (int idx = tid; idx < rows * HD; idx += 384) h_sh[idx] = 0.f;

    // gi prefetch: 28*96 float4 slots; thread does 8 strided slots
    const int pr = tid / 12, pc = tid % 12;
    const bool pact = (pr < rows);
    {
        const float* src = gi + ((size_t)(base + pr) * TS + 0) * GD;
        if (pact) {
            #pragma unroll
            for (int i = 0; i < 8; i++) {
                int f = pc + 12 * i;
                cp16(gi_sh + pr * GD + f * 4, src + f * 4);
            }
        }
        cp_commit();
    }
    __syncthreads();

    for (int t = 0; t < TS; t++) {
        // partial matvec: for each row, one h-half load feeds 2 outputs
        #pragma unroll 1
        for (int r = 0; r < rows; r++) {
            const ulonglong2* hp =
                (const ulonglong2*)(h_sh + r * HD + half * 64);
            ull a0 = 0ull, a1 = 0ull, b0 = 0ull, b1 = 0ull;
            #pragma unroll
            for (int q = 0; q < 16; q += 2) {
                ulonglong2 x0 = hp[q], x1 = hp[q + 1];
                ffma2(a0, x0.x, wq[2 * q]);
                ffma2(b0, x0.x, wq[32 + 2 * q]);
                ffma2(a1, x0.y, wq[2 * q + 1]);
                ffma2(b1, x0.y, wq[32 + 2 * q + 1]);
                ffma2(a0, x1.x, wq[2 * q + 2]);
                ffma2(b0, x1.x, wq[32 + 2 * q + 2]);
                ffma2(a1, x1.y, wq[2 * q + 3]);
                ffma2(b1, x1.y, wq[32 + 2 * q + 3]);
            }
            float2 pa0 = unpack2(a0), pa1 = unpack2(a1);
            float2 pb0 = unpack2(b0), pb1 = unpack2(b1);
            ghOut[r * GD + o]  = ((pa0.x + pa0.y) + (pa1.x + pa1.y)) + bo0;
            ghOut[r * GD + o2] = ((pb0.x + pb0.y) + (pb1.x + pb1.y)) + bo1;
        }
        cp_wait_all();
        __syncthreads();
        // gate update (sum the two partial buffers)
        #pragma unroll 1
        for (int idx = tid; idx < rows * HD; idx += 384) {
            int r = idx >> 7, j = idx & 127;
            float gir = gi_sh[r * GD + j];
            float giz = gi_sh[r * GD + j + 128];
            float gin = gi_sh[r * GD + j + 256];
            float ghr = ghA[r * GD + j]       + ghB[r * GD + j];
            float ghz = ghA[r * GD + j + 128] + ghB[r * GD + j + 128];
            float ghn = ghA[r * GD + j + 256] + ghB[r * GD + j + 256];
            float rg = __fdividef(1.f, 1.f + __expf(-(gir + ghr)));
            float zg = __fdividef(1.f, 1.f + __expf(-(giz + ghz)));
            float a2 = gin + rg * ghn;
            float ng = 1.f - __fdividef(2.f, __expf(2.f * a2) + 1.f);
            float hprev = h_sh[idx];
            float hn = (1.f - zg) * ng + zg * hprev;
            h_sh[idx] = hn;
            if (WRITE_SEQ)
                hout[((size_t)(base + r) * TS + t) * HD + j] = hn;
            else if (t == TS - 1)
                hout[(size_t)(base + r) * HD + j] = hn;
        }
        __syncthreads();
        // prefetch gi for t+1
        if (t + 1 < TS) {
            const float* src = gi + ((size_t)(base + pr) * TS + (t + 1)) * GD;
            if (pact) {
                #pragma unroll
                for (int i = 0; i < 8; i++) {
                    int f = pc + 12 * i;
                    cp16(gi_sh + pr * GD + f * 4, src + f * 4);
                }
            }
            cp_commit();
        }
    }
}

// ---------------- small helpers --------------------------------------------
__global__ void k_zero(float* p, int n) {
    int i = blockIdx.x * blockDim.x + threadIdx.x;
    if (i < n) p[i] = 0.f;
}

__global__ void k_rownorm(const float* __restrict__ src, float* __restrict__ dst) {
    int row = blockIdx.x * 8 + (threadIdx.x >> 5);
    int lane = threadIdx.x & 31;
    const float4* s4 = (const float4*)(src + (size_t)row * HD);
    float4 v = s4[lane];
    float ss = v.x*v.x + v.y*v.y + v.z*v.z + v.w*v.w;
    #pragma unroll
    for (int off = 16; off; off >>= 1) ss += __shfl_xor_sync(0xffffffffu, ss, off);
    float n = sqrtf(ss);
    float inv = (n > 0.f) ? 1.f / n : 0.f;
    ((float4*)(dst + (size_t)row * HD))[lane] =
        make_float4(v.x*inv, v.y*inv, v.z*inv, v.w*inv);
}

// top-K=20 per row of |sim| (diag excluded), jax-stable ties (lowest index).
__global__ __launch_bounds__(256) void k_topk(
    const float* __restrict__ sim, int* __restrict__ tidx,
    float* __restrict__ tval, float* __restrict__ colsum)
{
    int i = blockIdx.x;
    __shared__ float sabs[NS];
    __shared__ float wv[8];
    __shared__ int   wi[8];
    const float* row = sim + (size_t)i * NS;
    for (int c = threadIdx.x; c < NS; c += 256)
        sabs[c] = (c == i) ? -1.f : fabsf(row[c]);
    __syncthreads();
    for (int k = 0; k < NK; k++) {
        float bv = -2.f; int bi = 0;
        for (int c = threadIdx.x; c < NS; c += 256) {
            float v = sabs[c];
            if (v > bv) { bv = v; bi = c; }
        }
        #pragma unroll
        for (int off = 16; off; off >>= 1) {
            float ov = __shfl_down_sync(0xffffffffu, bv, off);
            int   oi = __shfl_down_sync(0xffffffffu, bi, off);
            if (ov > bv || (ov == bv && oi < bi)) { bv = ov; bi = oi; }
        }
        if ((threadIdx.x & 31) == 0) { wv[threadIdx.x >> 5] = bv; wi[threadIdx.x >> 5] = bi; }
        __syncthreads();
        if (threadIdx.x == 0) {
            for (int wd = 1; wd < 8; wd++)
                if (wv[wd] > bv || (wv[wd] == bv && wi[wd] < bi)) { bv = wv[wd]; bi = wi[wd]; }
            tidx[i * NK + k] = bi;
            float sv = row[bi];
            tval[i * NK + k] = sv;
            atomicAdd(&colsum[bi], sv);
            sabs[bi] = -2.f;
        }
        __syncthreads();
    }
}

__global__ void k_scatter(const int* __restrict__ tidx, const float* __restrict__ tval,
                          const float* __restrict__ g, float* __restrict__ concept)
{
    int i = blockIdx.x, d = threadIdx.x;
    float gv = g[(size_t)i * HD + d];
    #pragma unroll
    for (int k = 0; k < NK; k++) {
        int c = __ldg(&tidx[i * NK + k]);
        float v = __ldg(&tval[i * NK + k]);
        atomicAdd(&concept[(size_t)c * HD + d], v * gv);
    }
}

__global__ void k_diag_valid(const float* __restrict__ colsum, const float* __restrict__ sim,
                             const float* __restrict__ g, float* __restrict__ concept,
                             float* __restrict__ valid)
{
    int j = blockIdx.x, t = threadIdx.x;
    float cs = colsum[j];
    float v = concept[(size_t)j * HD + t];
    if (cs != 0.f) {
        float dg = sim[(size_t)j * NS + j];
        v += dg * g[(size_t)j * HD + t];
        concept[(size_t)j * HD + t] = v;
    }
    float s = v;
    #pragma unroll
    for (int off = 16; off; off >>= 1) s += __shfl_xor_sync(0xffffffffu, s, off);
    __shared__ float ws[4];
    if ((t & 31) == 0) ws[t >> 5] = s;
    __syncthreads();
    if (t == 0) {
        float tot = ws[0] + ws[1] + ws[2] + ws[3];
        valid[j] = (tot != 0.f) ? 1.f : 0.f;
    }
}

// column sums of E (E already holds exp(S))
__global__ void k_colz(const float* __restrict__ E, float* __restrict__ colZ) {
    int col = blockIdx.x * 128 + threadIdx.x;
    int r0 = blockIdx.y * 128;
    float s = 0.f;
    for (int r = r0; r < r0 + 128; r++) s += E[(size_t)r * NS + col];
    atomicAdd(&colZ[col], s);
}

__global__ void k_recip(float* __restrict__ colZ) {
    int i = blockIdx.x * blockDim.x + threadIdx.x;
    if (i < NS) colZ[i] = __fdividef(1.f, colZ[i]);
}

// attn = E * rcpZ  (E already exp'd; in place)
__global__ void k_scale(float* __restrict__ E, const float* __restrict__ colZ) {
    size_t q = (size_t)blockIdx.x * blockDim.x + threadIdx.x;
    size_t b = q * 4;
    float4 v = *(float4*)(E + b);
    int c = (int)(b & (NS - 1));
    float4 z = *(const float4*)(colZ + c);
    v.x *= z.x; v.y *= z.y; v.z *= z.z; v.w *= z.w;
    *(float4*)(E + b) = v;
}

__global__ void k_final(const float* __restrict__ fore, const float* __restrict__ indi,
                        const float* __restrict__ Wout, const float* __restrict__ bout,
                        float* __restrict__ out)
{
    int row = blockIdx.x * 8 + (threadIdx.x >> 5);
    int lane = threadIdx.x & 31;
    float4 a = ((const float4*)(fore + (size_t)row * HD))[lane];
    float4 b = ((const float4*)(indi + (size_t)row * HD))[lane];
    float4 w = ((const float4*)Wout)[lane];
    float s = (a.x+b.x)*w.x + (a.y+b.y)*w.y + (a.z+b.z)*w.z + (a.w+b.w)*w.w;
    #pragma unroll
    for (int off = 16; off; off >>= 1) s += __shfl_xor_sync(0xffffffffu, s, off);
    if (lane == 0) out[row] = s + bout[0];
}

// ---------------- driver -----------------------------------------------------
extern "C" void kernel_launch(void* const* d_in, const int* in_sizes, int n_in,
                              void* d_out, int out_size)
{
    const float* x     = (const float*)d_in[0];
    const float* Wih0  = (const float*)d_in[1];
    const float* Whh0  = (const float*)d_in[2];
    const float* bih0  = (const float*)d_in[3];
    const float* bhh0  = (const float*)d_in[4];
    const float* Wih1  = (const float*)d_in[5];
    const float* Whh1  = (const float*)d_in[6];
    const float* bih1  = (const float*)d_in[7];
    const float* bhh1  = (const float*)d_in[8];
    const float* W_hc  = (const float*)d_in[9];
    const float* b_hc  = (const float*)d_in[10];
    const float* W_hs  = (const float*)d_in[11];
    const float* b_hs  = (const float*)d_in[12];
    const float* W_fore= (const float*)d_in[13];
    const float* b_fore= (const float*)d_in[14];
    const float* W_back= (const float*)d_in[15];
    const float* b_back= (const float*)d_in[16];
    const float* W_indi= (const float*)d_in[17];
    const float* b_indi= (const float*)d_in[18];
    const float* W_out = (const float*)d_in[19];
    const float* b_out = (const float*)d_in[20];
    float* out = (float*)d_out;

    float *gi, *h0, *g, *gn, *sim, *colsum, *colZ, *valid, *concept;
    float *cf, *cfn, *hs, *t1, *t2, *t3, *t4, *tval;
    int* tidx;
    cudaGetSymbolAddress((void**)&gi,      d_gi);
    cudaGetSymbolAddress((void**)&h0,      d_h0);
    cudaGetSymbolAddress((void**)&g,       d_g);
    cudaGetSymbolAddress((void**)&gn,      d_gn);
    cudaGetSymbolAddress((void**)&sim,     d_sim);
    cudaGetSymbolAddress((void**)&tidx,    d_tidx);
    cudaGetSymbolAddress((void**)&tval,    d_tval);
    cudaGetSymbolAddress((void**)&colsum,  d_colsum);
    cudaGetSymbolAddress((void**)&colZ,    d_colZ);
    cudaGetSymbolAddress((void**)&valid,   d_valid);
    cudaGetSymbolAddress((void**)&concept, d_concept);
    cudaGetSymbolAddress((void**)&cf,      d_cf);
    cudaGetSymbolAddress((void**)&cfn,     d_cfn);
    cudaGetSymbolAddress((void**)&hs,      d_hsb);
    cudaGetSymbolAddress((void**)&t1,      d_t1);
    cudaGetSymbolAddress((void**)&t2,      d_t2);
    cudaGetSymbolAddress((void**)&t3,      d_t3);
    cudaGetSymbolAddress((void**)&t4,      d_t4);

    // h 28*128 + ghA/ghB 2*28*384 + gi 28*384 floats = 143360 B
    const int GRU_SMEM = (GRROWS * HD + 3 * GRROWS * GD) * 4;
    cudaFuncSetAttribute((const void*)k_gru<true>,
                         cudaFuncAttributeMaxDynamicSharedMemorySize, GRU_SMEM);
    cudaFuncSetAttribute((const void*)k_gru<false>,
                         cudaFuncAttributeMaxDynamicSharedMemorySize, GRU_SMEM);

    const int MT = NS * TS;         // 262144
    const int GRU_GRID = (NS + GRROWS - 1) / GRROWS;  // 147

    // Launch order: gru0 is our 4th launch so ncu (-s 5 -c 1, one harness
    // pre-launch) captures the GRU kernel.
    // #1 gi0 = x @ Wih0^T + bih0
    k_gemm<true, false, false><<<dim3(GD / 64, MT / 128, 1), 256>>>(
        x, Wih0, bih0, nullptr, gi, MT, GD, FI, FI);
    // #2, #3 tiny zeros (needed later)
    k_zero<<<(NS + 255) / 256, 256>>>(colsum, NS);
    k_zero<<<(NS + 255) / 256, 256>>>(colZ, NS);
    // #4 GRU layer 0 (writes full sequence)  <- ncu capture target
    k_gru<true><<<GRU_GRID, 384, GRU_SMEM>>>(gi, Whh0, bhh0, h0);
    // gi1 = h0 @ Wih1^T + bih1
    k_gemm<true, false, false><<<dim3(GD / 64, MT / 128, 1), 256>>>(
        h0, Wih1, bih1, nullptr, gi, MT, GD, HD, HD);
    // GRU layer 1 (writes final hidden only -> g)
    k_gru<false><<<GRU_GRID, 384, GRU_SMEM>>>(gi, Whh1, bhh1, g);

    // concept accumulator zero (before scatter)
    k_zero<<<(NS * HD + 255) / 256, 256>>>(concept, NS * HD);

    // normalized g, sim = gn @ gn^T
    k_rownorm<<<NS / 8, 256>>>(g, gn);
    k_gemm<true, false, false><<<dim3(NS / 64, NS / 128, 1), 256>>>(
        gn, gn, nullptr, nullptr, sim, NS, NS, HD, HD);

    // top-K selection + concept aggregation
    k_topk<<<NS, 256>>>(sim, tidx, tval, colsum);
    k_scatter<<<NS, 128>>>(tidx, tval, g, concept);
    k_diag_valid<<<NS, 128>>>(colsum, sim, g, concept, valid);

    // cf = lrelu(concept @ W_hc^T + b_hc) * valid
    k_gemm64<true, false><<<dim3(HD / 64, NS / 64), 256>>>(
        concept, W_hc, b_hc, valid, nullptr, cf, NS, HD, HD);
    k_rownorm<<<NS / 8, 256>>>(cf, cfn);

    // E = exp(gn @ cfn^T)  (exp fused into GEMM epilogue)
    k_gemm<true, false, true><<<dim3(NS / 64, NS / 128, 1), 256>>>(
        gn, cfn, nullptr, nullptr, sim, NS, NS, HD, HD);
    k_colz<<<dim3(NS / 128, NS / 128), 128>>>(sim, colZ);
    k_recip<<<NS / 256, 256>>>(colZ);
    k_scale<<<(int)(((size_t)NS * NS / 4) / 256), 256>>>(sim, colZ);

    // t1 = attn @ cf  (K=4096, split-K=8 into gi scratch, then reduce)
    k_gemm<false, false, false><<<dim3(HD / 64, NS / 128, 8), 256>>>(
        sim, cf, nullptr, nullptr, gi, NS, HD, NS, NS / 8);
    k_reduce<<<(NS * HD / 4 + 255) / 256, 256>>>(gi, t1, 8, NS * HD / 4);

    // hs = lrelu(t1 @ W_hs^T + b_hs)
    k_gemm64<true, false><<<dim3(HD / 64, NS / 64), 256>>>(
        t1, W_hs, b_hs, nullptr, nullptr, hs, NS, HD, HD);

    // t3 = g - lrelu(hs @ W_back^T + b_back)   (fused subtract)
    k_gemm64<true, true><<<dim3(HD / 64, NS / 64), 256>>>(
        hs, W_back, b_back, nullptr, g, t3, NS, HD, HD);
    // t2 = lrelu(hs @ W_fore^T + b_fore)
    k_gemm64<true, false><<<dim3(HD / 64, NS / 64), 256>>>(
        hs, W_fore, b_fore, nullptr, nullptr, t2, NS, HD, HD);
    // t4 = lrelu(t3 @ W_indi^T + b_indi)
    k_gemm64<true, false><<<dim3(HD / 64, NS / 64), 256>>>(
        t3, W_indi, b_indi, nullptr, nullptr, t4, NS, HD, HD);
    k_final<<<NS / 8, 256>>>(t2, t4, W_out, b_out, out);
}

// round 9
// speedup vs baseline: 1.1966x; 1.0389x over previous
#include <cuda_runtime.h>
#include <math.h>
#include <stdint.h>
#include <stddef.h>

// Problem dims (fixed by the dataset)
#define NS   4096      // batch
#define TS   64        // timesteps
#define FI   32        // input features
#define HD   128       // hidden
#define GD   384       // 3*H
#define NK   20        // top-k
#define SLOPE_F 0.2f
#define GRROWS 28      // batch rows per GRU CTA (147 CTAs -> all 148 SMs)

typedef unsigned long long ull;

// ---------------- f32x2 packed helpers (Blackwell FFMA2) --------------------
__device__ __forceinline__ ull pack2(float lo, float hi) {
    ull r;
    asm("mov.b64 %0, {%1, %2};" : "=l"(r) : "f"(lo), "f"(hi));
    return r;
}
__device__ __forceinline__ float2 unpack2(ull v) {
    float2 r;
    asm("mov.b64 {%0, %1}, %2;" : "=f"(r.x), "=f"(r.y) : "l"(v));
    return r;
}
__device__ __forceinline__ void ffma2(ull& d, ull a, ull b) {
    asm("fma.rn.f32x2 %0, %1, %2, %0;" : "+l"(d) : "l"(a), "l"(b));
}

// ---------------- cp.async helpers -----------------------------------------
__device__ __forceinline__ void cp16(float* dst_sh, const float* src_g) {
    uint32_t d = (uint32_t)__cvta_generic_to_shared(dst_sh);
    asm volatile("cp.async.ca.shared.global [%0], [%1], 16;" :: "r"(d), "l"(src_g));
}
__device__ __forceinline__ void cp_commit() {
    asm volatile("cp.async.commit_group;");
}
__device__ __forceinline__ void cp_wait_all() {
    asm volatile("cp.async.wait_all;");
}

// ---------------- scratch (device globals; no runtime allocation) ----------
__device__ float d_gi[(size_t)NS * TS * GD];
__device__ float d_h0[(size_t)NS * TS * HD];
__device__ float d_g  [NS * HD];
__device__ float d_gn [NS * HD];
__device__ float d_sim[(size_t)NS * NS];
__device__ int   d_tidx[NS * NK];
__device__ float d_tval[NS * NK];
__device__ float d_colsum[NS];
__device__ float d_colZ[NS];
__device__ float d_valid[NS];
__device__ float d_concept[NS * HD];
__device__ float d_cf [NS * HD];
__device__ float d_cfn[NS * HD];
__device__ float d_hsb[NS * HD];
__device__ float d_t1 [NS * HD];
__device__ float d_t2 [NS * HD];
__device__ float d_t3 [NS * HD];
__device__ float d_t4 [NS * HD];

// ---------------- fp32 GEMM: 128x64 tile, 256 thr, 8x4 micro, FFMA2 ---------
// EXPOUT: write __expf(result) (for fused softmax numerator)
template<bool TRANSB, bool ACT, bool EXPOUT>
__global__ __launch_bounds__(256) void k_gemm(
    const float* __restrict__ A, const float* __restrict__ B,
    const float* __restrict__ bias, const float* __restrict__ rs,
    float* __restrict__ C, int M, int N, int K, int ksplit)
{
    __shared__ alignas(16) float As[16][132];
    __shared__ alignas(16) float Bs[16][68];
    const int bm = blockIdx.y * 128, bn = blockIdx.x * 64;
    const int tid = threadIdx.x;
    const int kbase = blockIdx.z * ksplit;

    const int a_m = tid >> 1, a_k = (tid & 1) * 8;
    const int ty = tid >> 4, tx = tid & 15;
    const int m0 = ty * 8, n0 = tx * 4;

    ull acc2[4][4];
    #pragma unroll
    for (int p = 0; p < 4; p++)
        #pragma unroll
        for (int j = 0; j < 4; j++) acc2[p][j] = 0ull;

    for (int k0 = kbase; k0 < kbase + ksplit; k0 += 16) {
        const float* Ap = A + (size_t)(bm + a_m) * K + k0 + a_k;
        float4 av0 = *(const float4*)(Ap);
        float4 av1 = *(const float4*)(Ap + 4);
        As[a_k + 0][a_m] = av0.x; As[a_k + 1][a_m] = av0.y;
        As[a_k + 2][a_m] = av0.z; As[a_k + 3][a_m] = av0.w;
        As[a_k + 4][a_m] = av1.x; As[a_k + 5][a_m] = av1.y;
        As[a_k + 6][a_m] = av1.z; As[a_k + 7][a_m] = av1.w;
        if (TRANSB) {
            const int b_n = tid >> 2, b_k = (tid & 3) * 4;
            float4 bv = *(const float4*)(B + (size_t)(bn + b_n) * K + k0 + b_k);
            Bs[b_k + 0][b_n] = bv.x; Bs[b_k + 1][b_n] = bv.y;
            Bs[b_k + 2][b_n] = bv.z; Bs[b_k + 3][b_n] = bv.w;
        } else {
            const int b_k = tid >> 4, b_n4 = (tid & 15) * 4;
            *(float4*)&Bs[b_k][b_n4] =
                *(const float4*)(B + (size_t)(k0 + b_k) * N + bn + b_n4);
        }
        __syncthreads();
        #pragma unroll
        for (int kk = 0; kk < 16; kk++) {
            ulonglong2 aP01 = *(const ulonglong2*)&As[kk][m0];
            ulonglong2 aP23 = *(const ulonglong2*)&As[kk][m0 + 4];
            float4 b = *(const float4*)&Bs[kk][n0];
            ull bd0 = pack2(b.x, b.x), bd1 = pack2(b.y, b.y);
            ull bd2 = pack2(b.z, b.z), bd3 = pack2(b.w, b.w);
            ffma2(acc2[0][0], aP01.x, bd0); ffma2(acc2[0][1], aP01.x, bd1);
            ffma2(acc2[0][2], aP01.x, bd2); ffma2(acc2[0][3], aP01.x, bd3);
            ffma2(acc2[1][0], aP01.y, bd0); ffma2(acc2[1][1], aP01.y, bd1);
            ffma2(acc2[1][2], aP01.y, bd2); ffma2(acc2[1][3], aP01.y, bd3);
            ffma2(acc2[2][0], aP23.x, bd0); ffma2(acc2[2][1], aP23.x, bd1);
            ffma2(acc2[2][2], aP23.x, bd2); ffma2(acc2[2][3], aP23.x, bd3);
            ffma2(acc2[3][0], aP23.y, bd0); ffma2(acc2[3][1], aP23.y, bd1);
            ffma2(acc2[3][2], aP23.y, bd2); ffma2(acc2[3][3], aP23.y, bd3);
        }
        __syncthreads();
    }

    float* Cw = C + (size_t)blockIdx.z * ((size_t)M * N);
    #pragma unroll
    for (int p = 0; p < 4; p++) {
        int rowA = bm + m0 + 2 * p;
        int rowB = rowA + 1;
        float rsA = rs ? rs[rowA] : 1.f;
        float rsB = rs ? rs[rowB] : 1.f;
        float va[4], vb[4];
        #pragma unroll
        for (int j = 0; j < 4; j++) {
            float2 v = unpack2(acc2[p][j]);
            float a = v.x, b = v.y;
            if (bias) { float bj = bias[bn + n0 + j]; a += bj; b += bj; }
            if (ACT) {
                a = a > 0.f ? a : SLOPE_F * a;
                b = b > 0.f ? b : SLOPE_F * b;
            }
            if (EXPOUT) { a = __expf(a); b = __expf(b); }
            va[j] = a * rsA; vb[j] = b * rsB;
        }
        *(float4*)(Cw + (size_t)rowA * N + bn + n0) =
            make_float4(va[0], va[1], va[2], va[3]);
        *(float4*)(Cw + (size_t)rowB * N + bn + n0) =
            make_float4(vb[0], vb[1], vb[2], vb[3]);
    }
}

// ---------------- fp32 GEMM: 64x64 tile (for NS x 128 x 128 head GEMMs) -----
template<bool ACT, bool SUBPRE>
__global__ __launch_bounds__(256) void k_gemm64(
    const float* __restrict__ A, const float* __restrict__ B,
    const float* __restrict__ bias, const float* __restrict__ rs,
    const float* __restrict__ pre, float* __restrict__ C,
    int M, int N, int K)
{
    __shared__ alignas(16) float As[16][68];
    __shared__ alignas(16) float Bs[16][68];
    const int bm = blockIdx.y * 64, bn = blockIdx.x * 64;
    const int tid = threadIdx.x;
    const int a_m = tid >> 2, a_k = (tid & 3) * 4;
    const int ty = tid >> 4, tx = tid & 15;
    const int m0 = ty * 4, n0 = tx * 4;

    ull acc2[2][4];
    #pragma unroll
    for (int p = 0; p < 2; p++)
        #pragma unroll
        for (int j = 0; j < 4; j++) acc2[p][j] = 0ull;

    for (int k0 = 0; k0 < K; k0 += 16) {
        float4 av = *(const float4*)(A + (size_t)(bm + a_m) * K + k0 + a_k);
        As[a_k + 0][a_m] = av.x; As[a_k + 1][a_m] = av.y;
        As[a_k + 2][a_m] = av.z; As[a_k + 3][a_m] = av.w;
        float4 bv = *(const float4*)(B + (size_t)(bn + a_m) * K + k0 + a_k);
        Bs[a_k + 0][a_m] = bv.x; Bs[a_k + 1][a_m] = bv.y;
        Bs[a_k + 2][a_m] = bv.z; Bs[a_k + 3][a_m] = bv.w;
        __syncthreads();
        #pragma unroll
        for (int kk = 0; kk < 16; kk++) {
            ulonglong2 aP = *(const ulonglong2*)&As[kk][m0];
            float4 b = *(const float4*)&Bs[kk][n0];
            ull bd0 = pack2(b.x, b.x), bd1 = pack2(b.y, b.y);
            ull bd2 = pack2(b.z, b.z), bd3 = pack2(b.w, b.w);
            ffma2(acc2[0][0], aP.x, bd0); ffma2(acc2[0][1], aP.x, bd1);
            ffma2(acc2[0][2], aP.x, bd2); ffma2(acc2[0][3], aP.x, bd3);
            ffma2(acc2[1][0], aP.y, bd0); ffma2(acc2[1][1], aP.y, bd1);
            ffma2(acc2[1][2], aP.y, bd2); ffma2(acc2[1][3], aP.y, bd3);
        }
        __syncthreads();
    }

    #pragma unroll
    for (int p = 0; p < 2; p++) {
        int rowA = bm + m0 + 2 * p;
        int rowB = rowA + 1;
        float rsA = rs ? rs[rowA] : 1.f;
        float rsB = rs ? rs[rowB] : 1.f;
        float va[4], vb[4];
        #pragma unroll
        for (int j = 0; j < 4; j++) {
            float2 v = unpack2(acc2[p][j]);
            float a = v.x, b = v.y;
            if (bias) { float bj = bias[bn + n0 + j]; a += bj; b += bj; }
            if (ACT) {
                a = a > 0.f ? a : SLOPE_F * a;
                b = b > 0.f ? b : SLOPE_F * b;
            }
            a *= rsA; b *= rsB;
            if (SUBPRE) {
                a = pre[(size_t)rowA * N + bn + n0 + j] - a;
                b = pre[(size_t)rowB * N + bn + n0 + j] - b;
            }
            va[j] = a; vb[j] = b;
        }
        *(float4*)(C + (size_t)rowA * N + bn + n0) =
            make_float4(va[0], va[1], va[2], va[3]);
        *(float4*)(C + (size_t)rowB * N + bn + n0) =
            make_float4(vb[0], vb[1], vb[2], vb[3]);
    }
}

// reduce over split-K partial slices: C = sum_z P[z]
__global__ void k_reduce(const float* __restrict__ P, float* __restrict__ C,
                         int nslice, int total4)
{
    int i = blockIdx.x * blockDim.x + threadIdx.x;
    if (i >= total4) return;
    size_t b = (size_t)i * 4;
    float4 s = make_float4(0.f, 0.f, 0.f, 0.f);
    for (int z = 0; z < nslice; z++) {
        float4 v = *(const float4*)(P + (size_t)z * total4 * 4 + b);
        s.x += v.x; s.y += v.y; s.z += v.z; s.w += v.w;
    }
    *(float4*)(C + b) = s;
}

// ---------------- persistent GRU recurrent kernel ---------------------------
// 384 threads, mapping (2 outputs, half-k): o = tid%192, half = tid/192.
// Thread owns Whh rows o and o+192 restricted to its 64-element k-half.
// Matvec processes TWO rows per iteration (4 independent chains; row r+1's
// LDS overlaps row r's FFMA tail -> hides LDS latency at 12 warps/SM).
template<bool WRITE_SEQ>
__global__ __launch_bounds__(384, 1) void k_gru(
    const float* __restrict__ gi, const float* __restrict__ Whh,
    const float* __restrict__ bhh, float* __restrict__ hout)
{
    extern __shared__ float sm[];
    float* h_sh = sm;                          // GRROWS*128
    float* ghA  = sm + GRROWS * HD;            // GRROWS*384
    float* ghB  = ghA + GRROWS * GD;           // GRROWS*384
    float* gi_sh = ghB + GRROWS * GD;          // GRROWS*384
    const int tid = threadIdx.x;
    const int o = tid % 192;
    const int half = tid / 192;                 // 0 or 1
    const int o2 = o + 192;
    const int base = blockIdx.x * GRROWS;
    const int rows = (NS - base < GRROWS) ? (NS - base) : GRROWS;
    float* ghOut = half ? ghB : ghA;

    // weights: rows o and o+192, k in [64*half, 64*half+64)
    ull wq[64];
    {
        const ulonglong2* wg0 =
            (const ulonglong2*)(Whh + (size_t)o * HD + half * 64);
        const ulonglong2* wg1 =
            (const ulonglong2*)(Whh + (size_t)o2 * HD + half * 64);
        #pragma unroll
        for (int q = 0; q < 16; q++) {
            ulonglong2 t0 = wg0[q];
            wq[2 * q] = t0.x; wq[2 * q + 1] = t0.y;
        }
        #pragma unroll
        for (int q = 0; q < 16; q++) {
            ulonglong2 t1 = wg1[q];
            wq[32 + 2 * q] = t1.x; wq[32 + 2 * q + 1] = t1.y;
        }
    }
    const float bo0 = half ? 0.f : bhh[o];
    const float bo1 = half ? 0.f : bhh[o2];
    for (int idx = tid; idx < rows * HD; idx += 384) h_sh[idx] = 0.f;

    // gi prefetch: 28*96 float4 slots; thread does 8 strided slots
    const int pr = tid / 12, pc = tid % 12;
    const bool pact = (pr < rows);
    {
        const float* src = gi + ((size_t)(base + pr) * TS + 0) * GD;
        if (pact) {
            #pragma unroll
            for (int i = 0; i < 8; i++) {
                int f = pc + 12 * i;
                cp16(gi_sh + pr * GD + f * 4, src + f * 4);
            }
        }
        cp_commit();
    }
    __syncthreads();

    for (int t = 0; t < TS; t++) {
        // partial matvec: TWO rows per iteration, 4 independent chains
        #pragma unroll 1
        for (int r = 0; r < rows; r += 2) {
            const ulonglong2* hp0 =
                (const ulonglong2*)(h_sh + r * HD + half * 64);
            const ulonglong2* hp1 =
                (const ulonglong2*)(h_sh + (r + 1) * HD + half * 64);
            ull a0 = 0ull, b0 = 0ull, a1 = 0ull, b1 = 0ull;
            #pragma unroll
            for (int q = 0; q < 16; q++) {
                ulonglong2 x0 = hp0[q];
                ulonglong2 x1 = hp1[q];
                ffma2(a0, x0.x, wq[2 * q]);
                ffma2(b0, x0.x, wq[32 + 2 * q]);
                ffma2(a1, x1.x, wq[2 * q]);
                ffma2(b1, x1.x, wq[32 + 2 * q]);
                ffma2(a0, x0.y, wq[2 * q + 1]);
                ffma2(b0, x0.y, wq[32 + 2 * q + 1]);
                ffma2(a1, x1.y, wq[2 * q + 1]);
                ffma2(b1, x1.y, wq[32 + 2 * q + 1]);
            }
            float2 pa0 = unpack2(a0), pb0 = unpack2(b0);
            float2 pa1 = unpack2(a1), pb1 = unpack2(b1);
            ghOut[r * GD + o]        = (pa0.x + pa0.y) + bo0;
            ghOut[r * GD + o2]       = (pb0.x + pb0.y) + bo1;
            ghOut[(r + 1) * GD + o]  = (pa1.x + pa1.y) + bo0;
            ghOut[(r + 1) * GD + o2] = (pb1.x + pb1.y) + bo1;
        }
        cp_wait_all();
        __syncthreads();
        // gate update (sum the two partial buffers)
        #pragma unroll 1
        for (int idx = tid; idx < rows * HD; idx += 384) {
            int r = idx >> 7, j = idx & 127;
            float gir = gi_sh[r * GD + j];
            float giz = gi_sh[r * GD + j + 128];
            float gin = gi_sh[r * GD + j + 256];
            float ghr = ghA[r * GD + j]       + ghB[r * GD + j];
            float ghz = ghA[r * GD + j + 128] + ghB[r * GD + j + 128];
            float ghn = ghA[r * GD + j + 256] + ghB[r * GD + j + 256];
            float rg = __fdividef(1.f, 1.f + __expf(-(gir + ghr)));
            float zg = __fdividef(1.f, 1.f + __expf(-(giz + ghz)));
            float a2 = gin + rg * ghn;
            float ng = 1.f - __fdividef(2.f, __expf(2.f * a2) + 1.f);
            float hprev = h_sh[idx];
            float hn = (1.f - zg) * ng + zg * hprev;
            h_sh[idx] = hn;
            if (WRITE_SEQ)
                hout[((size_t)(base + r) * TS + t) * HD + j] = hn;
            else if (t == TS - 1)
                hout[(size_t)(base + r) * HD + j] = hn;
        }
        __syncthreads();
        // prefetch gi for t+1
        if (t + 1 < TS) {
            const float* src = gi + ((size_t)(base + pr) * TS + (t + 1)) * GD;
            if (pact) {
                #pragma unroll
                for (int i = 0; i < 8; i++) {
                    int f = pc + 12 * i;
                    cp16(gi_sh + pr * GD + f * 4, src + f * 4);
                }
            }
            cp_commit();
        }
    }
}

// ---------------- small helpers --------------------------------------------
__global__ void k_zero(float* p, int n) {
    int i = blockIdx.x * blockDim.x + threadIdx.x;
    if (i < n) p[i] = 0.f;
}

__global__ void k_rownorm(const float* __restrict__ src, float* __restrict__ dst) {
    int row = blockIdx.x * 8 + (threadIdx.x >> 5);
    int lane = threadIdx.x & 31;
    const float4* s4 = (const float4*)(src + (size_t)row * HD);
    float4 v = s4[lane];
    float ss = v.x*v.x + v.y*v.y + v.z*v.z + v.w*v.w;
    #pragma unroll
    for (int off = 16; off; off >>= 1) ss += __shfl_xor_sync(0xffffffffu, ss, off);
    float n = sqrtf(ss);
    float inv = (n > 0.f) ? 1.f / n : 0.f;
    ((float4*)(dst + (size_t)row * HD))[lane] =
        make_float4(v.x*inv, v.y*inv, v.z*inv, v.w*inv);
}

// top-K=20 per row of |sim| (diag excluded), jax-stable ties (lowest index).
// Segment-max scheme: 128 segment maxima over 32 elems each; per round,
// reduce 128 maxima, then rescan only the winning segment.
__global__ __launch_bounds__(256) void k_topk(
    const float* __restrict__ sim, int* __restrict__ tidx,
    float* __restrict__ tval, float* __restrict__ colsum)
{
    int i = blockIdx.x;
    __shared__ float sabs[NS];
    __shared__ float segv[128];
    __shared__ int   segi[128];
    __shared__ float bcv[4];
    __shared__ int   bci[4];
    __shared__ int   sel;
    const int tid = threadIdx.x;
    const float* row = sim + (size_t)i * NS;

    // vectorized |row| into SMEM
    for (int c4 = tid; c4 < NS / 4; c4 += 256) {
        float4 v = *(const float4*)(row + c4 * 4);
        float4 a = make_float4(fabsf(v.x), fabsf(v.y), fabsf(v.z), fabsf(v.w));
        *(float4*)&sabs[c4 * 4] = a;
    }
    __syncthreads();
    if (tid == 0) sabs[i] = -1.f;   // exclude diagonal
    __syncthreads();

    // build segment maxima (thread s scans its 32, ascending -> lowest idx tie)
    if (tid < 128) {
        float bv = -2.f; int bi = tid * 32;
        #pragma unroll 4
        for (int j = 0; j < 32; j++) {
            float v = sabs[tid * 32 + j];
            if (v > bv) { bv = v; bi = tid * 32 + j; }
        }
        segv[tid] = bv; segi[tid] = bi;
    }
    __syncthreads();

    for (int k = 0; k < NK; k++) {
        if (tid < 128) {
            float bv = segv[tid]; int bi = segi[tid];
            #pragma unroll
            for (int off = 16; off; off >>= 1) {
                float ov = __shfl_down_sync(0xffffffffu, bv, off);
                int   oi = __shfl_down_sync(0xffffffffu, bi, off);
                if (ov > bv || (ov == bv && oi < bi)) { bv = ov; bi = oi; }
            }
            if ((tid & 31) == 0) { bcv[tid >> 5] = bv; bci[tid >> 5] = bi; }
        }
        __syncthreads();
        if (tid == 0) {
            float bv = bcv[0]; int bi = bci[0];
            #pragma unroll
            for (int w = 1; w < 4; w++)
                if (bcv[w] > bv || (bcv[w] == bv && bci[w] < bi)) {
                    bv = bcv[w]; bi = bci[w];
                }
            tidx[i * NK + k] = bi;
            float sv = row[bi];
            tval[i * NK + k] = sv;
            atomicAdd(&colsum[bi], sv);
            sabs[bi] = -2.f;
            sel = bi;
        }
        __syncthreads();
        // rescan the dirty segment with warp 0
        if (tid < 32) {
            int s = sel >> 5;
            int idx = s * 32 + tid;
            float bv = sabs[idx]; int bi = idx;
            #pragma unroll
            for (int off = 16; off; off >>= 1) {
                float ov = __shfl_down_sync(0xffffffffu, bv, off);
                int   oi = __shfl_down_sync(0xffffffffu, bi, off);
                if (ov > bv || (ov == bv && oi < bi)) { bv = ov; bi = oi; }
            }
            if (tid == 0) { segv[s] = bv; segi[s] = bi; }
        }
        __syncthreads();
    }
}

__global__ void k_scatter(const int* __restrict__ tidx, const float* __restrict__ tval,
                          const float* __restrict__ g, float* __restrict__ concept)
{
    int i = blockIdx.x, d = threadIdx.x;
    float gv = g[(size_t)i * HD + d];
    #pragma unroll
    for (int k = 0; k < NK; k++) {
        int c = __ldg(&tidx[i * NK + k]);
        float v = __ldg(&tval[i * NK + k]);
        atomicAdd(&concept[(size_t)c * HD + d], v * gv);
    }
}

__global__ void k_diag_valid(const float* __restrict__ colsum, const float* __restrict__ sim,
                             const float* __restrict__ g, float* __restrict__ concept,
                             float* __restrict__ valid)
{
    int j = blockIdx.x, t = threadIdx.x;
    float cs = colsum[j];
    float v = concept[(size_t)j * HD + t];
    if (cs != 0.f) {
        float dg = sim[(size_t)j * NS + j];
        v += dg * g[(size_t)j * HD + t];
        concept[(size_t)j * HD + t] = v;
    }
    float s = v;
    #pragma unroll
    for (int off = 16; off; off >>= 1) s += __shfl_xor_sync(0xffffffffu, s, off);
    __shared__ float ws[4];
    if ((t & 31) == 0) ws[t >> 5] = s;
    __syncthreads();
    if (t == 0) {
        float tot = ws[0] + ws[1] + ws[2] + ws[3];
        valid[j] = (tot != 0.f) ? 1.f : 0.f;
    }
}

// column sums of E (E already holds exp(S))
__global__ void k_colz(const float* __restrict__ E, float* __restrict__ colZ) {
    int col = blockIdx.x * 128 + threadIdx.x;
    int r0 = blockIdx.y * 128;
    float s = 0.f;
    for (int r = r0; r < r0 + 128; r++) s += E[(size_t)r * NS + col];
    atomicAdd(&colZ[col], s);
}

__global__ void k_recip(float* __restrict__ colZ) {
    int i = blockIdx.x * blockDim.x + threadIdx.x;
    if (i < NS) colZ[i] = __fdividef(1.f, colZ[i]);
}

// attn = E * rcpZ  (E already exp'd; in place)
__global__ void k_scale(float* __restrict__ E, const float* __restrict__ colZ) {
    size_t q = (size_t)blockIdx.x * blockDim.x + threadIdx.x;
    size_t b = q * 4;
    float4 v = *(float4*)(E + b);
    int c = (int)(b & (NS - 1));
    float4 z = *(const float4*)(colZ + c);
    v.x *= z.x; v.y *= z.y; v.z *= z.z; v.w *= z.w;
    *(float4*)(E + b) = v;
}

__global__ void k_final(const float* __restrict__ fore, const float* __restrict__ indi,
                        const float* __restrict__ Wout, const float* __restrict__ bout,
                        float* __restrict__ out)
{
    int row = blockIdx.x * 8 + (threadIdx.x >> 5);
    int lane = threadIdx.x & 31;
    float4 a = ((const float4*)(fore + (size_t)row * HD))[lane];
    float4 b = ((const float4*)(indi + (size_t)row * HD))[lane];
    float4 w = ((const float4*)Wout)[lane];
    float s = (a.x+b.x)*w.x + (a.y+b.y)*w.y + (a.z+b.z)*w.z + (a.w+b.w)*w.w;
    #pragma unroll
    for (int off = 16; off; off >>= 1) s += __shfl_xor_sync(0xffffffffu, s, off);
    if (lane == 0) out[row] = s + bout[0];
}

// ---------------- driver -----------------------------------------------------
extern "C" void kernel_launch(void* const* d_in, const int* in_sizes, int n_in,
                              void* d_out, int out_size)
{
    const float* x     = (const float*)d_in[0];
    const float* Wih0  = (const float*)d_in[1];
    const float* Whh0  = (const float*)d_in[2];
    const float* bih0  = (const float*)d_in[3];
    const float* bhh0  = (const float*)d_in[4];
    const float* Wih1  = (const float*)d_in[5];
    const float* Whh1  = (const float*)d_in[6];
    const float* bih1  = (const float*)d_in[7];
    const float* bhh1  = (const float*)d_in[8];
    const float* W_hc  = (const float*)d_in[9];
    const float* b_hc  = (const float*)d_in[10];
    const float* W_hs  = (const float*)d_in[11];
    const float* b_hs  = (const float*)d_in[12];
    const float* W_fore= (const float*)d_in[13];
    const float* b_fore= (const float*)d_in[14];
    const float* W_back= (const float*)d_in[15];
    const float* b_back= (const float*)d_in[16];
    const float* W_indi= (const float*)d_in[17];
    const float* b_indi= (const float*)d_in[18];
    const float* W_out = (const float*)d_in[19];
    const float* b_out = (const float*)d_in[20];
    float* out = (float*)d_out;

    float *gi, *h0, *g, *gn, *sim, *colsum, *colZ, *valid, *concept;
    float *cf, *cfn, *hs, *t1, *t2, *t3, *t4, *tval;
    int* tidx;
    cudaGetSymbolAddress((void**)&gi,      d_gi);
    cudaGetSymbolAddress((void**)&h0,      d_h0);
    cudaGetSymbolAddress((void**)&g,       d_g);
    cudaGetSymbolAddress((void**)&gn,      d_gn);
    cudaGetSymbolAddress((void**)&sim,     d_sim);
    cudaGetSymbolAddress((void**)&tidx,    d_tidx);
    cudaGetSymbolAddress((void**)&tval,    d_tval);
    cudaGetSymbolAddress((void**)&colsum,  d_colsum);
    cudaGetSymbolAddress((void**)&colZ,    d_colZ);
    cudaGetSymbolAddress((void**)&valid,   d_valid);
    cudaGetSymbolAddress((void**)&concept, d_concept);
    cudaGetSymbolAddress((void**)&cf,      d_cf);
    cudaGetSymbolAddress((void**)&cfn,     d_cfn);
    cudaGetSymbolAddress((void**)&hs,      d_hsb);
    cudaGetSymbolAddress((void**)&t1,      d_t1);
    cudaGetSymbolAddress((void**)&t2,      d_t2);
    cudaGetSymbolAddress((void**)&t3,      d_t3);
    cudaGetSymbolAddress((void**)&t4,      d_t4);

    // h 28*128 + ghA/ghB 2*28*384 + gi 28*384 floats = 143360 B
    const int GRU_SMEM = (GRROWS * HD + 3 * GRROWS * GD) * 4;
    cudaFuncSetAttribute((const void*)k_gru<true>,
                         cudaFuncAttributeMaxDynamicSharedMemorySize, GRU_SMEM);
    cudaFuncSetAttribute((const void*)k_gru<false>,
                         cudaFuncAttributeMaxDynamicSharedMemorySize, GRU_SMEM);

    const int MT = NS * TS;         // 262144
    const int GRU_GRID = (NS + GRROWS - 1) / GRROWS;  // 147

    // Launch order: gru0 is our 4th launch so ncu (-s 5 -c 1, one harness
    // pre-launch) captures the GRU kernel.
    // #1 gi0 = x @ Wih0^T + bih0
    k_gemm<true, false, false><<<dim3(GD / 64, MT / 128, 1), 256>>>(
        x, Wih0, bih0, nullptr, gi, MT, GD, FI, FI);
    // #2, #3 tiny zeros (needed later)
    k_zero<<<(NS + 255) / 256, 256>>>(colsum, NS);
    k_zero<<<(NS + 255) / 256, 256>>>(colZ, NS);
    // #4 GRU layer 0 (writes full sequence)  <- ncu capture target
    k_gru<true><<<GRU_GRID, 384, GRU_SMEM>>>(gi, Whh0, bhh0, h0);
    // gi1 = h0 @ Wih1^T + bih1
    k_gemm<true, false, false><<<dim3(GD / 64, MT / 128, 1), 256>>>(
        h0, Wih1, bih1, nullptr, gi, MT, GD, HD, HD);
    // GRU layer 1 (writes final hidden only -> g)
    k_gru<false><<<GRU_GRID, 384, GRU_SMEM>>>(gi, Whh1, bhh1, g);

    // concept accumulator zero (before scatter)
    k_zero<<<(NS * HD + 255) / 256, 256>>>(concept, NS * HD);

    // normalized g, sim = gn @ gn^T
    k_rownorm<<<NS / 8, 256>>>(g, gn);
    k_gemm<true, false, false><<<dim3(NS / 64, NS / 128, 1), 256>>>(
        gn, gn, nullptr, nullptr, sim, NS, NS, HD, HD);

    // top-K selection + concept aggregation
    k_topk<<<NS, 256>>>(sim, tidx, tval, colsum);
    k_scatter<<<NS, 128>>>(tidx, tval, g, concept);
    k_diag_valid<<<NS, 128>>>(colsum, sim, g, concept, valid);

    // cf = lrelu(concept @ W_hc^T + b_hc) * valid
    k_gemm64<true, false><<<dim3(HD / 64, NS / 64), 256>>>(
        concept, W_hc, b_hc, valid, nullptr, cf, NS, HD, HD);
    k_rownorm<<<NS / 8, 256>>>(cf, cfn);

    // E = exp(gn @ cfn^T)  (exp fused into GEMM epilogue)
    k_gemm<true, false, true><<<dim3(NS / 64, NS / 128, 1), 256>>>(
        gn, cfn, nullptr, nullptr, sim, NS, NS, HD, HD);
    k_colz<<<dim3(NS / 128, NS / 128), 128>>>(sim, colZ);
    k_recip<<<NS / 256, 256>>>(colZ);
    k_scale<<<(int)(((size_t)NS * NS / 4) / 256), 256>>>(sim, colZ);

    // t1 = attn @ cf  (K=4096, split-K=8 into gi scratch, then reduce)
    k_gemm<false, false, false><<<dim3(HD / 64, NS / 128, 8), 256>>>(
        sim, cf, nullptr, nullptr, gi, NS, HD, NS, NS / 8);
    k_reduce<<<(NS * HD / 4 + 255) / 256, 256>>>(gi, t1, 8, NS * HD / 4);

    // hs = lrelu(t1 @ W_hs^T + b_hs)
    k_gemm64<true, false><<<dim3(HD / 64, NS / 64), 256>>>(
        t1, W_hs, b_hs, nullptr, nullptr, hs, NS, HD, HD);

    // t3 = g - lrelu(hs @ W_back^T + b_back)   (fused subtract)
    k_gemm64<true, true><<<dim3(HD / 64, NS / 64), 256>>>(
        hs, W_back, b_back, nullptr, g, t3, NS, HD, HD);
    // t2 = lrelu(hs @ W_fore^T + b_fore)
    k_gemm64<true, false><<<dim3(HD / 64, NS / 64), 256>>>(
        hs, W_fore, b_fore, nullptr, nullptr, t2, NS, HD, HD);
    // t4 = lrelu(t3 @ W_indi^T + b_indi)
    k_gemm64<true, false><<<dim3(HD / 64, NS / 64), 256>>>(
        t3, W_indi, b_indi, nullptr, nullptr, t4, NS, HD, HD);
    k_final<<<NS / 8, 256>>>(t2, t4, W_out, b_out, out);
}

// round 10
// speedup vs baseline: 1.2335x; 1.0308x over previous
#include <cuda_runtime.h>
#include <math.h>
#include <stdint.h>
#include <stddef.h>

// Problem dims (fixed by the dataset)
#define NS   4096      // batch
#define TS   64        // timesteps
#define FI   32        // input features
#define HD   128       // hidden
#define GD   384       // 3*H
#define NK   20        // top-k
#define SLOPE_F 0.2f
#define GRROWS 28      // batch rows per GRU CTA (147 CTAs -> all 148 SMs)

typedef unsigned long long ull;

// ---------------- f32x2 packed helpers (Blackwell FFMA2) --------------------
__device__ __forceinline__ ull pack2(float lo, float hi) {
    ull r;
    asm("mov.b64 %0, {%1, %2};" : "=l"(r) : "f"(lo), "f"(hi));
    return r;
}
__device__ __forceinline__ float2 unpack2(ull v) {
    float2 r;
    asm("mov.b64 {%0, %1}, %2;" : "=f"(r.x), "=f"(r.y) : "l"(v));
    return r;
}
__device__ __forceinline__ void ffma2(ull& d, ull a, ull b) {
    asm("fma.rn.f32x2 %0, %1, %2, %0;" : "+l"(d) : "l"(a), "l"(b));
}

// ---------------- cp.async helpers -----------------------------------------
__device__ __forceinline__ void cp16(float* dst_sh, const float* src_g) {
    uint32_t d = (uint32_t)__cvta_generic_to_shared(dst_sh);
    asm volatile("cp.async.ca.shared.global [%0], [%1], 16;" :: "r"(d), "l"(src_g));
}
__device__ __forceinline__ void cp_commit() {
    asm volatile("cp.async.commit_group;");
}
__device__ __forceinline__ void cp_wait_all() {
    asm volatile("cp.async.wait_all;");
}

// ---------------- scratch (device globals; no runtime allocation) ----------
__device__ float d_gi[(size_t)NS * TS * GD];
__device__ float d_h0[(size_t)NS * TS * HD];
__device__ float d_g  [NS * HD];
__device__ float d_gn [NS * HD];
__device__ float d_sim[(size_t)NS * NS];
__device__ int   d_tidx[NS * NK];
__device__ float d_tval[NS * NK];
__device__ float d_colsum[NS];
__device__ float d_colZ[NS];
__device__ float d_valid[NS];
__device__ float d_concept[NS * HD];
__device__ float d_cf [NS * HD];
__device__ float d_cfn[NS * HD];
__device__ float d_hsb[NS * HD];
__device__ float d_t1 [NS * HD];
__device__ float d_t2 [NS * HD];
__device__ float d_t3 [NS * HD];
__device__ float d_t4 [NS * HD];

// ---------------- fp32 GEMM: 128x64 tile, 256 thr, 8x4 micro, FFMA2 ---------
// Register double-buffering: tile i+1's LDGs issue before tile i's compute,
// hiding DRAM/L2 latency behind the FFMA2 stream.
// EXPOUT: write __expf(result) (for fused softmax numerator)
template<bool TRANSB, bool ACT, bool EXPOUT>
__global__ __launch_bounds__(256) void k_gemm(
    const float* __restrict__ A, const float* __restrict__ B,
    const float* __restrict__ bias, const float* __restrict__ rs,
    float* __restrict__ C, int M, int N, int K, int ksplit)
{
    __shared__ alignas(16) float As[16][132];
    __shared__ alignas(16) float Bs[16][68];
    const int bm = blockIdx.y * 128, bn = blockIdx.x * 64;
    const int tid = threadIdx.x;
    const int kbase = blockIdx.z * ksplit;
    const int kend = kbase + ksplit;

    const int a_m = tid >> 1, a_k = (tid & 1) * 8;
    const int ty = tid >> 4, tx = tid & 15;
    const int m0 = ty * 8, n0 = tx * 4;
    const int b_n = tid >> 2, b_k = (tid & 3) * 4;     // TRANSB loader
    const int nb_k = tid >> 4, nb_n4 = (tid & 15) * 4; // non-trans loader

    ull acc2[4][4];
    #pragma unroll
    for (int p = 0; p < 4; p++)
        #pragma unroll
        for (int j = 0; j < 4; j++) acc2[p][j] = 0ull;

    // prologue: load tile 0 into registers
    float4 ra0, ra1, rb;
    {
        const float* Ap = A + (size_t)(bm + a_m) * K + kbase + a_k;
        ra0 = *(const float4*)(Ap);
        ra1 = *(const float4*)(Ap + 4);
        if (TRANSB)
            rb = *(const float4*)(B + (size_t)(bn + b_n) * K + kbase + b_k);
        else
            rb = *(const float4*)(B + (size_t)(kbase + nb_k) * N + bn + nb_n4);
    }

    for (int k0 = kbase; k0 < kend; k0 += 16) {
        // store current tile to SMEM
        As[a_k + 0][a_m] = ra0.x; As[a_k + 1][a_m] = ra0.y;
        As[a_k + 2][a_m] = ra0.z; As[a_k + 3][a_m] = ra0.w;
        As[a_k + 4][a_m] = ra1.x; As[a_k + 5][a_m] = ra1.y;
        As[a_k + 6][a_m] = ra1.z; As[a_k + 7][a_m] = ra1.w;
        if (TRANSB) {
            Bs[b_k + 0][b_n] = rb.x; Bs[b_k + 1][b_n] = rb.y;
            Bs[b_k + 2][b_n] = rb.z; Bs[b_k + 3][b_n] = rb.w;
        } else {
            *(float4*)&Bs[nb_k][nb_n4] = rb;
        }
        __syncthreads();
        // issue next tile's loads (overlap with compute below)
        if (k0 + 16 < kend) {
            const float* Ap = A + (size_t)(bm + a_m) * K + (k0 + 16) + a_k;
            ra0 = *(const float4*)(Ap);
            ra1 = *(const float4*)(Ap + 4);
            if (TRANSB)
                rb = *(const float4*)(B + (size_t)(bn + b_n) * K + (k0 + 16) + b_k);
            else
                rb = *(const float4*)(B + (size_t)(k0 + 16 + nb_k) * N + bn + nb_n4);
        }
        #pragma unroll
        for (int kk = 0; kk < 16; kk++) {
            ulonglong2 aP01 = *(const ulonglong2*)&As[kk][m0];
            ulonglong2 aP23 = *(const ulonglong2*)&As[kk][m0 + 4];
            float4 b = *(const float4*)&Bs[kk][n0];
            ull bd0 = pack2(b.x, b.x), bd1 = pack2(b.y, b.y);
            ull bd2 = pack2(b.z, b.z), bd3 = pack2(b.w, b.w);
            ffma2(acc2[0][0], aP01.x, bd0); ffma2(acc2[0][1], aP01.x, bd1);
            ffma2(acc2[0][2], aP01.x, bd2); ffma2(acc2[0][3], aP01.x, bd3);
            ffma2(acc2[1][0], aP01.y, bd0); ffma2(acc2[1][1], aP01.y, bd1);
            ffma2(acc2[1][2], aP01.y, bd2); ffma2(acc2[1][3], aP01.y, bd3);
            ffma2(acc2[2][0], aP23.x, bd0); ffma2(acc2[2][1], aP23.x, bd1);
            ffma2(acc2[2][2], aP23.x, bd2); ffma2(acc2[2][3], aP23.x, bd3);
            ffma2(acc2[3][0], aP23.y, bd0); ffma2(acc2[3][1], aP23.y, bd1);
            ffma2(acc2[3][2], aP23.y, bd2); ffma2(acc2[3][3], aP23.y, bd3);
        }
        __syncthreads();
    }

    float* Cw = C + (size_t)blockIdx.z * ((size_t)M * N);
    #pragma unroll
    for (int p = 0; p < 4; p++) {
        int rowA = bm + m0 + 2 * p;
        int rowB = rowA + 1;
        float rsA = rs ? rs[rowA] : 1.f;
        float rsB = rs ? rs[rowB] : 1.f;
        float va[4], vb[4];
        #pragma unroll
        for (int j = 0; j < 4; j++) {
            float2 v = unpack2(acc2[p][j]);
            float a = v.x, b = v.y;
            if (bias) { float bj = bias[bn + n0 + j]; a += bj; b += bj; }
            if (ACT) {
                a = a > 0.f ? a : SLOPE_F * a;
                b = b > 0.f ? b : SLOPE_F * b;
            }
            if (EXPOUT) { a = __expf(a); b = __expf(b); }
            va[j] = a * rsA; vb[j] = b * rsB;
        }
        *(float4*)(Cw + (size_t)rowA * N + bn + n0) =
            make_float4(va[0], va[1], va[2], va[3]);
        *(float4*)(Cw + (size_t)rowB * N + bn + n0) =
            make_float4(vb[0], vb[1], vb[2], vb[3]);
    }
}

// ---------------- fp32 GEMM: 64x64 tile (NS x 128 x 128 head GEMMs) ---------
// Register double-buffered like k_gemm.
template<bool ACT, bool SUBPRE>
__global__ __launch_bounds__(256) void k_gemm64(
    const float* __restrict__ A, const float* __restrict__ B,
    const float* __restrict__ bias, const float* __restrict__ rs,
    const float* __restrict__ pre, float* __restrict__ C,
    int M, int N, int K)
{
    __shared__ alignas(16) float As[16][68];
    __shared__ alignas(16) float Bs[16][68];
    const int bm = blockIdx.y * 64, bn = blockIdx.x * 64;
    const int tid = threadIdx.x;
    const int a_m = tid >> 2, a_k = (tid & 3) * 4;
    const int ty = tid >> 4, tx = tid & 15;
    const int m0 = ty * 4, n0 = tx * 4;

    ull acc2[2][4];
    #pragma unroll
    for (int p = 0; p < 2; p++)
        #pragma unroll
        for (int j = 0; j < 4; j++) acc2[p][j] = 0ull;

    float4 ra, rb;
    ra = *(const float4*)(A + (size_t)(bm + a_m) * K + a_k);
    rb = *(const float4*)(B + (size_t)(bn + a_m) * K + a_k);

    for (int k0 = 0; k0 < K; k0 += 16) {
        As[a_k + 0][a_m] = ra.x; As[a_k + 1][a_m] = ra.y;
        As[a_k + 2][a_m] = ra.z; As[a_k + 3][a_m] = ra.w;
        Bs[a_k + 0][a_m] = rb.x; Bs[a_k + 1][a_m] = rb.y;
        Bs[a_k + 2][a_m] = rb.z; Bs[a_k + 3][a_m] = rb.w;
        __syncthreads();
        if (k0 + 16 < K) {
            ra = *(const float4*)(A + (size_t)(bm + a_m) * K + k0 + 16 + a_k);
            rb = *(const float4*)(B + (size_t)(bn + a_m) * K + k0 + 16 + a_k);
        }
        #pragma unroll
        for (int kk = 0; kk < 16; kk++) {
            ulonglong2 aP = *(const ulonglong2*)&As[kk][m0];
            float4 b = *(const float4*)&Bs[kk][n0];
            ull bd0 = pack2(b.x, b.x), bd1 = pack2(b.y, b.y);
            ull bd2 = pack2(b.z, b.z), bd3 = pack2(b.w, b.w);
            ffma2(acc2[0][0], aP.x, bd0); ffma2(acc2[0][1], aP.x, bd1);
            ffma2(acc2[0][2], aP.x, bd2); ffma2(acc2[0][3], aP.x, bd3);
            ffma2(acc2[1][0], aP.y, bd0); ffma2(acc2[1][1], aP.y, bd1);
            ffma2(acc2[1][2], aP.y, bd2); ffma2(acc2[1][3], aP.y, bd3);
        }
        __syncthreads();
    }

    #pragma unroll
    for (int p = 0; p < 2; p++) {
        int rowA = bm + m0 + 2 * p;
        int rowB = rowA + 1;
        float rsA = rs ? rs[rowA] : 1.f;
        float rsB = rs ? rs[rowB] : 1.f;
        float va[4], vb[4];
        #pragma unroll
        for (int j = 0; j < 4; j++) {
            float2 v = unpack2(acc2[p][j]);
            float a = v.x, b = v.y;
            if (bias) { float bj = bias[bn + n0 + j]; a += bj; b += bj; }
            if (ACT) {
                a = a > 0.f ? a : SLOPE_F * a;
                b = b > 0.f ? b : SLOPE_F * b;
            }
            a *= rsA; b *= rsB;
            if (SUBPRE) {
                a = pre[(size_t)rowA * N + bn + n0 + j] - a;
                b = pre[(size_t)rowB * N + bn + n0 + j] - b;
            }
            va[j] = a; vb[j] = b;
        }
        *(float4*)(C + (size_t)rowA * N + bn + n0) =
            make_float4(va[0], va[1], va[2], va[3]);
        *(float4*)(C + (size_t)rowB * N + bn + n0) =
            make_float4(vb[0], vb[1], vb[2], vb[3]);
    }
}

// reduce over split-K partial slices: C = sum_z P[z]
__global__ void k_reduce(const float* __restrict__ P, float* __restrict__ C,
                         int nslice, int total4)
{
    int i = blockIdx.x * blockDim.x + threadIdx.x;
    if (i >= total4) return;
    size_t b = (size_t)i * 4;
    float4 s = make_float4(0.f, 0.f, 0.f, 0.f);
    for (int z = 0; z < nslice; z++) {
        float4 v = *(const float4*)(P + (size_t)z * total4 * 4 + b);
        s.x += v.x; s.y += v.y; s.z += v.z; s.w += v.w;
    }
    *(float4*)(C + b) = s;
}

// ---------------- persistent GRU recurrent kernel ---------------------------
// 384 threads, mapping (2 outputs, half-k): o = tid%192, half = tid/192.
// Thread owns Whh rows o and o+192 restricted to its 64-element k-half.
// Matvec processes TWO rows per iteration (4 independent chains).
template<bool WRITE_SEQ>
__global__ __launch_bounds__(384, 1) void k_gru(
    const float* __restrict__ gi, const float* __restrict__ Whh,
    const float* __restrict__ bhh, float* __restrict__ hout)
{
    extern __shared__ float sm[];
    float* h_sh = sm;                          // GRROWS*128
    float* ghA  = sm + GRROWS * HD;            // GRROWS*384
    float* ghB  = ghA + GRROWS * GD;           // GRROWS*384
    float* gi_sh = ghB + GRROWS * GD;          // GRROWS*384
    const int tid = threadIdx.x;
    const int o = tid % 192;
    const int half = tid / 192;                 // 0 or 1
    const int o2 = o + 192;
    const int base = blockIdx.x * GRROWS;
    const int rows = (NS - base < GRROWS) ? (NS - base) : GRROWS;
    float* ghOut = half ? ghB : ghA;

    // weights: rows o and o+192, k in [64*half, 64*half+64)
    ull wq[64];
    {
        const ulonglong2* wg0 =
            (const ulonglong2*)(Whh + (size_t)o * HD + half * 64);
        const ulonglong2* wg1 =
            (const ulonglong2*)(Whh + (size_t)o2 * HD + half * 64);
        #pragma unroll
        for (int q = 0; q < 16; q++) {
            ulonglong2 t0 = wg0[q];
            wq[2 * q] = t0.x; wq[2 * q + 1] = t0.y;
        }
        #pragma unroll
        for (int q = 0; q < 16; q++) {
            ulonglong2 t1 = wg1[q];
            wq[32 + 2 * q] = t1.x; wq[32 + 2 * q + 1] = t1.y;
        }
    }
    const float bo0 = half ? 0.f : bhh[o];
    const float bo1 = half ? 0.f : bhh[o2];
    for (int idx = tid; idx < rows * HD; idx += 384) h_sh[idx] = 0.f;

    // gi prefetch: 28*96 float4 slots; thread does 8 strided slots
    const int pr = tid / 12, pc = tid % 12;
    const bool pact = (pr < rows);
    {
        const float* src = gi + ((size_t)(base + pr) * TS + 0) * GD;
        if (pact) {
            #pragma unroll
            for (int i = 0; i < 8; i++) {
                int f = pc + 12 * i;
                cp16(gi_sh + pr * GD + f * 4, src + f * 4);
            }
        }
        cp_commit();
    }
    __syncthreads();

    for (int t = 0; t < TS; t++) {
        // partial matvec: TWO rows per iteration, 4 independent chains
        #pragma unroll 1
        for (int r = 0; r < rows; r += 2) {
            const ulonglong2* hp0 =
                (const ulonglong2*)(h_sh + r * HD + half * 64);
            const ulonglong2* hp1 =
                (const ulonglong2*)(h_sh + (r + 1) * HD + half * 64);
            ull a0 = 0ull, b0 = 0ull, a1 = 0ull, b1 = 0ull;
            #pragma unroll
            for (int q = 0; q < 16; q++) {
                ulonglong2 x0 = hp0[q];
                ulonglong2 x1 = hp1[q];
                ffma2(a0, x0.x, wq[2 * q]);
                ffma2(b0, x0.x, wq[32 + 2 * q]);
                ffma2(a1, x1.x, wq[2 * q]);
                ffma2(b1, x1.x, wq[32 + 2 * q]);
                ffma2(a0, x0.y, wq[2 * q + 1]);
                ffma2(b0, x0.y, wq[32 + 2 * q + 1]);
                ffma2(a1, x1.y, wq[2 * q + 1]);
                ffma2(b1, x1.y, wq[32 + 2 * q + 1]);
            }
            float2 pa0 = unpack2(a0), pb0 = unpack2(b0);
            float2 pa1 = unpack2(a1), pb1 = unpack2(b1);
            ghOut[r * GD + o]        = (pa0.x + pa0.y) + bo0;
            ghOut[r * GD + o2]       = (pb0.x + pb0.y) + bo1;
            ghOut[(r + 1) * GD + o]  = (pa1.x + pa1.y) + bo0;
            ghOut[(r + 1) * GD + o2] = (pb1.x + pb1.y) + bo1;
        }
        cp_wait_all();
        __syncthreads();
        // gate update (sum the two partial buffers)
        #pragma unroll 1
        for (int idx = tid; idx < rows * HD; idx += 384) {
            int r = idx >> 7, j = idx & 127;
            float gir = gi_sh[r * GD + j];
            float giz = gi_sh[r * GD + j + 128];
            float gin = gi_sh[r * GD + j + 256];
            float ghr = ghA[r * GD + j]       + ghB[r * GD + j];
            float ghz = ghA[r * GD + j + 128] + ghB[r * GD + j + 128];
            float ghn = ghA[r * GD + j + 256] + ghB[r * GD + j + 256];
            float rg = __fdividef(1.f, 1.f + __expf(-(gir + ghr)));
            float zg = __fdividef(1.f, 1.f + __expf(-(giz + ghz)));
            float a2 = gin + rg * ghn;
            float ng = 1.f - __fdividef(2.f, __expf(2.f * a2) + 1.f);
            float hprev = h_sh[idx];
            float hn = (1.f - zg) * ng + zg * hprev;
            h_sh[idx] = hn;
            if (WRITE_SEQ)
                hout[((size_t)(base + r) * TS + t) * HD + j] = hn;
            else if (t == TS - 1)
                hout[(size_t)(base + r) * HD + j] = hn;
        }
        __syncthreads();
        // prefetch gi for t+1
        if (t + 1 < TS) {
            const float* src = gi + ((size_t)(base + pr) * TS + (t + 1)) * GD;
            if (pact) {
                #pragma unroll
                for (int i = 0; i < 8; i++) {
                    int f = pc + 12 * i;
                    cp16(gi_sh + pr * GD + f * 4, src + f * 4);
                }
            }
            cp_commit();
        }
    }
}

// ---------------- small helpers --------------------------------------------
__global__ void k_zero(float* p, int n) {
    int i = blockIdx.x * blockDim.x + threadIdx.x;
    if (i < n) p[i] = 0.f;
}

__global__ void k_rownorm(const float* __restrict__ src, float* __restrict__ dst) {
    int row = blockIdx.x * 8 + (threadIdx.x >> 5);
    int lane = threadIdx.x & 31;
    const float4* s4 = (const float4*)(src + (size_t)row * HD);
    float4 v = s4[lane];
    float ss = v.x*v.x + v.y*v.y + v.z*v.z + v.w*v.w;
    #pragma unroll
    for (int off = 16; off; off >>= 1) ss += __shfl_xor_sync(0xffffffffu, ss, off);
    float n = sqrtf(ss);
    float inv = (n > 0.f) ? 1.f / n : 0.f;
    ((float4*)(dst + (size_t)row * HD))[lane] =
        make_float4(v.x*inv, v.y*inv, v.z*inv, v.w*inv);
}

// top-K=20 per row of |sim| (diag excluded), jax-stable ties (lowest index).
// Segment-max scheme: 128 segment maxima over 32 elems each; per round,
// reduce 128 maxima, then rescan only the winning segment.
__global__ __launch_bounds__(256) void k_topk(
    const float* __restrict__ sim, int* __restrict__ tidx,
    float* __restrict__ tval, float* __restrict__ colsum)
{
    int i = blockIdx.x;
    __shared__ float sabs[NS];
    __shared__ float segv[128];
    __shared__ int   segi[128];
    __shared__ float bcv[4];
    __shared__ int   bci[4];
    __shared__ int   sel;
    const int tid = threadIdx.x;
    const float* row = sim + (size_t)i * NS;

    for (int c4 = tid; c4 < NS / 4; c4 += 256) {
        float4 v = *(const float4*)(row + c4 * 4);
        float4 a = make_float4(fabsf(v.x), fabsf(v.y), fabsf(v.z), fabsf(v.w));
        *(float4*)&sabs[c4 * 4] = a;
    }
    __syncthreads();
    if (tid == 0) sabs[i] = -1.f;
    __syncthreads();

    if (tid < 128) {
        float bv = -2.f; int bi = tid * 32;
        #pragma unroll 4
        for (int j = 0; j < 32; j++) {
            float v = sabs[tid * 32 + j];
            if (v > bv) { bv = v; bi = tid * 32 + j; }
        }
        segv[tid] = bv; segi[tid] = bi;
    }
    __syncthreads();

    for (int k = 0; k < NK; k++) {
        if (tid < 128) {
            float bv = segv[tid]; int bi = segi[tid];
            #pragma unroll
            for (int off = 16; off; off >>= 1) {
                float ov = __shfl_down_sync(0xffffffffu, bv, off);
                int   oi = __shfl_down_sync(0xffffffffu, bi, off);
                if (ov > bv || (ov == bv && oi < bi)) { bv = ov; bi = oi; }
            }
            if ((tid & 31) == 0) { bcv[tid >> 5] = bv; bci[tid >> 5] = bi; }
        }
        __syncthreads();
        if (tid == 0) {
            float bv = bcv[0]; int bi = bci[0];
            #pragma unroll
            for (int w = 1; w < 4; w++)
                if (bcv[w] > bv || (bcv[w] == bv && bci[w] < bi)) {
                    bv = bcv[w]; bi = bci[w];
                }
            tidx[i * NK + k] = bi;
            float sv = row[bi];
            tval[i * NK + k] = sv;
            atomicAdd(&colsum[bi], sv);
            sabs[bi] = -2.f;
            sel = bi;
        }
        __syncthreads();
        if (tid < 32) {
            int s = sel >> 5;
            int idx = s * 32 + tid;
            float bv = sabs[idx]; int bi = idx;
            #pragma unroll
            for (int off = 16; off; off >>= 1) {
                float ov = __shfl_down_sync(0xffffffffu, bv, off);
                int   oi = __shfl_down_sync(0xffffffffu, bi, off);
                if (ov > bv || (ov == bv && oi < bi)) { bv = ov; bi = oi; }
            }
            if (tid == 0) { segv[s] = bv; segi[s] = bi; }
        }
        __syncthreads();
    }
}

__global__ void k_scatter(const int* __restrict__ tidx, const float* __restrict__ tval,
                          const float* __restrict__ g, float* __restrict__ concept)
{
    int i = blockIdx.x, d = threadIdx.x;
    float gv = g[(size_t)i * HD + d];
    #pragma unroll
    for (int k = 0; k < NK; k++) {
        int c = __ldg(&tidx[i * NK + k]);
        float v = __ldg(&tval[i * NK + k]);
        atomicAdd(&concept[(size_t)c * HD + d], v * gv);
    }
}

__global__ void k_diag_valid(const float* __restrict__ colsum, const float* __restrict__ sim,
                             const float* __restrict__ g, float* __restrict__ concept,
                             float* __restrict__ valid)
{
    int j = blockIdx.x, t = threadIdx.x;
    float cs = colsum[j];
    float v = concept[(size_t)j * HD + t];
    if (cs != 0.f) {
        float dg = sim[(size_t)j * NS + j];
        v += dg * g[(size_t)j * HD + t];
        concept[(size_t)j * HD + t] = v;
    }
    float s = v;
    #pragma unroll
    for (int off = 16; off; off >>= 1) s += __shfl_xor_sync(0xffffffffu, s, off);
    __shared__ float ws[4];
    if ((t & 31) == 0) ws[t >> 5] = s;
    __syncthreads();
    if (t == 0) {
        float tot = ws[0] + ws[1] + ws[2] + ws[3];
        valid[j] = (tot != 0.f) ? 1.f : 0.f;
    }
}

// column sums of E (E already holds exp(S))
__global__ void k_colz(const float* __restrict__ E, float* __restrict__ colZ) {
    int col = blockIdx.x * 128 + threadIdx.x;
    int r0 = blockIdx.y * 128;
    float s = 0.f;
    for (int r = r0; r < r0 + 128; r++) s += E[(size_t)r * NS + col];
    atomicAdd(&colZ[col], s);
}

__global__ void k_recip(float* __restrict__ colZ) {
    int i = blockIdx.x * blockDim.x + threadIdx.x;
    if (i < NS) colZ[i] = __fdividef(1.f, colZ[i]);
}

// attn = E * rcpZ  (E already exp'd; in place)
__global__ void k_scale(float* __restrict__ E, const float* __restrict__ colZ) {
    size_t q = (size_t)blockIdx.x * blockDim.x + threadIdx.x;
    size_t b = q * 4;
    float4 v = *(float4*)(E + b);
    int c = (int)(b & (NS - 1));
    float4 z = *(const float4*)(colZ + c);
    v.x *= z.x; v.y *= z.y; v.z *= z.z; v.w *= z.w;
    *(float4*)(E + b) = v;
}

__global__ void k_final(const float* __restrict__ fore, const float* __restrict__ indi,
                        const float* __restrict__ Wout, const float* __restrict__ bout,
                        float* __restrict__ out)
{
    int row = blockIdx.x * 8 + (threadIdx.x >> 5);
    int lane = threadIdx.x & 31;
    float4 a = ((const float4*)(fore + (size_t)row * HD))[lane];
    float4 b = ((const float4*)(indi + (size_t)row * HD))[lane];
    float4 w = ((const float4*)Wout)[lane];
    float s = (a.x+b.x)*w.x + (a.y+b.y)*w.y + (a.z+b.z)*w.z + (a.w+b.w)*w.w;
    #pragma unroll
    for (int off = 16; off; off >>= 1) s += __shfl_xor_sync(0xffffffffu, s, off);
    if (lane == 0) out[row] = s + bout[0];
}

// ---------------- driver -----------------------------------------------------
extern "C" void kernel_launch(void* const* d_in, const int* in_sizes, int n_in,
                              void* d_out, int out_size)
{
    const float* x     = (const float*)d_in[0];
    const float* Wih0  = (const float*)d_in[1];
    const float* Whh0  = (const float*)d_in[2];
    const float* bih0  = (const float*)d_in[3];
    const float* bhh0  = (const float*)d_in[4];
    const float* Wih1  = (const float*)d_in[5];
    const float* Whh1  = (const float*)d_in[6];
    const float* bih1  = (const float*)d_in[7];
    const float* bhh1  = (const float*)d_in[8];
    const float* W_hc  = (const float*)d_in[9];
    const float* b_hc  = (const float*)d_in[10];
    const float* W_hs  = (const float*)d_in[11];
    const float* b_hs  = (const float*)d_in[12];
    const float* W_fore= (const float*)d_in[13];
    const float* b_fore= (const float*)d_in[14];
    const float* W_back= (const float*)d_in[15];
    const float* b_back= (const float*)d_in[16];
    const float* W_indi= (const float*)d_in[17];
    const float* b_indi= (const float*)d_in[18];
    const float* W_out = (const float*)d_in[19];
    const float* b_out = (const float*)d_in[20];
    float* out = (float*)d_out;

    float *gi, *h0, *g, *gn, *sim, *colsum, *colZ, *valid, *concept;
    float *cf, *cfn, *hs, *t1, *t2, *t3, *t4, *tval;
    int* tidx;
    cudaGetSymbolAddress((void**)&gi,      d_gi);
    cudaGetSymbolAddress((void**)&h0,      d_h0);
    cudaGetSymbolAddress((void**)&g,       d_g);
    cudaGetSymbolAddress((void**)&gn,      d_gn);
    cudaGetSymbolAddress((void**)&sim,     d_sim);
    cudaGetSymbolAddress((void**)&tidx,    d_tidx);
    cudaGetSymbolAddress((void**)&tval,    d_tval);
    cudaGetSymbolAddress((void**)&colsum,  d_colsum);
    cudaGetSymbolAddress((void**)&colZ,    d_colZ);
    cudaGetSymbolAddress((void**)&valid,   d_valid);
    cudaGetSymbolAddress((void**)&concept, d_concept);
    cudaGetSymbolAddress((void**)&cf,      d_cf);
    cudaGetSymbolAddress((void**)&cfn,     d_cfn);
    cudaGetSymbolAddress((void**)&hs,      d_hsb);
    cudaGetSymbolAddress((void**)&t1,      d_t1);
    cudaGetSymbolAddress((void**)&t2,      d_t2);
    cudaGetSymbolAddress((void**)&t3,      d_t3);
    cudaGetSymbolAddress((void**)&t4,      d_t4);

    // h 28*128 + ghA/ghB 2*28*384 + gi 28*384 floats = 143360 B
    const int GRU_SMEM = (GRROWS * HD + 3 * GRROWS * GD) * 4;
    cudaFuncSetAttribute((const void*)k_gru<true>,
                         cudaFuncAttributeMaxDynamicSharedMemorySize, GRU_SMEM);
    cudaFuncSetAttribute((const void*)k_gru<false>,
                         cudaFuncAttributeMaxDynamicSharedMemorySize, GRU_SMEM);

    const int MT = NS * TS;         // 262144
    const int GRU_GRID = (NS + GRROWS - 1) / GRROWS;  // 147

    // Launch order: gru0 is our 4th launch so ncu (-s 5 -c 1, one harness
    // pre-launch) captures the GRU kernel.
    // #1 gi0 = x @ Wih0^T + bih0
    k_gemm<true, false, false><<<dim3(GD / 64, MT / 128, 1), 256>>>(
        x, Wih0, bih0, nullptr, gi, MT, GD, FI, FI);
    // #2, #3 tiny zeros (needed later)
    k_zero<<<(NS + 255) / 256, 256>>>(colsum, NS);
    k_zero<<<(NS + 255) / 256, 256>>>(colZ, NS);
    // #4 GRU layer 0 (writes full sequence)  <- ncu capture target
    k_gru<true><<<GRU_GRID, 384, GRU_SMEM>>>(gi, Whh0, bhh0, h0);
    // gi1 = h0 @ Wih1^T + bih1
    k_gemm<true, false, false><<<dim3(GD / 64, MT / 128, 1), 256>>>(
        h0, Wih1, bih1, nullptr, gi, MT, GD, HD, HD);
    // GRU layer 1 (writes final hidden only -> g)
    k_gru<false><<<GRU_GRID, 384, GRU_SMEM>>>(gi, Whh1, bhh1, g);

    // concept accumulator zero (before scatter)
    k_zero<<<(NS * HD + 255) / 256, 256>>>(concept, NS * HD);

    // normalized g, sim = gn @ gn^T
    k_rownorm<<<NS / 8, 256>>>(g, gn);
    k_gemm<true, false, false><<<dim3(NS / 64, NS / 128, 1), 256>>>(
        gn, gn, nullptr, nullptr, sim, NS, NS, HD, HD);

    // top-K selection + concept aggregation
    k_topk<<<NS, 256>>>(sim, tidx, tval, colsum);
    k_scatter<<<NS, 128>>>(tidx, tval, g, concept);
    k_diag_valid<<<NS, 128>>>(colsum, sim, g, concept, valid);

    // cf = lrelu(concept @ W_hc^T + b_hc) * valid
    k_gemm64<true, false><<<dim3(HD / 64, NS / 64), 256>>>(
        concept, W_hc, b_hc, valid, nullptr, cf, NS, HD, HD);
    k_rownorm<<<NS / 8, 256>>>(cf, cfn);

    // E = exp(gn @ cfn^T)  (exp fused into GEMM epilogue)
    k_gemm<true, false, true><<<dim3(NS / 64, NS / 128, 1), 256>>>(
        gn, cfn, nullptr, nullptr, sim, NS, NS, HD, HD);
    k_colz<<<dim3(NS / 128, NS / 128), 128>>>(sim, colZ);
    k_recip<<<NS / 256, 256>>>(colZ);
    k_scale<<<(int)(((size_t)NS * NS / 4) / 256), 256>>>(sim, colZ);

    // t1 = attn @ cf  (K=4096, split-K=8 into gi scratch, then reduce)
    k_gemm<false, false, false><<<dim3(HD / 64, NS / 128, 8), 256>>>(
        sim, cf, nullptr, nullptr, gi, NS, HD, NS, NS / 8);
    k_reduce<<<(NS * HD / 4 + 255) / 256, 256>>>(gi, t1, 8, NS * HD / 4);

    // hs = lrelu(t1 @ W_hs^T + b_hs)
    k_gemm64<true, false><<<dim3(HD / 64, NS / 64), 256>>>(
        t1, W_hs, b_hs, nullptr, nullptr, hs, NS, HD, HD);

    // t3 = g - lrelu(hs @ W_back^T + b_back)   (fused subtract)
    k_gemm64<true, true><<<dim3(HD / 64, NS / 64), 256>>>(
        hs, W_back, b_back, nullptr, g, t3, NS, HD, HD);
    // t2 = lrelu(hs @ W_fore^T + b_fore)
    k_gemm64<true, false><<<dim3(HD / 64, NS / 64), 256>>>(
        hs, W_fore, b_fore, nullptr, nullptr, t2, NS, HD, HD);
    // t4 = lrelu(t3 @ W_indi^T + b_indi)
    k_gemm64<true, false><<<dim3(HD / 64, NS / 64), 256>>>(
        t3, W_indi, b_indi, nullptr, nullptr, t4, NS, HD, HD);
    k_final<<<NS / 8, 256>>>(t2, t4, W_out, b_out, out);
}

// round 11
// speedup vs baseline: 1.2398x; 1.0051x over previous
#include <cuda_runtime.h>
#include <math.h>
#include <stdint.h>
#include <stddef.h>

// Problem dims (fixed by the dataset)
#define NS   4096      // batch
#define TS   64        // timesteps
#define FI   32        // input features
#define HD   128       // hidden
#define GD   384       // 3*H
#define NK   20        // top-k
#define SLOPE_F 0.2f
#define GRROWS 28      // batch rows per GRU CTA (147 CTAs -> all 148 SMs)

typedef unsigned long long ull;

// ---------------- f32x2 packed helpers (Blackwell FFMA2) --------------------
__device__ __forceinline__ ull pack2(float lo, float hi) {
    ull r;
    asm("mov.b64 %0, {%1, %2};" : "=l"(r) : "f"(lo), "f"(hi));
    return r;
}
__device__ __forceinline__ float2 unpack2(ull v) {
    float2 r;
    asm("mov.b64 {%0, %1}, %2;" : "=f"(r.x), "=f"(r.y) : "l"(v));
    return r;
}
__device__ __forceinline__ void ffma2(ull& d, ull a, ull b) {
    asm("fma.rn.f32x2 %0, %1, %2, %0;" : "+l"(d) : "l"(a), "l"(b));
}

// ---------------- cp.async helpers -----------------------------------------
__device__ __forceinline__ void cp16(float* dst_sh, const float* src_g) {
    uint32_t d = (uint32_t)__cvta_generic_to_shared(dst_sh);
    asm volatile("cp.async.ca.shared.global [%0], [%1], 16;" :: "r"(d), "l"(src_g));
}
__device__ __forceinline__ void cp_commit() {
    asm volatile("cp.async.commit_group;");
}
__device__ __forceinline__ void cp_wait_all() {
    asm volatile("cp.async.wait_all;");
}

// ---------------- scratch (device globals; no runtime allocation) ----------
__device__ float d_gi[(size_t)NS * TS * GD];
__device__ float d_h0[(size_t)NS * TS * HD];
__device__ float d_g  [NS * HD];
__device__ float d_gn [NS * HD];
__device__ float d_sim[(size_t)NS * NS];
__device__ int   d_tidx[NS * NK];
__device__ float d_tval[NS * NK];
__device__ float d_colsum[NS];
__device__ float d_colZ[NS];
__device__ float d_valid[NS];
__device__ float d_concept[NS * HD];
__device__ float d_cf [NS * HD];
__device__ float d_cfn[NS * HD];
__device__ float d_hsb[NS * HD];
__device__ float d_t1 [NS * HD];
__device__ float d_t2 [NS * HD];
__device__ float d_t3 [NS * HD];
__device__ float d_t4 [NS * HD];

// ---------------- fp32 GEMM: 128x64 tile, 256 thr, 8x4 micro, FFMA2 ---------
// Register double-buffering of global loads.
// EXPOUT: write __expf(result). COLSUM: accumulate column sums of the (post-
// epilogue) output into colZacc via SMEM partials + atomics (fused softmax Z).
template<bool TRANSB, bool ACT, bool EXPOUT, bool COLSUM>
__global__ __launch_bounds__(256) void k_gemm(
    const float* __restrict__ A, const float* __restrict__ B,
    const float* __restrict__ bias, const float* __restrict__ rs,
    float* __restrict__ colZacc,
    float* __restrict__ C, int M, int N, int K, int ksplit)
{
    __shared__ alignas(16) float As[16][132];
    __shared__ alignas(16) float Bs[16][68];
    __shared__ float colsh[64];
    const int bm = blockIdx.y * 128, bn = blockIdx.x * 64;
    const int tid = threadIdx.x;
    const int kbase = blockIdx.z * ksplit;
    const int kend = kbase + ksplit;

    const int a_m = tid >> 1, a_k = (tid & 1) * 8;
    const int ty = tid >> 4, tx = tid & 15;
    const int m0 = ty * 8, n0 = tx * 4;
    const int b_n = tid >> 2, b_k = (tid & 3) * 4;     // TRANSB loader
    const int nb_k = tid >> 4, nb_n4 = (tid & 15) * 4; // non-trans loader

    ull acc2[4][4];
    #pragma unroll
    for (int p = 0; p < 4; p++)
        #pragma unroll
        for (int j = 0; j < 4; j++) acc2[p][j] = 0ull;

    // prologue: load tile 0 into registers
    float4 ra0, ra1, rb;
    {
        const float* Ap = A + (size_t)(bm + a_m) * K + kbase + a_k;
        ra0 = *(const float4*)(Ap);
        ra1 = *(const float4*)(Ap + 4);
        if (TRANSB)
            rb = *(const float4*)(B + (size_t)(bn + b_n) * K + kbase + b_k);
        else
            rb = *(const float4*)(B + (size_t)(kbase + nb_k) * N + bn + nb_n4);
    }

    for (int k0 = kbase; k0 < kend; k0 += 16) {
        As[a_k + 0][a_m] = ra0.x; As[a_k + 1][a_m] = ra0.y;
        As[a_k + 2][a_m] = ra0.z; As[a_k + 3][a_m] = ra0.w;
        As[a_k + 4][a_m] = ra1.x; As[a_k + 5][a_m] = ra1.y;
        As[a_k + 6][a_m] = ra1.z; As[a_k + 7][a_m] = ra1.w;
        if (TRANSB) {
            Bs[b_k + 0][b_n] = rb.x; Bs[b_k + 1][b_n] = rb.y;
            Bs[b_k + 2][b_n] = rb.z; Bs[b_k + 3][b_n] = rb.w;
        } else {
            *(float4*)&Bs[nb_k][nb_n4] = rb;
        }
        __syncthreads();
        if (k0 + 16 < kend) {
            const float* Ap = A + (size_t)(bm + a_m) * K + (k0 + 16) + a_k;
            ra0 = *(const float4*)(Ap);
            ra1 = *(const float4*)(Ap + 4);
            if (TRANSB)
                rb = *(const float4*)(B + (size_t)(bn + b_n) * K + (k0 + 16) + b_k);
            else
                rb = *(const float4*)(B + (size_t)(k0 + 16 + nb_k) * N + bn + nb_n4);
        }
        #pragma unroll
        for (int kk = 0; kk < 16; kk++) {
            ulonglong2 aP01 = *(const ulonglong2*)&As[kk][m0];
            ulonglong2 aP23 = *(const ulonglong2*)&As[kk][m0 + 4];
            float4 b = *(const float4*)&Bs[kk][n0];
            ull bd0 = pack2(b.x, b.x), bd1 = pack2(b.y, b.y);
            ull bd2 = pack2(b.z, b.z), bd3 = pack2(b.w, b.w);
            ffma2(acc2[0][0], aP01.x, bd0); ffma2(acc2[0][1], aP01.x, bd1);
            ffma2(acc2[0][2], aP01.x, bd2); ffma2(acc2[0][3], aP01.x, bd3);
            ffma2(acc2[1][0], aP01.y, bd0); ffma2(acc2[1][1], aP01.y, bd1);
            ffma2(acc2[1][2], aP01.y, bd2); ffma2(acc2[1][3], aP01.y, bd3);
            ffma2(acc2[2][0], aP23.x, bd0); ffma2(acc2[2][1], aP23.x, bd1);
            ffma2(acc2[2][2], aP23.x, bd2); ffma2(acc2[2][3], aP23.x, bd3);
            ffma2(acc2[3][0], aP23.y, bd0); ffma2(acc2[3][1], aP23.y, bd1);
            ffma2(acc2[3][2], aP23.y, bd2); ffma2(acc2[3][3], aP23.y, bd3);
        }
        __syncthreads();
    }

    if (COLSUM) {
        if (tid < 64) colsh[tid] = 0.f;
        __syncthreads();
    }

    float cp[4] = {0.f, 0.f, 0.f, 0.f};
    float* Cw = C + (size_t)blockIdx.z * ((size_t)M * N);
    #pragma unroll
    for (int p = 0; p < 4; p++) {
        int rowA = bm + m0 + 2 * p;
        int rowB = rowA + 1;
        float rsA = rs ? rs[rowA] : 1.f;
        float rsB = rs ? rs[rowB] : 1.f;
        float va[4], vb[4];
        #pragma unroll
        for (int j = 0; j < 4; j++) {
            float2 v = unpack2(acc2[p][j]);
            float a = v.x, b = v.y;
            if (bias) { float bj = bias[bn + n0 + j]; a += bj; b += bj; }
            if (ACT) {
                a = a > 0.f ? a : SLOPE_F * a;
                b = b > 0.f ? b : SLOPE_F * b;
            }
            if (EXPOUT) { a = __expf(a); b = __expf(b); }
            va[j] = a * rsA; vb[j] = b * rsB;
            if (COLSUM) cp[j] += va[j] + vb[j];
        }
        *(float4*)(Cw + (size_t)rowA * N + bn + n0) =
            make_float4(va[0], va[1], va[2], va[3]);
        *(float4*)(Cw + (size_t)rowB * N + bn + n0) =
            make_float4(vb[0], vb[1], vb[2], vb[3]);
    }

    if (COLSUM) {
        #pragma unroll
        for (int j = 0; j < 4; j++)
            atomicAdd(&colsh[n0 + j], cp[j]);
        __syncthreads();
        if (tid < 64) atomicAdd(&colZacc[bn + tid], colsh[tid]);
    }
}

// ---------------- fp32 GEMM: 64x64 tile (NS x 128 x 128 head GEMMs) ---------
template<bool ACT, bool SUBPRE>
__global__ __launch_bounds__(256) void k_gemm64(
    const float* __restrict__ A, const float* __restrict__ B,
    const float* __restrict__ bias, const float* __restrict__ rs,
    const float* __restrict__ pre, float* __restrict__ C,
    int M, int N, int K)
{
    __shared__ alignas(16) float As[16][68];
    __shared__ alignas(16) float Bs[16][68];
    const int bm = blockIdx.y * 64, bn = blockIdx.x * 64;
    const int tid = threadIdx.x;
    const int a_m = tid >> 2, a_k = (tid & 3) * 4;
    const int ty = tid >> 4, tx = tid & 15;
    const int m0 = ty * 4, n0 = tx * 4;

    ull acc2[2][4];
    #pragma unroll
    for (int p = 0; p < 2; p++)
        #pragma unroll
        for (int j = 0; j < 4; j++) acc2[p][j] = 0ull;

    float4 ra, rb;
    ra = *(const float4*)(A + (size_t)(bm + a_m) * K + a_k);
    rb = *(const float4*)(B + (size_t)(bn + a_m) * K + a_k);

    for (int k0 = 0; k0 < K; k0 += 16) {
        As[a_k + 0][a_m] = ra.x; As[a_k + 1][a_m] = ra.y;
        As[a_k + 2][a_m] = ra.z; As[a_k + 3][a_m] = ra.w;
        Bs[a_k + 0][a_m] = rb.x; Bs[a_k + 1][a_m] = rb.y;
        Bs[a_k + 2][a_m] = rb.z; Bs[a_k + 3][a_m] = rb.w;
        __syncthreads();
        if (k0 + 16 < K) {
            ra = *(const float4*)(A + (size_t)(bm + a_m) * K + k0 + 16 + a_k);
            rb = *(const float4*)(B + (size_t)(bn + a_m) * K + k0 + 16 + a_k);
        }
        #pragma unroll
        for (int kk = 0; kk < 16; kk++) {
            ulonglong2 aP = *(const ulonglong2*)&As[kk][m0];
            float4 b = *(const float4*)&Bs[kk][n0];
            ull bd0 = pack2(b.x, b.x), bd1 = pack2(b.y, b.y);
            ull bd2 = pack2(b.z, b.z), bd3 = pack2(b.w, b.w);
            ffma2(acc2[0][0], aP.x, bd0); ffma2(acc2[0][1], aP.x, bd1);
            ffma2(acc2[0][2], aP.x, bd2); ffma2(acc2[0][3], aP.x, bd3);
            ffma2(acc2[1][0], aP.y, bd0); ffma2(acc2[1][1], aP.y, bd1);
            ffma2(acc2[1][2], aP.y, bd2); ffma2(acc2[1][3], aP.y, bd3);
        }
        __syncthreads();
    }

    #pragma unroll
    for (int p = 0; p < 2; p++) {
        int rowA = bm + m0 + 2 * p;
        int rowB = rowA + 1;
        float rsA = rs ? rs[rowA] : 1.f;
        float rsB = rs ? rs[rowB] : 1.f;
        float va[4], vb[4];
        #pragma unroll
        for (int j = 0; j < 4; j++) {
            float2 v = unpack2(acc2[p][j]);
            float a = v.x, b = v.y;
            if (bias) { float bj = bias[bn + n0 + j]; a += bj; b += bj; }
            if (ACT) {
                a = a > 0.f ? a : SLOPE_F * a;
                b = b > 0.f ? b : SLOPE_F * b;
            }
            a *= rsA; b *= rsB;
            if (SUBPRE) {
                a = pre[(size_t)rowA * N + bn + n0 + j] - a;
                b = pre[(size_t)rowB * N + bn + n0 + j] - b;
            }
            va[j] = a; vb[j] = b;
        }
        *(float4*)(C + (size_t)rowA * N + bn + n0) =
            make_float4(va[0], va[1], va[2], va[3]);
        *(float4*)(C + (size_t)rowB * N + bn + n0) =
            make_float4(vb[0], vb[1], vb[2], vb[3]);
    }
}

// reduce over split-K partial slices: C = sum_z P[z]
__global__ void k_reduce(const float* __restrict__ P, float* __restrict__ C,
                         int nslice, int total4)
{
    int i = blockIdx.x * blockDim.x + threadIdx.x;
    if (i >= total4) return;
    size_t b = (size_t)i * 4;
    float4 s = make_float4(0.f, 0.f, 0.f, 0.f);
    for (int z = 0; z < nslice; z++) {
        float4 v = *(const float4*)(P + (size_t)z * total4 * 4 + b);
        s.x += v.x; s.y += v.y; s.z += v.z; s.w += v.w;
    }
    *(float4*)(C + b) = s;
}

// ---------------- persistent GRU recurrent kernel ---------------------------
// 384 threads, mapping (2 outputs, half-k): o = tid%192, half = tid/192.
// Thread owns Whh rows o and o+192 restricted to its 64-element k-half.
// Matvec processes TWO rows per iteration (4 independent chains).
template<bool WRITE_SEQ>
__global__ __launch_bounds__(384, 1) void k_gru(
    const float* __restrict__ gi, const float* __restrict__ Whh,
    const float* __restrict__ bhh, float* __restrict__ hout)
{
    extern __shared__ float sm[];
    float* h_sh = sm;                          // GRROWS*128
    float* ghA  = sm + GRROWS * HD;            // GRROWS*384
    float* ghB  = ghA + GRROWS * GD;           // GRROWS*384
    float* gi_sh = ghB + GRROWS * GD;          // GRROWS*384
    const int tid = threadIdx.x;
    const int o = tid % 192;
    const int half = tid / 192;                 // 0 or 1
    const int o2 = o + 192;
    const int base = blockIdx.x * GRROWS;
    const int rows = (NS - base < GRROWS) ? (NS - base) : GRROWS;
    float* ghOut = half ? ghB : ghA;

    ull wq[64];
    {
        const ulonglong2* wg0 =
            (const ulonglong2*)(Whh + (size_t)o * HD + half * 64);
        const ulonglong2* wg1 =
            (const ulonglong2*)(Whh + (size_t)o2 * HD + half * 64);
        #pragma unroll
        for (int q = 0; q < 16; q++) {
            ulonglong2 t0 = wg0[q];
            wq[2 * q] = t0.x; wq[2 * q + 1] = t0.y;
        }
        #pragma unroll
        for (int q = 0; q < 16; q++) {
            ulonglong2 t1 = wg1[q];
            wq[32 + 2 * q] = t1.x; wq[32 + 2 * q + 1] = t1.y;
        }
    }
    const float bo0 = half ? 0.f : bhh[o];
    const float bo1 = half ? 0.f : bhh[o2];
    for (int idx = tid; idx < rows * HD; idx += 384) h_sh[idx] = 0.f;

    // gi prefetch: 28*96 float4 slots; thread does 8 strided slots
    const int pr = tid / 12, pc = tid % 12;
    const bool pact = (pr < rows);
    {
        const float* src = gi + ((size_t)(base + pr) * TS + 0) * GD;
        if (pact) {
            #pragma unroll
            for (int i = 0; i < 8; i++) {
                int f = pc + 12 * i;
                cp16(gi_sh + pr * GD + f * 4, src + f * 4);
            }
        }
        cp_commit();
    }
    __syncthreads();

    for (int t = 0; t < TS; t++) {
        #pragma unroll 1
        for (int r = 0; r < rows; r += 2) {
            const ulonglong2* hp0 =
                (const ulonglong2*)(h_sh + r * HD + half * 64);
            const ulonglong2* hp1 =
                (const ulonglong2*)(h_sh + (r + 1) * HD + half * 64);
            ull a0 = 0ull, b0 = 0ull, a1 = 0ull, b1 = 0ull;
            #pragma unroll
            for (int q = 0; q < 16; q++) {
                ulonglong2 x0 = hp0[q];
                ulonglong2 x1 = hp1[q];
                ffma2(a0, x0.x, wq[2 * q]);
                ffma2(b0, x0.x, wq[32 + 2 * q]);
                ffma2(a1, x1.x, wq[2 * q]);
                ffma2(b1, x1.x, wq[32 + 2 * q]);
                ffma2(a0, x0.y, wq[2 * q + 1]);
                ffma2(b0, x0.y, wq[32 + 2 * q + 1]);
                ffma2(a1, x1.y, wq[2 * q + 1]);
                ffma2(b1, x1.y, wq[32 + 2 * q + 1]);
            }
            float2 pa0 = unpack2(a0), pb0 = unpack2(b0);
            float2 pa1 = unpack2(a1), pb1 = unpack2(b1);
            ghOut[r * GD + o]        = (pa0.x + pa0.y) + bo0;
            ghOut[r * GD + o2]       = (pb0.x + pb0.y) + bo1;
            ghOut[(r + 1) * GD + o]  = (pa1.x + pa1.y) + bo0;
            ghOut[(r + 1) * GD + o2] = (pb1.x + pb1.y) + bo1;
        }
        cp_wait_all();
        __syncthreads();
        #pragma unroll 1
        for (int idx = tid; idx < rows * HD; idx += 384) {
            int r = idx >> 7, j = idx & 127;
            float gir = gi_sh[r * GD + j];
            float giz = gi_sh[r * GD + j + 128];
            float gin = gi_sh[r * GD + j + 256];
            float ghr = ghA[r * GD + j]       + ghB[r * GD + j];
            float ghz = ghA[r * GD + j + 128] + ghB[r * GD + j + 128];
            float ghn = ghA[r * GD + j + 256] + ghB[r * GD + j + 256];
            float rg = __fdividef(1.f, 1.f + __expf(-(gir + ghr)));
            float zg = __fdividef(1.f, 1.f + __expf(-(giz + ghz)));
            float a2 = gin + rg * ghn;
            float ng = 1.f - __fdividef(2.f, __expf(2.f * a2) + 1.f);
            float hprev = h_sh[idx];
            float hn = (1.f - zg) * ng + zg * hprev;
            h_sh[idx] = hn;
            if (WRITE_SEQ)
                hout[((size_t)(base + r) * TS + t) * HD + j] = hn;
            else if (t == TS - 1)
                hout[(size_t)(base + r) * HD + j] = hn;
        }
        __syncthreads();
        if (t + 1 < TS) {
            const float* src = gi + ((size_t)(base + pr) * TS + (t + 1)) * GD;
            if (pact) {
                #pragma unroll
                for (int i = 0; i < 8; i++) {
                    int f = pc + 12 * i;
                    cp16(gi_sh + pr * GD + f * 4, src + f * 4);
                }
            }
            cp_commit();
        }
    }
}

// ---------------- small helpers --------------------------------------------
__global__ void k_zero(float* p, int n) {
    int i = blockIdx.x * blockDim.x + threadIdx.x;
    if (i < n) p[i] = 0.f;
}

__global__ void k_rownorm(const float* __restrict__ src, float* __restrict__ dst) {
    int row = blockIdx.x * 8 + (threadIdx.x >> 5);
    int lane = threadIdx.x & 31;
    const float4* s4 = (const float4*)(src + (size_t)row * HD);
    float4 v = s4[lane];
    float ss = v.x*v.x + v.y*v.y + v.z*v.z + v.w*v.w;
    #pragma unroll
    for (int off = 16; off; off >>= 1) ss += __shfl_xor_sync(0xffffffffu, ss, off);
    float n = sqrtf(ss);
    float inv = (n > 0.f) ? 1.f / n : 0.f;
    ((float4*)(dst + (size_t)row * HD))[lane] =
        make_float4(v.x*inv, v.y*inv, v.z*inv, v.w*inv);
}

// cf2[row,:] = cf[row,:] / colZ[row]  (softmax normalization folded into cf)
__global__ void k_cfscale(const float* __restrict__ cf,
                          const float* __restrict__ colZ,
                          float* __restrict__ out)
{
    int row = blockIdx.x * 8 + (threadIdx.x >> 5);
    int lane = threadIdx.x & 31;
    float rz = __fdividef(1.f, colZ[row]);
    float4 v = ((const float4*)(cf + (size_t)row * HD))[lane];
    ((float4*)(out + (size_t)row * HD))[lane] =
        make_float4(v.x * rz, v.y * rz, v.z * rz, v.w * rz);
}

// top-K=20 per row of |sim| (diag excluded), jax-stable ties (lowest index).
// Segment-max scheme, 2 syncthreads per round.
__global__ __launch_bounds__(256) void k_topk(
    const float* __restrict__ sim, int* __restrict__ tidx,
    float* __restrict__ tval, float* __restrict__ colsum)
{
    int i = blockIdx.x;
    __shared__ float sabs[NS];
    __shared__ float segv[128];
    __shared__ int   segi[128];
    __shared__ float bcv[4];
    __shared__ int   bci[4];
    const int tid = threadIdx.x;
    const float* row = sim + (size_t)i * NS;

    for (int c4 = tid; c4 < NS / 4; c4 += 256) {
        float4 v = *(const float4*)(row + c4 * 4);
        float4 a = make_float4(fabsf(v.x), fabsf(v.y), fabsf(v.z), fabsf(v.w));
        *(float4*)&sabs[c4 * 4] = a;
    }
    __syncthreads();
    if (tid == 0) sabs[i] = -1.f;
    __syncthreads();

    if (tid < 128) {
        float bv = -2.f; int bi = tid * 32;
        #pragma unroll 4
        for (int j = 0; j < 32; j++) {
            float v = sabs[tid * 32 + j];
            if (v > bv) { bv = v; bi = tid * 32 + j; }
        }
        segv[tid] = bv; segi[tid] = bi;
    }
    __syncthreads();

    for (int k = 0; k < NK; k++) {
        if (tid < 128) {
            float bv = segv[tid]; int bi = segi[tid];
            #pragma unroll
            for (int off = 16; off; off >>= 1) {
                float ov = __shfl_down_sync(0xffffffffu, bv, off);
                int   oi = __shfl_down_sync(0xffffffffu, bi, off);
                if (ov > bv || (ov == bv && oi < bi)) { bv = ov; bi = oi; }
            }
            if ((tid & 31) == 0) { bcv[tid >> 5] = bv; bci[tid >> 5] = bi; }
        }
        __syncthreads();
        if (tid < 32) {
            int bi = 0;
            if (tid == 0) {
                float bv = bcv[0]; bi = bci[0];
                #pragma unroll
                for (int w = 1; w < 4; w++)
                    if (bcv[w] > bv || (bcv[w] == bv && bci[w] < bi)) {
                        bv = bcv[w]; bi = bci[w];
                    }
                tidx[i * NK + k] = bi;
                float sv = row[bi];
                tval[i * NK + k] = sv;
                atomicAdd(&colsum[bi], sv);
                sabs[bi] = -2.f;
            }
            bi = __shfl_sync(0xffffffffu, bi, 0);
            __syncwarp();
            int s = bi >> 5;
            int idx = s * 32 + tid;
            float bv2 = sabs[idx]; int bi2 = idx;
            #pragma unroll
            for (int off = 16; off; off >>= 1) {
                float ov = __shfl_down_sync(0xffffffffu, bv2, off);
                int   oi = __shfl_down_sync(0xffffffffu, bi2, off);
                if (ov > bv2 || (ov == bv2 && oi < bi2)) { bv2 = ov; bi2 = oi; }
            }
            if (tid == 0) { segv[s] = bv2; segi[s] = bi2; }
        }
        __syncthreads();
    }
}

__global__ void k_scatter(const int* __restrict__ tidx, const float* __restrict__ tval,
                          const float* __restrict__ g, float* __restrict__ concept)
{
    int i = blockIdx.x, d = threadIdx.x;
    float gv = g[(size_t)i * HD + d];
    #pragma unroll
    for (int k = 0; k < NK; k++) {
        int c = __ldg(&tidx[i * NK + k]);
        float v = __ldg(&tval[i * NK + k]);
        atomicAdd(&concept[(size_t)c * HD + d], v * gv);
    }
}

__global__ void k_diag_valid(const float* __restrict__ colsum, const float* __restrict__ sim,
                             const float* __restrict__ g, float* __restrict__ concept,
                             float* __restrict__ valid)
{
    int j = blockIdx.x, t = threadIdx.x;
    float cs = colsum[j];
    float v = concept[(size_t)j * HD + t];
    if (cs != 0.f) {
        float dg = sim[(size_t)j * NS + j];
        v += dg * g[(size_t)j * HD + t];
        concept[(size_t)j * HD + t] = v;
    }
    float s = v;
    #pragma unroll
    for (int off = 16; off; off >>= 1) s += __shfl_xor_sync(0xffffffffu, s, off);
    __shared__ float ws[4];
    if ((t & 31) == 0) ws[t >> 5] = s;
    __syncthreads();
    if (t == 0) {
        float tot = ws[0] + ws[1] + ws[2] + ws[3];
        valid[j] = (tot != 0.f) ? 1.f : 0.f;
    }
}

__global__ void k_final(const float* __restrict__ fore, const float* __restrict__ indi,
                        const float* __restrict__ Wout, const float* __restrict__ bout,
                        float* __restrict__ out)
{
    int row = blockIdx.x * 8 + (threadIdx.x >> 5);
    int lane = threadIdx.x & 31;
    float4 a = ((const float4*)(fore + (size_t)row * HD))[lane];
    float4 b = ((const float4*)(indi + (size_t)row * HD))[lane];
    float4 w = ((const float4*)Wout)[lane];
    float s = (a.x+b.x)*w.x + (a.y+b.y)*w.y + (a.z+b.z)*w.z + (a.w+b.w)*w.w;
    #pragma unroll
    for (int off = 16; off; off >>= 1) s += __shfl_xor_sync(0xffffffffu, s, off);
    if (lane == 0) out[row] = s + bout[0];
}

// ---------------- driver -----------------------------------------------------
extern "C" void kernel_launch(void* const* d_in, const int* in_sizes, int n_in,
                              void* d_out, int out_size)
{
    const float* x     = (const float*)d_in[0];
    const float* Wih0  = (const float*)d_in[1];
    const float* Whh0  = (const float*)d_in[2];
    const float* bih0  = (const float*)d_in[3];
    const float* bhh0  = (const float*)d_in[4];
    const float* Wih1  = (const float*)d_in[5];
    const float* Whh1  = (const float*)d_in[6];
    const float* bih1  = (const float*)d_in[7];
    const float* bhh1  = (const float*)d_in[8];
    const float* W_hc  = (const float*)d_in[9];
    const float* b_hc  = (const float*)d_in[10];
    const float* W_hs  = (const float*)d_in[11];
    const float* b_hs  = (const float*)d_in[12];
    const float* W_fore= (const float*)d_in[13];
    const float* b_fore= (const float*)d_in[14];
    const float* W_back= (const float*)d_in[15];
    const float* b_back= (const float*)d_in[16];
    const float* W_indi= (const float*)d_in[17];
    const float* b_indi= (const float*)d_in[18];
    const float* W_out = (const float*)d_in[19];
    const float* b_out = (const float*)d_in[20];
    float* out = (float*)d_out;

    float *gi, *h0, *g, *gn, *sim, *colsum, *colZ, *valid, *concept;
    float *cf, *cfn, *hs, *t1, *t2, *t3, *t4, *tval;
    int* tidx;
    cudaGetSymbolAddress((void**)&gi,      d_gi);
    cudaGetSymbolAddress((void**)&h0,      d_h0);
    cudaGetSymbolAddress((void**)&g,       d_g);
    cudaGetSymbolAddress((void**)&gn,      d_gn);
    cudaGetSymbolAddress((void**)&sim,     d_sim);
    cudaGetSymbolAddress((void**)&tidx,    d_tidx);
    cudaGetSymbolAddress((void**)&tval,    d_tval);
    cudaGetSymbolAddress((void**)&colsum,  d_colsum);
    cudaGetSymbolAddress((void**)&colZ,    d_colZ);
    cudaGetSymbolAddress((void**)&valid,   d_valid);
    cudaGetSymbolAddress((void**)&concept, d_concept);
    cudaGetSymbolAddress((void**)&cf,      d_cf);
    cudaGetSymbolAddress((void**)&cfn,     d_cfn);
    cudaGetSymbolAddress((void**)&hs,      d_hsb);
    cudaGetSymbolAddress((void**)&t1,      d_t1);
    cudaGetSymbolAddress((void**)&t2,      d_t2);
    cudaGetSymbolAddress((void**)&t3,      d_t3);
    cudaGetSymbolAddress((void**)&t4,      d_t4);

    // h 28*128 + ghA/ghB 2*28*384 + gi 28*384 floats = 143360 B
    const int GRU_SMEM = (GRROWS * HD + 3 * GRROWS * GD) * 4;
    cudaFuncSetAttribute((const void*)k_gru<true>,
                         cudaFuncAttributeMaxDynamicSharedMemorySize, GRU_SMEM);
    cudaFuncSetAttribute((const void*)k_gru<false>,
                         cudaFuncAttributeMaxDynamicSharedMemorySize, GRU_SMEM);

    const int MT = NS * TS;         // 262144
    const int GRU_GRID = (NS + GRROWS - 1) / GRROWS;  // 147

    // Launch order: gru0 is our 4th launch so ncu (-s 5 -c 1, one harness
    // pre-launch) captures the GRU kernel.
    // #1 gi0 = x @ Wih0^T + bih0
    k_gemm<true, false, false, false><<<dim3(GD / 64, MT / 128, 1), 256>>>(
        x, Wih0, bih0, nullptr, nullptr, gi, MT, GD, FI, FI);
    // #2, #3 tiny zeros (needed later)
    k_zero<<<(NS + 255) / 256, 256>>>(colsum, NS);
    k_zero<<<(NS + 255) / 256, 256>>>(colZ, NS);
    // #4 GRU layer 0 (writes full sequence)  <- ncu capture target
    k_gru<true><<<GRU_GRID, 384, GRU_SMEM>>>(gi, Whh0, bhh0, h0);
    // gi1 = h0 @ Wih1^T + bih1
    k_gemm<true, false, false, false><<<dim3(GD / 64, MT / 128, 1), 256>>>(
        h0, Wih1, bih1, nullptr, nullptr, gi, MT, GD, HD, HD);
    // GRU layer 1 (writes final hidden only -> g)
    k_gru<false><<<GRU_GRID, 384, GRU_SMEM>>>(gi, Whh1, bhh1, g);

    // concept accumulator zero (before scatter)
    k_zero<<<(NS * HD + 255) / 256, 256>>>(concept, NS * HD);

    // normalized g, sim = gn @ gn^T
    k_rownorm<<<NS / 8, 256>>>(g, gn);
    k_gemm<true, false, false, false><<<dim3(NS / 64, NS / 128, 1), 256>>>(
        gn, gn, nullptr, nullptr, nullptr, sim, NS, NS, HD, HD);

    // top-K selection + concept aggregation
    k_topk<<<NS, 256>>>(sim, tidx, tval, colsum);
    k_scatter<<<NS, 128>>>(tidx, tval, g, concept);
    k_diag_valid<<<NS, 128>>>(colsum, sim, g, concept, valid);

    // cf = lrelu(concept @ W_hc^T + b_hc) * valid
    k_gemm64<true, false><<<dim3(HD / 64, NS / 64), 256>>>(
        concept, W_hc, b_hc, valid, nullptr, cf, NS, HD, HD);
    k_rownorm<<<NS / 8, 256>>>(cf, cfn);

    // E = exp(gn @ cfn^T) with column sums fused into the epilogue
    k_gemm<true, false, true, true><<<dim3(NS / 64, NS / 128, 1), 256>>>(
        gn, cfn, nullptr, nullptr, colZ, sim, NS, NS, HD, HD);

    // cf2 = cf / colZ (row-wise); then t1 = E @ cf2 == softmax(S,axis0) @ cf
    k_cfscale<<<NS / 8, 256>>>(cf, colZ, t2);
    k_gemm<false, false, false, false><<<dim3(HD / 64, NS / 128, 8), 256>>>(
        sim, t2, nullptr, nullptr, nullptr, gi, NS, HD, NS, NS / 8);
    k_reduce<<<(NS * HD / 4 + 255) / 256, 256>>>(gi, t1, 8, NS * HD / 4);

    // hs = lrelu(t1 @ W_hs^T + b_hs)
    k_gemm64<true, false><<<dim3(HD / 64, NS / 64), 256>>>(
        t1, W_hs, b_hs, nullptr, nullptr, hs, NS, HD, HD);

    // t3 = g - lrelu(hs @ W_back^T + b_back)   (fused subtract)
    k_gemm64<true, true><<<dim3(HD / 64, NS / 64), 256>>>(
        hs, W_back, b_back, nullptr, g, t3, NS, HD, HD);
    // t2 = lrelu(hs @ W_fore^T + b_fore)
    k_gemm64<true, false><<<dim3(HD / 64, NS / 64), 256>>>(
        hs, W_fore, b_fore, nullptr, nullptr, t2, NS, HD, HD);
    // t4 = lrelu(t3 @ W_indi^T + b_indi)
    k_gemm64<true, false><<<dim3(HD / 64, NS / 64), 256>>>(
        t3, W_indi, b_indi, nullptr, nullptr, t4, NS, HD, HD);
    k_final<<<NS / 8, 256>>>(t2, t4, W_out, b_out, out);
}

// round 12
// speedup vs baseline: 1.3110x; 1.0574x over previous
#include <cuda_runtime.h>
#include <cuda_bf16.h>
#include <mma.h>
#include <math.h>
#include <stdint.h>
#include <stddef.h>

using namespace nvcuda;

// Problem dims (fixed by the dataset)
#define NS   4096      // batch
#define TS   64        // timesteps
#define FI   32        // input features
#define HD   128       // hidden
#define GD   384       // 3*H
#define NK   20        // top-k
#define SLOPE_F 0.2f
#define GRROWS 28      // batch rows per GRU CTA (147 CTAs -> all 148 SMs)

typedef unsigned long long ull;

// ---------------- f32x2 packed helpers (Blackwell FFMA2) --------------------
__device__ __forceinline__ ull pack2(float lo, float hi) {
    ull r;
    asm("mov.b64 %0, {%1, %2};" : "=l"(r) : "f"(lo), "f"(hi));
    return r;
}
__device__ __forceinline__ float2 unpack2(ull v) {
    float2 r;
    asm("mov.b64 {%0, %1}, %2;" : "=f"(r.x), "=f"(r.y) : "l"(v));
    return r;
}
__device__ __forceinline__ void ffma2(ull& d, ull a, ull b) {
    asm("fma.rn.f32x2 %0, %1, %2, %0;" : "+l"(d) : "l"(a), "l"(b));
}

// ---------------- cp.async helpers -----------------------------------------
__device__ __forceinline__ void cp16(float* dst_sh, const float* src_g) {
    uint32_t d = (uint32_t)__cvta_generic_to_shared(dst_sh);
    asm volatile("cp.async.ca.shared.global [%0], [%1], 16;" :: "r"(d), "l"(src_g));
}
__device__ __forceinline__ void cp_commit() {
    asm volatile("cp.async.commit_group;");
}
__device__ __forceinline__ void cp_wait_all() {
    asm volatile("cp.async.wait_all;");
}

// ---------------- scratch (device globals; no runtime allocation) ----------
__device__ float d_gi[(size_t)NS * TS * GD];
__device__ float d_h0[(size_t)NS * TS * HD];
__device__ float d_g  [NS * HD];
__device__ float d_gn [NS * HD];
__device__ float d_sim[(size_t)NS * NS];
__device__ int   d_tidx[NS * NK];
__device__ float d_tval[NS * NK];
__device__ float d_colsum[NS];
__device__ float d_colZ[NS];
__device__ float d_valid[NS];
__device__ float d_concept[NS * HD];
__device__ float d_cf [NS * HD];
__device__ float d_cfn[NS * HD];
__device__ float d_hsb[NS * HD];
__device__ float d_t1 [NS * HD];
__device__ float d_t2 [NS * HD];
__device__ float d_t3 [NS * HD];
__device__ float d_t4 [NS * HD];
__device__ __nv_bfloat16 d_Whi[GD * HD];   // Wih1 split high
__device__ __nv_bfloat16 d_Wlo[GD * HD];   // Wih1 split low

// ---------------- fp32 GEMM: 128x64 tile, 256 thr, 8x4 micro, FFMA2 ---------
template<bool TRANSB, bool ACT, bool EXPOUT, bool COLSUM>
__global__ __launch_bounds__(256) void k_gemm(
    const float* __restrict__ A, const float* __restrict__ B,
    const float* __restrict__ bias, const float* __restrict__ rs,
    float* __restrict__ colZacc,
    float* __restrict__ C, int M, int N, int K, int ksplit)
{
    __shared__ alignas(16) float As[16][132];
    __shared__ alignas(16) float Bs[16][68];
    __shared__ float colsh[64];
    const int bm = blockIdx.y * 128, bn = blockIdx.x * 64;
    const int tid = threadIdx.x;
    const int kbase = blockIdx.z * ksplit;
    const int kend = kbase + ksplit;

    const int a_m = tid >> 1, a_k = (tid & 1) * 8;
    const int ty = tid >> 4, tx = tid & 15;
    const int m0 = ty * 8, n0 = tx * 4;
    const int b_n = tid >> 2, b_k = (tid & 3) * 4;
    const int nb_k = tid >> 4, nb_n4 = (tid & 15) * 4;

    ull acc2[4][4];
    #pragma unroll
    for (int p = 0; p < 4; p++)
        #pragma unroll
        for (int j = 0; j < 4; j++) acc2[p][j] = 0ull;

    float4 ra0, ra1, rb;
    {
        const float* Ap = A + (size_t)(bm + a_m) * K + kbase + a_k;
        ra0 = *(const float4*)(Ap);
        ra1 = *(const float4*)(Ap + 4);
        if (TRANSB)
            rb = *(const float4*)(B + (size_t)(bn + b_n) * K + kbase + b_k);
        else
            rb = *(const float4*)(B + (size_t)(kbase + nb_k) * N + bn + nb_n4);
    }

    for (int k0 = kbase; k0 < kend; k0 += 16) {
        As[a_k + 0][a_m] = ra0.x; As[a_k + 1][a_m] = ra0.y;
        As[a_k + 2][a_m] = ra0.z; As[a_k + 3][a_m] = ra0.w;
        As[a_k + 4][a_m] = ra1.x; As[a_k + 5][a_m] = ra1.y;
        As[a_k + 6][a_m] = ra1.z; As[a_k + 7][a_m] = ra1.w;
        if (TRANSB) {
            Bs[b_k + 0][b_n] = rb.x; Bs[b_k + 1][b_n] = rb.y;
            Bs[b_k + 2][b_n] = rb.z; Bs[b_k + 3][b_n] = rb.w;
        } else {
            *(float4*)&Bs[nb_k][nb_n4] = rb;
        }
        __syncthreads();
        if (k0 + 16 < kend) {
            const float* Ap = A + (size_t)(bm + a_m) * K + (k0 + 16) + a_k;
            ra0 = *(const float4*)(Ap);
            ra1 = *(const float4*)(Ap + 4);
            if (TRANSB)
                rb = *(const float4*)(B + (size_t)(bn + b_n) * K + (k0 + 16) + b_k);
            else
                rb = *(const float4*)(B + (size_t)(k0 + 16 + nb_k) * N + bn + nb_n4);
        }
        #pragma unroll
        for (int kk = 0; kk < 16; kk++) {
            ulonglong2 aP01 = *(const ulonglong2*)&As[kk][m0];
            ulonglong2 aP23 = *(const ulonglong2*)&As[kk][m0 + 4];
            float4 b = *(const float4*)&Bs[kk][n0];
            ull bd0 = pack2(b.x, b.x), bd1 = pack2(b.y, b.y);
            ull bd2 = pack2(b.z, b.z), bd3 = pack2(b.w, b.w);
            ffma2(acc2[0][0], aP01.x, bd0); ffma2(acc2[0][1], aP01.x, bd1);
            ffma2(acc2[0][2], aP01.x, bd2); ffma2(acc2[0][3], aP01.x, bd3);
            ffma2(acc2[1][0], aP01.y, bd0); ffma2(acc2[1][1], aP01.y, bd1);
            ffma2(acc2[1][2], aP01.y, bd2); ffma2(acc2[1][3], aP01.y, bd3);
            ffma2(acc2[2][0], aP23.x, bd0); ffma2(acc2[2][1], aP23.x, bd1);
            ffma2(acc2[2][2], aP23.x, bd2); ffma2(acc2[2][3], aP23.x, bd3);
            ffma2(acc2[3][0], aP23.y, bd0); ffma2(acc2[3][1], aP23.y, bd1);
            ffma2(acc2[3][2], aP23.y, bd2); ffma2(acc2[3][3], aP23.y, bd3);
        }
        __syncthreads();
    }

    if (COLSUM) {
        if (tid < 64) colsh[tid] = 0.f;
        __syncthreads();
    }

    float cp[4] = {0.f, 0.f, 0.f, 0.f};
    float* Cw = C + (size_t)blockIdx.z * ((size_t)M * N);
    #pragma unroll
    for (int p = 0; p < 4; p++) {
        int rowA = bm + m0 + 2 * p;
        int rowB = rowA + 1;
        float rsA = rs ? rs[rowA] : 1.f;
        float rsB = rs ? rs[rowB] : 1.f;
        float va[4], vb[4];
        #pragma unroll
        for (int j = 0; j < 4; j++) {
            float2 v = unpack2(acc2[p][j]);
            float a = v.x, b = v.y;
            if (bias) { float bj = bias[bn + n0 + j]; a += bj; b += bj; }
            if (ACT) {
                a = a > 0.f ? a : SLOPE_F * a;
                b = b > 0.f ? b : SLOPE_F * b;
            }
            if (EXPOUT) { a = __expf(a); b = __expf(b); }
            va[j] = a * rsA; vb[j] = b * rsB;
            if (COLSUM) cp[j] += va[j] + vb[j];
        }
        *(float4*)(Cw + (size_t)rowA * N + bn + n0) =
            make_float4(va[0], va[1], va[2], va[3]);
        *(float4*)(Cw + (size_t)rowB * N + bn + n0) =
            make_float4(vb[0], vb[1], vb[2], vb[3]);
    }

    if (COLSUM) {
        #pragma unroll
        for (int j = 0; j < 4; j++)
            atomicAdd(&colsh[n0 + j], cp[j]);
        __syncthreads();
        if (tid < 64) atomicAdd(&colZacc[bn + tid], colsh[tid]);
    }
}

// ---------------- fp32 GEMM: 64x64 tile (NS x 128 x 128 head GEMMs) ---------
template<bool ACT, bool SUBPRE>
__global__ __launch_bounds__(256) void k_gemm64(
    const float* __restrict__ A, const float* __restrict__ B,
    const float* __restrict__ bias, const float* __restrict__ rs,
    const float* __restrict__ pre, float* __restrict__ C,
    int M, int N, int K)
{
    __shared__ alignas(16) float As[16][68];
    __shared__ alignas(16) float Bs[16][68];
    const int bm = blockIdx.y * 64, bn = blockIdx.x * 64;
    const int tid = threadIdx.x;
    const int a_m = tid >> 2, a_k = (tid & 3) * 4;
    const int ty = tid >> 4, tx = tid & 15;
    const int m0 = ty * 4, n0 = tx * 4;

    ull acc2[2][4];
    #pragma unroll
    for (int p = 0; p < 2; p++)
        #pragma unroll
        for (int j = 0; j < 4; j++) acc2[p][j] = 0ull;

    float4 ra, rb;
    ra = *(const float4*)(A + (size_t)(bm + a_m) * K + a_k);
    rb = *(const float4*)(B + (size_t)(bn + a_m) * K + a_k);

    for (int k0 = 0; k0 < K; k0 += 16) {
        As[a_k + 0][a_m] = ra.x; As[a_k + 1][a_m] = ra.y;
        As[a_k + 2][a_m] = ra.z; As[a_k + 3][a_m] = ra.w;
        Bs[a_k + 0][a_m] = rb.x; Bs[a_k + 1][a_m] = rb.y;
        Bs[a_k + 2][a_m] = rb.z; Bs[a_k + 3][a_m] = rb.w;
        __syncthreads();
        if (k0 + 16 < K) {
            ra = *(const float4*)(A + (size_t)(bm + a_m) * K + k0 + 16 + a_k);
            rb = *(const float4*)(B + (size_t)(bn + a_m) * K + k0 + 16 + a_k);
        }
        #pragma unroll
        for (int kk = 0; kk < 16; kk++) {
            ulonglong2 aP = *(const ulonglong2*)&As[kk][m0];
            float4 b = *(const float4*)&Bs[kk][n0];
            ull bd0 = pack2(b.x, b.x), bd1 = pack2(b.y, b.y);
            ull bd2 = pack2(b.z, b.z), bd3 = pack2(b.w, b.w);
            ffma2(acc2[0][0], aP.x, bd0); ffma2(acc2[0][1], aP.x, bd1);
            ffma2(acc2[0][2], aP.x, bd2); ffma2(acc2[0][3], aP.x, bd3);
            ffma2(acc2[1][0], aP.y, bd0); ffma2(acc2[1][1], aP.y, bd1);
            ffma2(acc2[1][2], aP.y, bd2); ffma2(acc2[1][3], aP.y, bd3);
        }
        __syncthreads();
    }

    #pragma unroll
    for (int p = 0; p < 2; p++) {
        int rowA = bm + m0 + 2 * p;
        int rowB = rowA + 1;
        float rsA = rs ? rs[rowA] : 1.f;
        float rsB = rs ? rs[rowB] : 1.f;
        float va[4], vb[4];
        #pragma unroll
        for (int j = 0; j < 4; j++) {
            float2 v = unpack2(acc2[p][j]);
            float a = v.x, b = v.y;
            if (bias) { float bj = bias[bn + n0 + j]; a += bj; b += bj; }
            if (ACT) {
                a = a > 0.f ? a : SLOPE_F * a;
                b = b > 0.f ? b : SLOPE_F * b;
            }
            a *= rsA; b *= rsB;
            if (SUBPRE) {
                a = pre[(size_t)rowA * N + bn + n0 + j] - a;
                b = pre[(size_t)rowB * N + bn + n0 + j] - b;
            }
            va[j] = a; vb[j] = b;
        }
        *(float4*)(C + (size_t)rowA * N + bn + n0) =
            make_float4(va[0], va[1], va[2], va[3]);
        *(float4*)(C + (size_t)rowB * N + bn + n0) =
            make_float4(vb[0], vb[1], vb[2], vb[3]);
    }
}

// reduce over split-K partial slices: C = sum_z P[z]
__global__ void k_reduce(const float* __restrict__ P, float* __restrict__ C,
                         int nslice, int total4)
{
    int i = blockIdx.x * blockDim.x + threadIdx.x;
    if (i >= total4) return;
    size_t b = (size_t)i * 4;
    float4 s = make_float4(0.f, 0.f, 0.f, 0.f);
    for (int z = 0; z < nslice; z++) {
        float4 v = *(const float4*)(P + (size_t)z * total4 * 4 + b);
        s.x += v.x; s.y += v.y; s.z += v.z; s.w += v.w;
    }
    *(float4*)(C + b) = s;
}

// ---------------- bf16 hi/lo split of the gi1 weight matrix -----------------
__global__ void k_wsplit(const float* __restrict__ W,
                         __nv_bfloat16* __restrict__ hi,
                         __nv_bfloat16* __restrict__ lo, int n)
{
    int i = blockIdx.x * 256 + threadIdx.x;
    if (i < n) {
        float v = W[i];
        __nv_bfloat16 h = __float2bfloat16(v);
        hi[i] = h;
        lo[i] = __float2bfloat16(v - __bfloat162float(h));
    }
}

// ---------------- gi1 via wmma bf16x3 (hi*hi + hi*lo + lo*hi) ----------------
// C[m,n] = sum_k A[m,k] * W[n,k];  A fp32 split in-kernel, W pre-split.
// CTA tile 128x64, 8 warps each 32x32. K loop 8 steps of 16.
__global__ __launch_bounds__(256) void k_gi1_wmma(
    const float* __restrict__ A,
    const __nv_bfloat16* __restrict__ Bhi,
    const __nv_bfloat16* __restrict__ Blo,
    float* __restrict__ C)
{
    __shared__ alignas(32) __nv_bfloat16 Ahi[128][24];
    __shared__ alignas(32) __nv_bfloat16 Alo[128][24];
    __shared__ alignas(32) __nv_bfloat16 Bh[64][24];
    __shared__ alignas(32) __nv_bfloat16 Bl[64][24];
    const int bm = blockIdx.y * 128, bn = blockIdx.x * 64;
    const int tid = threadIdx.x, wid = tid >> 5;
    const int wm = (wid >> 1) * 32, wn = (wid & 1) * 32;

    wmma::fragment<wmma::accumulator, 16, 16, 16, float> acc[2][2];
    #pragma unroll
    for (int i = 0; i < 2; i++)
        #pragma unroll
        for (int j = 0; j < 2; j++) wmma::fill_fragment(acc[i][j], 0.f);

    const int a_m = tid >> 1, a_k = (tid & 1) * 8;
    const int b_n = tid >> 2, b_k = (tid & 3) * 4;

    for (int k0 = 0; k0 < HD; k0 += 16) {
        // A tile: fp32 -> hi/lo bf16 (packed STS.128)
        const float* Ap = A + (size_t)(bm + a_m) * HD + k0 + a_k;
        float4 v0 = *(const float4*)Ap;
        float4 v1 = *(const float4*)(Ap + 4);
        float av[8] = {v0.x, v0.y, v0.z, v0.w, v1.x, v1.y, v1.z, v1.w};
        __nv_bfloat16 hb[8], lb[8];
        #pragma unroll
        for (int q = 0; q < 8; q++) {
            __nv_bfloat16 h = __float2bfloat16(av[q]);
            hb[q] = h;
            lb[q] = __float2bfloat16(av[q] - __bfloat162float(h));
        }
        *(uint4*)&Ahi[a_m][a_k] = *(uint4*)hb;
        *(uint4*)&Alo[a_m][a_k] = *(uint4*)lb;
        // B tiles (already bf16)
        *(uint2*)&Bh[b_n][b_k] =
            *(const uint2*)(Bhi + (size_t)(bn + b_n) * HD + k0 + b_k);
        *(uint2*)&Bl[b_n][b_k] =
            *(const uint2*)(Blo + (size_t)(bn + b_n) * HD + k0 + b_k);
        __syncthreads();

        wmma::fragment<wmma::matrix_a, 16, 16, 16, __nv_bfloat16, wmma::row_major> af[2];
        wmma::fragment<wmma::matrix_b, 16, 16, 16, __nv_bfloat16, wmma::col_major> bf[2];
        // hi * hi
        wmma::load_matrix_sync(af[0], &Ahi[wm][0], 24);
        wmma::load_matrix_sync(af[1], &Ahi[wm + 16][0], 24);
        wmma::load_matrix_sync(bf[0], &Bh[wn][0], 24);
        wmma::load_matrix_sync(bf[1], &Bh[wn + 16][0], 24);
        #pragma unroll
        for (int i = 0; i < 2; i++)
            #pragma unroll
            for (int j = 0; j < 2; j++)
                wmma::mma_sync(acc[i][j], af[i], bf[j], acc[i][j]);
        // hi * lo
        wmma::load_matrix_sync(bf[0], &Bl[wn][0], 24);
        wmma::load_matrix_sync(bf[1], &Bl[wn + 16][0], 24);
        #pragma unroll
        for (int i = 0; i < 2; i++)
            #pragma unroll
            for (int j = 0; j < 2; j++)
                wmma::mma_sync(acc[i][j], af[i], bf[j], acc[i][j]);
        // lo * hi
        wmma::load_matrix_sync(af[0], &Alo[wm][0], 24);
        wmma::load_matrix_sync(af[1], &Alo[wm + 16][0], 24);
        wmma::load_matrix_sync(bf[0], &Bh[wn][0], 24);
        wmma::load_matrix_sync(bf[1], &Bh[wn + 16][0], 24);
        #pragma unroll
        for (int i = 0; i < 2; i++)
            #pragma unroll
            for (int j = 0; j < 2; j++)
                wmma::mma_sync(acc[i][j], af[i], bf[j], acc[i][j]);
        __syncthreads();
    }

    #pragma unroll
    for (int i = 0; i < 2; i++)
        #pragma unroll
        for (int j = 0; j < 2; j++)
            wmma::store_matrix_sync(
                C + (size_t)(bm + wm + 16 * i) * GD + bn + wn + 16 * j,
                acc[i][j], GD, wmma::mem_row_major);
}

// ---------------- persistent GRU recurrent kernel ---------------------------
// 384 threads, mapping (2 outputs, half-k). Input bias bih folded into the
// gate phase (gi buffers hold the raw GEMM product).
template<bool WRITE_SEQ>
__global__ __launch_bounds__(384, 1) void k_gru(
    const float* __restrict__ gi, const float* __restrict__ Whh,
    const float* __restrict__ bhh, const float* __restrict__ bih,
    float* __restrict__ hout)
{
    extern __shared__ float sm[];
    float* h_sh = sm;                          // GRROWS*128
    float* ghA  = sm + GRROWS * HD;            // GRROWS*384
    float* ghB  = ghA + GRROWS * GD;           // GRROWS*384
    float* gi_sh = ghB + GRROWS * GD;          // GRROWS*384
    __shared__ float bih_sh[GD];
    const int tid = threadIdx.x;
    const int o = tid % 192;
    const int half = tid / 192;
    const int o2 = o + 192;
    const int base = blockIdx.x * GRROWS;
    const int rows = (NS - base < GRROWS) ? (NS - base) : GRROWS;
    float* ghOut = half ? ghB : ghA;

    ull wq[64];
    {
        const ulonglong2* wg0 =
            (const ulonglong2*)(Whh + (size_t)o * HD + half * 64);
        const ulonglong2* wg1 =
            (const ulonglong2*)(Whh + (size_t)o2 * HD + half * 64);
        #pragma unroll
        for (int q = 0; q < 16; q++) {
            ulonglong2 t0 = wg0[q];
            wq[2 * q] = t0.x; wq[2 * q + 1] = t0.y;
        }
        #pragma unroll
        for (int q = 0; q < 16; q++) {
            ulonglong2 t1 = wg1[q];
            wq[32 + 2 * q] = t1.x; wq[32 + 2 * q + 1] = t1.y;
        }
    }
    const float bo0 = half ? 0.f : bhh[o];
    const float bo1 = half ? 0.f : bhh[o2];
    bih_sh[tid] = bih[tid];
    for (int idx = tid; idx < rows * HD; idx += 384) h_sh[idx] = 0.f;

    const int pr = tid / 12, pc = tid % 12;
    const bool pact = (pr < rows);
    {
        const float* src = gi + ((size_t)(base + pr) * TS + 0) * GD;
        if (pact) {
            #pragma unroll
            for (int i = 0; i < 8; i++) {
                int f = pc + 12 * i;
                cp16(gi_sh + pr * GD + f * 4, src + f * 4);
            }
        }
        cp_commit();
    }
    __syncthreads();

    for (int t = 0; t < TS; t++) {
        #pragma unroll 1
        for (int r = 0; r < rows; r += 2) {
            const ulonglong2* hp0 =
                (const ulonglong2*)(h_sh + r * HD + half * 64);
            const ulonglong2* hp1 =
                (const ulonglong2*)(h_sh + (r + 1) * HD + half * 64);
            ull a0 = 0ull, b0 = 0ull, a1 = 0ull, b1 = 0ull;
            #pragma unroll
            for (int q = 0; q < 16; q++) {
                ulonglong2 x0 = hp0[q];
                ulonglong2 x1 = hp1[q];
                ffma2(a0, x0.x, wq[2 * q]);
                ffma2(b0, x0.x, wq[32 + 2 * q]);
                ffma2(a1, x1.x, wq[2 * q]);
                ffma2(b1, x1.x, wq[32 + 2 * q]);
                ffma2(a0, x0.y, wq[2 * q + 1]);
                ffma2(b0, x0.y, wq[32 + 2 * q + 1]);
                ffma2(a1, x1.y, wq[2 * q + 1]);
                ffma2(b1, x1.y, wq[32 + 2 * q + 1]);
            }
            float2 pa0 = unpack2(a0), pb0 = unpack2(b0);
            float2 pa1 = unpack2(a1), pb1 = unpack2(b1);
            ghOut[r * GD + o]        = (pa0.x + pa0.y) + bo0;
            ghOut[r * GD + o2]       = (pb0.x + pb0.y) + bo1;
            ghOut[(r + 1) * GD + o]  = (pa1.x + pa1.y) + bo0;
            ghOut[(r + 1) * GD + o2] = (pb1.x + pb1.y) + bo1;
        }
        cp_wait_all();
        __syncthreads();
        #pragma unroll 1
        for (int idx = tid; idx < rows * HD; idx += 384) {
            int r = idx >> 7, j = idx & 127;
            float gir = gi_sh[r * GD + j]       + bih_sh[j];
            float giz = gi_sh[r * GD + j + 128] + bih_sh[j + 128];
            float gin = gi_sh[r * GD + j + 256] + bih_sh[j + 256];
            float ghr = ghA[r * GD + j]       + ghB[r * GD + j];
            float ghz = ghA[r * GD + j + 128] + ghB[r * GD + j + 128];
            float ghn = ghA[r * GD + j + 256] + ghB[r * GD + j + 256];
            float rg = __fdividef(1.f, 1.f + __expf(-(gir + ghr)));
            float zg = __fdividef(1.f, 1.f + __expf(-(giz + ghz)));
            float a2 = gin + rg * ghn;
            float ng = 1.f - __fdividef(2.f, __expf(2.f * a2) + 1.f);
            float hprev = h_sh[idx];
            float hn = (1.f - zg) * ng + zg * hprev;
            h_sh[idx] = hn;
            if (WRITE_SEQ)
                hout[((size_t)(base + r) * TS + t) * HD + j] = hn;
            else if (t == TS - 1)
                hout[(size_t)(base + r) * HD + j] = hn;
        }
        __syncthreads();
        if (t + 1 < TS) {
            const float* src = gi + ((size_t)(base + pr) * TS + (t + 1)) * GD;
            if (pact) {
                #pragma unroll
                for (int i = 0; i < 8; i++) {
                    int f = pc + 12 * i;
                    cp16(gi_sh + pr * GD + f * 4, src + f * 4);
                }
            }
            cp_commit();
        }
    }
}

// ---------------- small helpers --------------------------------------------
__global__ void k_zero(float* p, int n) {
    int i = blockIdx.x * blockDim.x + threadIdx.x;
    if (i < n) p[i] = 0.f;
}

__global__ void k_rownorm(const float* __restrict__ src, float* __restrict__ dst) {
    int row = blockIdx.x * 8 + (threadIdx.x >> 5);
    int lane = threadIdx.x & 31;
    const float4* s4 = (const float4*)(src + (size_t)row * HD);
    float4 v = s4[lane];
    float ss = v.x*v.x + v.y*v.y + v.z*v.z + v.w*v.w;
    #pragma unroll
    for (int off = 16; off; off >>= 1) ss += __shfl_xor_sync(0xffffffffu, ss, off);
    float n = sqrtf(ss);
    float inv = (n > 0.f) ? 1.f / n : 0.f;
    ((float4*)(dst + (size_t)row * HD))[lane] =
        make_float4(v.x*inv, v.y*inv, v.z*inv, v.w*inv);
}

// cf2[row,:] = cf[row,:] / colZ[row]
__global__ void k_cfscale(const float* __restrict__ cf,
                          const float* __restrict__ colZ,
                          float* __restrict__ out)
{
    int row = blockIdx.x * 8 + (threadIdx.x >> 5);
    int lane = threadIdx.x & 31;
    float rz = __fdividef(1.f, colZ[row]);
    float4 v = ((const float4*)(cf + (size_t)row * HD))[lane];
    ((float4*)(out + (size_t)row * HD))[lane] =
        make_float4(v.x * rz, v.y * rz, v.z * rz, v.w * rz);
}

// top-K=20 per row of |sim| (diag excluded), jax-stable ties (lowest index).
__global__ __launch_bounds__(256) void k_topk(
    const float* __restrict__ sim, int* __restrict__ tidx,
    float* __restrict__ tval, float* __restrict__ colsum)
{
    int i = blockIdx.x;
    __shared__ float sabs[NS];
    __shared__ float segv[128];
    __shared__ int   segi[128];
    __shared__ float bcv[4];
    __shared__ int   bci[4];
    const int tid = threadIdx.x;
    const float* row = sim + (size_t)i * NS;

    for (int c4 = tid; c4 < NS / 4; c4 += 256) {
        float4 v = *(const float4*)(row + c4 * 4);
        float4 a = make_float4(fabsf(v.x), fabsf(v.y), fabsf(v.z), fabsf(v.w));
        *(float4*)&sabs[c4 * 4] = a;
    }
    __syncthreads();
    if (tid == 0) sabs[i] = -1.f;
    __syncthreads();

    if (tid < 128) {
        float bv = -2.f; int bi = tid * 32;
        #pragma unroll 4
        for (int j = 0; j < 32; j++) {
            float v = sabs[tid * 32 + j];
            if (v > bv) { bv = v; bi = tid * 32 + j; }
        }
        segv[tid] = bv; segi[tid] = bi;
    }
    __syncthreads();

    for (int k = 0; k < NK; k++) {
        if (tid < 128) {
            float bv = segv[tid]; int bi = segi[tid];
            #pragma unroll
            for (int off = 16; off; off >>= 1) {
                float ov = __shfl_down_sync(0xffffffffu, bv, off);
                int   oi = __shfl_down_sync(0xffffffffu, bi, off);
                if (ov > bv || (ov == bv && oi < bi)) { bv = ov; bi = oi; }
            }
            if ((tid & 31) == 0) { bcv[tid >> 5] = bv; bci[tid >> 5] = bi; }
        }
        __syncthreads();
        if (tid < 32) {
            int bi = 0;
            if (tid == 0) {
                float bv = bcv[0]; bi = bci[0];
                #pragma unroll
                for (int w = 1; w < 4; w++)
                    if (bcv[w] > bv || (bcv[w] == bv && bci[w] < bi)) {
                        bv = bcv[w]; bi = bci[w];
                    }
                tidx[i * NK + k] = bi;
                float sv = row[bi];
                tval[i * NK + k] = sv;
                atomicAdd(&colsum[bi], sv);
                sabs[bi] = -2.f;
            }
            bi = __shfl_sync(0xffffffffu, bi, 0);
            __syncwarp();
            int s = bi >> 5;
            int idx = s * 32 + tid;
            float bv2 = sabs[idx]; int bi2 = idx;
            #pragma unroll
            for (int off = 16; off; off >>= 1) {
                float ov = __shfl_down_sync(0xffffffffu, bv2, off);
                int   oi = __shfl_down_sync(0xffffffffu, bi2, off);
                if (ov > bv2 || (ov == bv2 && oi < bi2)) { bv2 = ov; bi2 = oi; }
            }
            if (tid == 0) { segv[s] = bv2; segi[s] = bi2; }
        }
        __syncthreads();
    }
}

__global__ void k_scatter(const int* __restrict__ tidx, const float* __restrict__ tval,
                          const float* __restrict__ g, float* __restrict__ concept)
{
    int i = blockIdx.x, d = threadIdx.x;
    float gv = g[(size_t)i * HD + d];
    #pragma unroll
    for (int k = 0; k < NK; k++) {
        int c = __ldg(&tidx[i * NK + k]);
        float v = __ldg(&tval[i * NK + k]);
        atomicAdd(&concept[(size_t)c * HD + d], v * gv);
    }
}

__global__ void k_diag_valid(const float* __restrict__ colsum, const float* __restrict__ sim,
                             const float* __restrict__ g, float* __restrict__ concept,
                             float* __restrict__ valid)
{
    int j = blockIdx.x, t = threadIdx.x;
    float cs = colsum[j];
    float v = concept[(size_t)j * HD + t];
    if (cs != 0.f) {
        float dg = sim[(size_t)j * NS + j];
        v += dg * g[(size_t)j * HD + t];
        concept[(size_t)j * HD + t] = v;
    }
    float s = v;
    #pragma unroll
    for (int off = 16; off; off >>= 1) s += __shfl_xor_sync(0xffffffffu, s, off);
    __shared__ float ws[4];
    if ((t & 31) == 0) ws[t >> 5] = s;
    __syncthreads();
    if (t == 0) {
        float tot = ws[0] + ws[1] + ws[2] + ws[3];
        valid[j] = (tot != 0.f) ? 1.f : 0.f;
    }
}

__global__ void k_final(const float* __restrict__ fore, const float* __restrict__ indi,
                        const float* __restrict__ Wout, const float* __restrict__ bout,
                        float* __restrict__ out)
{
    int row = blockIdx.x * 8 + (threadIdx.x >> 5);
    int lane = threadIdx.x & 31;
    float4 a = ((const float4*)(fore + (size_t)row * HD))[lane];
    float4 b = ((const float4*)(indi + (size_t)row * HD))[lane];
    float4 w = ((const float4*)Wout)[lane];
    float s = (a.x+b.x)*w.x + (a.y+b.y)*w.y + (a.z+b.z)*w.z + (a.w+b.w)*w.w;
    #pragma unroll
    for (int off = 16; off; off >>= 1) s += __shfl_xor_sync(0xffffffffu, s, off);
    if (lane == 0) out[row] = s + bout[0];
}

// ---------------- driver -----------------------------------------------------
extern "C" void kernel_launch(void* const* d_in, const int* in_sizes, int n_in,
                              void* d_out, int out_size)
{
    const float* x     = (const float*)d_in[0];
    const float* Wih0  = (const float*)d_in[1];
    const float* Whh0  = (const float*)d_in[2];
    const float* bih0  = (const float*)d_in[3];
    const float* bhh0  = (const float*)d_in[4];
    const float* Wih1  = (const float*)d_in[5];
    const float* Whh1  = (const float*)d_in[6];
    const float* bih1  = (const float*)d_in[7];
    const float* bhh1  = (const float*)d_in[8];
    const float* W_hc  = (const float*)d_in[9];
    const float* b_hc  = (const float*)d_in[10];
    const float* W_hs  = (const float*)d_in[11];
    const float* b_hs  = (const float*)d_in[12];
    const float* W_fore= (const float*)d_in[13];
    const float* b_fore= (const float*)d_in[14];
    const float* W_back= (const float*)d_in[15];
    const float* b_back= (const float*)d_in[16];
    const float* W_indi= (const float*)d_in[17];
    const float* b_indi= (const float*)d_in[18];
    const float* W_out = (const float*)d_in[19];
    const float* b_out = (const float*)d_in[20];
    float* out = (float*)d_out;

    float *gi, *h0, *g, *gn, *sim, *colsum, *colZ, *valid, *concept;
    float *cf, *cfn, *hs, *t1, *t2, *t3, *t4, *tval;
    int* tidx;
    __nv_bfloat16 *whi, *wlo;
    cudaGetSymbolAddress((void**)&gi,      d_gi);
    cudaGetSymbolAddress((void**)&h0,      d_h0);
    cudaGetSymbolAddress((void**)&g,       d_g);
    cudaGetSymbolAddress((void**)&gn,      d_gn);
    cudaGetSymbolAddress((void**)&sim,     d_sim);
    cudaGetSymbolAddress((void**)&tidx,    d_tidx);
    cudaGetSymbolAddress((void**)&tval,    d_tval);
    cudaGetSymbolAddress((void**)&colsum,  d_colsum);
    cudaGetSymbolAddress((void**)&colZ,    d_colZ);
    cudaGetSymbolAddress((void**)&valid,   d_valid);
    cudaGetSymbolAddress((void**)&concept, d_concept);
    cudaGetSymbolAddress((void**)&cf,      d_cf);
    cudaGetSymbolAddress((void**)&cfn,     d_cfn);
    cudaGetSymbolAddress((void**)&hs,      d_hsb);
    cudaGetSymbolAddress((void**)&t1,      d_t1);
    cudaGetSymbolAddress((void**)&t2,      d_t2);
    cudaGetSymbolAddress((void**)&t3,      d_t3);
    cudaGetSymbolAddress((void**)&t4,      d_t4);
    cudaGetSymbolAddress((void**)&whi,     d_Whi);
    cudaGetSymbolAddress((void**)&wlo,     d_Wlo);

    const int GRU_SMEM = (GRROWS * HD + 3 * GRROWS * GD) * 4;
    cudaFuncSetAttribute((const void*)k_gru<true>,
                         cudaFuncAttributeMaxDynamicSharedMemorySize, GRU_SMEM);
    cudaFuncSetAttribute((const void*)k_gru<false>,
                         cudaFuncAttributeMaxDynamicSharedMemorySize, GRU_SMEM);

    const int MT = NS * TS;         // 262144
    const int GRU_GRID = (NS + GRROWS - 1) / GRROWS;  // 147

    // Launch order: gru0 is our 4th launch so ncu (-s 5 -c 1, one harness
    // pre-launch) captures the GRU kernel.
    // #1 gi0 = x @ Wih0^T (bias folded into GRU gate phase)
    k_gemm<true, false, false, false><<<dim3(GD / 64, MT / 128, 1), 256>>>(
        x, Wih0, nullptr, nullptr, nullptr, gi, MT, GD, FI, FI);
    // #2, #3 tiny zeros (needed later)
    k_zero<<<(NS + 255) / 256, 256>>>(colsum, NS);
    k_zero<<<(NS + 255) / 256, 256>>>(colZ, NS);
    // #4 GRU layer 0 (writes full sequence)  <- ncu capture target
    k_gru<true><<<GRU_GRID, 384, GRU_SMEM>>>(gi, Whh0, bhh0, bih0, h0);
    // Wih1 hi/lo split, then gi1 = h0 @ Wih1^T via wmma bf16x3
    k_wsplit<<<(GD * HD + 255) / 256, 256>>>(Wih1, whi, wlo, GD * HD);
    k_gi1_wmma<<<dim3(GD / 64, MT / 128), 256>>>(h0, whi, wlo, gi);
    // GRU layer 1 (writes final hidden only -> g)
    k_gru<false><<<GRU_GRID, 384, GRU_SMEM>>>(gi, Whh1, bhh1, bih1, g);

    // concept accumulator zero (before scatter)
    k_zero<<<(NS * HD + 255) / 256, 256>>>(concept, NS * HD);

    // normalized g, sim = gn @ gn^T
    k_rownorm<<<NS / 8, 256>>>(g, gn);
    k_gemm<true, false, false, false><<<dim3(NS / 64, NS / 128, 1), 256>>>(
        gn, gn, nullptr, nullptr, nullptr, sim, NS, NS, HD, HD);

    // top-K selection + concept aggregation
    k_topk<<<NS, 256>>>(sim, tidx, tval, colsum);
    k_scatter<<<NS, 128>>>(tidx, tval, g, concept);
    k_diag_valid<<<NS, 128>>>(colsum, sim, g, concept, valid);

    // cf = lrelu(concept @ W_hc^T + b_hc) * valid
    k_gemm64<true, false><<<dim3(HD / 64, NS / 64), 256>>>(
        concept, W_hc, b_hc, valid, nullptr, cf, NS, HD, HD);
    k_rownorm<<<NS / 8, 256>>>(cf, cfn);

    // E = exp(gn @ cfn^T) with column sums fused into the epilogue
    k_gemm<true, false, true, true><<<dim3(NS / 64, NS / 128, 1), 256>>>(
        gn, cfn, nullptr, nullptr, colZ, sim, NS, NS, HD, HD);

    // cf2 = cf / colZ (row-wise); then t1 = E @ cf2 == softmax(S,axis0) @ cf
    k_cfscale<<<NS / 8, 256>>>(cf, colZ, t2);
    k_gemm<false, false, false, false><<<dim3(HD / 64, NS / 128, 8), 256>>>(
        sim, t2, nullptr, nullptr, nullptr, gi, NS, HD, NS, NS / 8);
    k_reduce<<<(NS * HD / 4 + 255) / 256, 256>>>(gi, t1, 8, NS * HD / 4);

    // hs = lrelu(t1 @ W_hs^T + b_hs)
    k_gemm64<true, false><<<dim3(HD / 64, NS / 64), 256>>>(
        t1, W_hs, b_hs, nullptr, nullptr, hs, NS, HD, HD);

    // t3 = g - lrelu(hs @ W_back^T + b_back)
    k_gemm64<true, true><<<dim3(HD / 64, NS / 64), 256>>>(
        hs, W_back, b_back, nullptr, g, t3, NS, HD, HD);
    // t2 = lrelu(hs @ W_fore^T + b_fore)
    k_gemm64<true, false><<<dim3(HD / 64, NS / 64), 256>>>(
        hs, W_fore, b_fore, nullptr, nullptr, t2, NS, HD, HD);
    // t4 = lrelu(t3 @ W_indi^T + b_indi)
    k_gemm64<true, false><<<dim3(HD / 64, NS / 64), 256>>>(
        t3, W_indi, b_indi, nullptr, nullptr, t4, NS, HD, HD);
    k_final<<<NS / 8, 256>>>(t2, t4, W_out, b_out, out);
}

// round 13
// speedup vs baseline: 1.3556x; 1.0340x over previous
#include <cuda_runtime.h>
#include <cuda_bf16.h>
#include <mma.h>
#include <math.h>
#include <stdint.h>
#include <stddef.h>

using namespace nvcuda;

// Problem dims (fixed by the dataset)
#define NS   4096      // batch
#define TS   64        // timesteps
#define FI   32        // input features
#define HD   128       // hidden
#define GD   384       // 3*H
#define NK   20        // top-k
#define SLOPE_F 0.2f
#define GRROWS 28      // batch rows per GRU CTA (147 CTAs -> all 148 SMs)

typedef unsigned long long ull;
typedef __nv_bfloat16 bf16;

// ---------------- f32x2 packed helpers (Blackwell FFMA2) --------------------
__device__ __forceinline__ ull pack2(float lo, float hi) {
    ull r;
    asm("mov.b64 %0, {%1, %2};" : "=l"(r) : "f"(lo), "f"(hi));
    return r;
}
__device__ __forceinline__ float2 unpack2(ull v) {
    float2 r;
    asm("mov.b64 {%0, %1}, %2;" : "=f"(r.x), "=f"(r.y) : "l"(v));
    return r;
}
__device__ __forceinline__ void ffma2(ull& d, ull a, ull b) {
    asm("fma.rn.f32x2 %0, %1, %2, %0;" : "+l"(d) : "l"(a), "l"(b));
}

// ---------------- cp.async helpers -----------------------------------------
__device__ __forceinline__ void cp16(float* dst_sh, const float* src_g) {
    uint32_t d = (uint32_t)__cvta_generic_to_shared(dst_sh);
    asm volatile("cp.async.ca.shared.global [%0], [%1], 16;" :: "r"(d), "l"(src_g));
}
__device__ __forceinline__ void cp_commit() {
    asm volatile("cp.async.commit_group;");
}
__device__ __forceinline__ void cp_wait_all() {
    asm volatile("cp.async.wait_all;");
}

// ---------------- scratch (device globals; no runtime allocation) ----------
__device__ float d_gi[(size_t)NS * TS * GD];
__device__ float d_h0[(size_t)NS * TS * HD];
__device__ float d_g  [NS * HD];
__device__ float d_gn [NS * HD];
__device__ float d_sim[(size_t)NS * NS];
__device__ int   d_tidx[NS * NK];
__device__ float d_tval[NS * NK];
__device__ float d_colsum[NS];
__device__ float d_colZ[NS];
__device__ float d_valid[NS];
__device__ float d_concept[NS * HD];
__device__ float d_cf [NS * HD];
__device__ float d_cfn[NS * HD];
__device__ float d_hsb[NS * HD];
__device__ float d_t1 [NS * HD];
__device__ float d_t2 [NS * HD];
__device__ float d_t3 [NS * HD];
__device__ float d_t4 [NS * HD];
__device__ bf16 d_Whi[GD * HD];     // Wih1 split high
__device__ bf16 d_Wlo[GD * HD];     // Wih1 split low
__device__ bf16 d_gnhi[NS * HD];
__device__ bf16 d_gnlo[NS * HD];
__device__ bf16 d_cfnhi[NS * HD];
__device__ bf16 d_cfnlo[NS * HD];
__device__ bf16 d_cf2hi[NS * HD];
__device__ bf16 d_cf2lo[NS * HD];

// ---------------- fp32 GEMM: 128x64 tile, FFMA2 (kept for gi0, K=32) --------
template<bool TRANSB>
__global__ __launch_bounds__(256) void k_gemm(
    const float* __restrict__ A, const float* __restrict__ B,
    float* __restrict__ C, int M, int N, int K)
{
    __shared__ alignas(16) float As[16][132];
    __shared__ alignas(16) float Bs[16][68];
    const int bm = blockIdx.y * 128, bn = blockIdx.x * 64;
    const int tid = threadIdx.x;

    const int a_m = tid >> 1, a_k = (tid & 1) * 8;
    const int ty = tid >> 4, tx = tid & 15;
    const int m0 = ty * 8, n0 = tx * 4;
    const int b_n = tid >> 2, b_k = (tid & 3) * 4;
    const int nb_k = tid >> 4, nb_n4 = (tid & 15) * 4;

    ull acc2[4][4];
    #pragma unroll
    for (int p = 0; p < 4; p++)
        #pragma unroll
        for (int j = 0; j < 4; j++) acc2[p][j] = 0ull;

    float4 ra0, ra1, rb;
    {
        const float* Ap = A + (size_t)(bm + a_m) * K + a_k;
        ra0 = *(const float4*)(Ap);
        ra1 = *(const float4*)(Ap + 4);
        if (TRANSB)
            rb = *(const float4*)(B + (size_t)(bn + b_n) * K + b_k);
        else
            rb = *(const float4*)(B + (size_t)nb_k * N + bn + nb_n4);
    }

    for (int k0 = 0; k0 < K; k0 += 16) {
        As[a_k + 0][a_m] = ra0.x; As[a_k + 1][a_m] = ra0.y;
        As[a_k + 2][a_m] = ra0.z; As[a_k + 3][a_m] = ra0.w;
        As[a_k + 4][a_m] = ra1.x; As[a_k + 5][a_m] = ra1.y;
        As[a_k + 6][a_m] = ra1.z; As[a_k + 7][a_m] = ra1.w;
        if (TRANSB) {
            Bs[b_k + 0][b_n] = rb.x; Bs[b_k + 1][b_n] = rb.y;
            Bs[b_k + 2][b_n] = rb.z; Bs[b_k + 3][b_n] = rb.w;
        } else {
            *(float4*)&Bs[nb_k][nb_n4] = rb;
        }
        __syncthreads();
        if (k0 + 16 < K) {
            const float* Ap = A + (size_t)(bm + a_m) * K + (k0 + 16) + a_k;
            ra0 = *(const float4*)(Ap);
            ra1 = *(const float4*)(Ap + 4);
            if (TRANSB)
                rb = *(const float4*)(B + (size_t)(bn + b_n) * K + (k0 + 16) + b_k);
            else
                rb = *(const float4*)(B + (size_t)(k0 + 16 + nb_k) * N + bn + nb_n4);
        }
        #pragma unroll
        for (int kk = 0; kk < 16; kk++) {
            ulonglong2 aP01 = *(const ulonglong2*)&As[kk][m0];
            ulonglong2 aP23 = *(const ulonglong2*)&As[kk][m0 + 4];
            float4 b = *(const float4*)&Bs[kk][n0];
            ull bd0 = pack2(b.x, b.x), bd1 = pack2(b.y, b.y);
            ull bd2 = pack2(b.z, b.z), bd3 = pack2(b.w, b.w);
            ffma2(acc2[0][0], aP01.x, bd0); ffma2(acc2[0][1], aP01.x, bd1);
            ffma2(acc2[0][2], aP01.x, bd2); ffma2(acc2[0][3], aP01.x, bd3);
            ffma2(acc2[1][0], aP01.y, bd0); ffma2(acc2[1][1], aP01.y, bd1);
            ffma2(acc2[1][2], aP01.y, bd2); ffma2(acc2[1][3], aP01.y, bd3);
            ffma2(acc2[2][0], aP23.x, bd0); ffma2(acc2[2][1], aP23.x, bd1);
            ffma2(acc2[2][2], aP23.x, bd2); ffma2(acc2[2][3], aP23.x, bd3);
            ffma2(acc2[3][0], aP23.y, bd0); ffma2(acc2[3][1], aP23.y, bd1);
            ffma2(acc2[3][2], aP23.y, bd2); ffma2(acc2[3][3], aP23.y, bd3);
        }
        __syncthreads();
    }

    #pragma unroll
    for (int p = 0; p < 4; p++) {
        int rowA = bm + m0 + 2 * p;
        int rowB = rowA + 1;
        float va[4], vb[4];
        #pragma unroll
        for (int j = 0; j < 4; j++) {
            float2 v = unpack2(acc2[p][j]);
            va[j] = v.x; vb[j] = v.y;
        }
        *(float4*)(C + (size_t)rowA * N + bn + n0) =
            make_float4(va[0], va[1], va[2], va[3]);
        *(float4*)(C + (size_t)rowB * N + bn + n0) =
            make_float4(vb[0], vb[1], vb[2], vb[3]);
    }
}

// ---------------- fp32 GEMM: 64x64 tile (NS x 128 x 128 head GEMMs) ---------
template<bool ACT, bool SUBPRE>
__global__ __launch_bounds__(256) void k_gemm64(
    const float* __restrict__ A, const float* __restrict__ B,
    const float* __restrict__ bias, const float* __restrict__ rs,
    const float* __restrict__ pre, float* __restrict__ C,
    int M, int N, int K)
{
    __shared__ alignas(16) float As[16][68];
    __shared__ alignas(16) float Bs[16][68];
    const int bm = blockIdx.y * 64, bn = blockIdx.x * 64;
    const int tid = threadIdx.x;
    const int a_m = tid >> 2, a_k = (tid & 3) * 4;
    const int ty = tid >> 4, tx = tid & 15;
    const int m0 = ty * 4, n0 = tx * 4;

    ull acc2[2][4];
    #pragma unroll
    for (int p = 0; p < 2; p++)
        #pragma unroll
        for (int j = 0; j < 4; j++) acc2[p][j] = 0ull;

    float4 ra, rb;
    ra = *(const float4*)(A + (size_t)(bm + a_m) * K + a_k);
    rb = *(const float4*)(B + (size_t)(bn + a_m) * K + a_k);

    for (int k0 = 0; k0 < K; k0 += 16) {
        As[a_k + 0][a_m] = ra.x; As[a_k + 1][a_m] = ra.y;
        As[a_k + 2][a_m] = ra.z; As[a_k + 3][a_m] = ra.w;
        Bs[a_k + 0][a_m] = rb.x; Bs[a_k + 1][a_m] = rb.y;
        Bs[a_k + 2][a_m] = rb.z; Bs[a_k + 3][a_m] = rb.w;
        __syncthreads();
        if (k0 + 16 < K) {
            ra = *(const float4*)(A + (size_t)(bm + a_m) * K + k0 + 16 + a_k);
            rb = *(const float4*)(B + (size_t)(bn + a_m) * K + k0 + 16 + a_k);
        }
        #pragma unroll
        for (int kk = 0; kk < 16; kk++) {
            ulonglong2 aP = *(const ulonglong2*)&As[kk][m0];
            float4 b = *(const float4*)&Bs[kk][n0];
            ull bd0 = pack2(b.x, b.x), bd1 = pack2(b.y, b.y);
            ull bd2 = pack2(b.z, b.z), bd3 = pack2(b.w, b.w);
            ffma2(acc2[0][0], aP.x, bd0); ffma2(acc2[0][1], aP.x, bd1);
            ffma2(acc2[0][2], aP.x, bd2); ffma2(acc2[0][3], aP.x, bd3);
            ffma2(acc2[1][0], aP.y, bd0); ffma2(acc2[1][1], aP.y, bd1);
            ffma2(acc2[1][2], aP.y, bd2); ffma2(acc2[1][3], aP.y, bd3);
        }
        __syncthreads();
    }

    #pragma unroll
    for (int p = 0; p < 2; p++) {
        int rowA = bm + m0 + 2 * p;
        int rowB = rowA + 1;
        float rsA = rs ? rs[rowA] : 1.f;
        float rsB = rs ? rs[rowB] : 1.f;
        float va[4], vb[4];
        #pragma unroll
        for (int j = 0; j < 4; j++) {
            float2 v = unpack2(acc2[p][j]);
            float a = v.x, b = v.y;
            if (bias) { float bj = bias[bn + n0 + j]; a += bj; b += bj; }
            if (ACT) {
                a = a > 0.f ? a : SLOPE_F * a;
                b = b > 0.f ? b : SLOPE_F * b;
            }
            a *= rsA; b *= rsB;
            if (SUBPRE) {
                a = pre[(size_t)rowA * N + bn + n0 + j] - a;
                b = pre[(size_t)rowB * N + bn + n0 + j] - b;
            }
            va[j] = a; vb[j] = b;
        }
        *(float4*)(C + (size_t)rowA * N + bn + n0) =
            make_float4(va[0], va[1], va[2], va[3]);
        *(float4*)(C + (size_t)rowB * N + bn + n0) =
            make_float4(vb[0], vb[1], vb[2], vb[3]);
    }
}

// reduce over split-K partial slices: C = sum_z P[z]
__global__ void k_reduce(const float* __restrict__ P, float* __restrict__ C,
                         int nslice, int total4)
{
    int i = blockIdx.x * blockDim.x + threadIdx.x;
    if (i >= total4) return;
    size_t b = (size_t)i * 4;
    float4 s = make_float4(0.f, 0.f, 0.f, 0.f);
    for (int z = 0; z < nslice; z++) {
        float4 v = *(const float4*)(P + (size_t)z * total4 * 4 + b);
        s.x += v.x; s.y += v.y; s.z += v.z; s.w += v.w;
    }
    *(float4*)(C + b) = s;
}

// ---------------- bf16 hi/lo split helper ------------------------------------
__global__ void k_wsplit(const float* __restrict__ W,
                         bf16* __restrict__ hi, bf16* __restrict__ lo, int n)
{
    int i = blockIdx.x * 256 + threadIdx.x;
    if (i < n) {
        float v = W[i];
        bf16 h = __float2bfloat16(v);
        hi[i] = h;
        lo[i] = __float2bfloat16(v - __bfloat162float(h));
    }
}

// ---------------- generic wmma bf16x3:  C = A @ B^T,  K = 128 ----------------
// A fp32 [M,128] split in-kernel; Bhi/Blo [N,128] bf16 pre-split.
// CTA tile 128x64, 8 warps each 32x32.
// EXPCS: C = exp(raw); column sums accumulated into colZacc.
template<bool EXPCS>
__global__ __launch_bounds__(256) void k_wmma_nt(
    const float* __restrict__ A,
    const bf16* __restrict__ Bhi, const bf16* __restrict__ Blo,
    float* __restrict__ colZacc, float* __restrict__ C, int N)
{
    __shared__ alignas(32) bf16 Ahi[128][24];
    __shared__ alignas(32) bf16 Alo[128][24];
    __shared__ alignas(32) bf16 Bh[64][24];
    __shared__ alignas(32) bf16 Bl[64][24];
    __shared__ float colsh[64];
    __shared__ float stag[8][16][16];
    const int bm = blockIdx.y * 128, bn = blockIdx.x * 64;
    const int tid = threadIdx.x, wid = tid >> 5;
    const int lane = tid & 31;
    const int wm = (wid >> 1) * 32, wn = (wid & 1) * 32;

    if (EXPCS && tid < 64) colsh[tid] = 0.f;

    wmma::fragment<wmma::accumulator, 16, 16, 16, float> acc[2][2];
    #pragma unroll
    for (int i = 0; i < 2; i++)
        #pragma unroll
        for (int j = 0; j < 2; j++) wmma::fill_fragment(acc[i][j], 0.f);

    const int a_m = tid >> 1, a_k = (tid & 1) * 8;
    const int b_n = tid >> 2, b_k = (tid & 3) * 4;

    for (int k0 = 0; k0 < HD; k0 += 16) {
        const float* Ap = A + (size_t)(bm + a_m) * HD + k0 + a_k;
        float4 v0 = *(const float4*)Ap;
        float4 v1 = *(const float4*)(Ap + 4);
        float av[8] = {v0.x, v0.y, v0.z, v0.w, v1.x, v1.y, v1.z, v1.w};
        bf16 hb[8], lb[8];
        #pragma unroll
        for (int q = 0; q < 8; q++) {
            bf16 h = __float2bfloat16(av[q]);
            hb[q] = h;
            lb[q] = __float2bfloat16(av[q] - __bfloat162float(h));
        }
        *(uint4*)&Ahi[a_m][a_k] = *(uint4*)hb;
        *(uint4*)&Alo[a_m][a_k] = *(uint4*)lb;
        *(uint2*)&Bh[b_n][b_k] =
            *(const uint2*)(Bhi + (size_t)(bn + b_n) * HD + k0 + b_k);
        *(uint2*)&Bl[b_n][b_k] =
            *(const uint2*)(Blo + (size_t)(bn + b_n) * HD + k0 + b_k);
        __syncthreads();

        wmma::fragment<wmma::matrix_a, 16, 16, 16, bf16, wmma::row_major> af[2];
        wmma::fragment<wmma::matrix_b, 16, 16, 16, bf16, wmma::col_major> bf[2];
        wmma::load_matrix_sync(af[0], &Ahi[wm][0], 24);
        wmma::load_matrix_sync(af[1], &Ahi[wm + 16][0], 24);
        wmma::load_matrix_sync(bf[0], &Bh[wn][0], 24);
        wmma::load_matrix_sync(bf[1], &Bh[wn + 16][0], 24);
        #pragma unroll
        for (int i = 0; i < 2; i++)
            #pragma unroll
            for (int j = 0; j < 2; j++)
                wmma::mma_sync(acc[i][j], af[i], bf[j], acc[i][j]);
        wmma::load_matrix_sync(bf[0], &Bl[wn][0], 24);
        wmma::load_matrix_sync(bf[1], &Bl[wn + 16][0], 24);
        #pragma unroll
        for (int i = 0; i < 2; i++)
            #pragma unroll
            for (int j = 0; j < 2; j++)
                wmma::mma_sync(acc[i][j], af[i], bf[j], acc[i][j]);
        wmma::load_matrix_sync(af[0], &Alo[wm][0], 24);
        wmma::load_matrix_sync(af[1], &Alo[wm + 16][0], 24);
        wmma::load_matrix_sync(bf[0], &Bh[wn][0], 24);
        wmma::load_matrix_sync(bf[1], &Bh[wn + 16][0], 24);
        #pragma unroll
        for (int i = 0; i < 2; i++)
            #pragma unroll
            for (int j = 0; j < 2; j++)
                wmma::mma_sync(acc[i][j], af[i], bf[j], acc[i][j]);
        __syncthreads();
    }

    #pragma unroll
    for (int i = 0; i < 2; i++)
        #pragma unroll
        for (int j = 0; j < 2; j++) {
            if (EXPCS) {
                #pragma unroll
                for (int e = 0; e < acc[i][j].num_elements; e++)
                    acc[i][j].x[e] = __expf(acc[i][j].x[e]);
                // stage for column sums
                wmma::store_matrix_sync(&stag[wid][0][0], acc[i][j], 16,
                                        wmma::mem_row_major);
                __syncwarp();
                if (lane < 16) {
                    float s = 0.f;
                    #pragma unroll
                    for (int r = 0; r < 16; r++) s += stag[wid][r][lane];
                    atomicAdd(&colsh[wn + 16 * j + lane], s);
                }
                __syncwarp();
            }
            wmma::store_matrix_sync(
                C + (size_t)(bm + wm + 16 * i) * N + bn + wn + 16 * j,
                acc[i][j], N, wmma::mem_row_major);
        }

    if (EXPCS) {
        __syncthreads();
        if (tid < 64) atomicAdd(&colZacc[bn + tid], colsh[tid]);
    }
}

// ---------------- wmma bf16x3:  P[z] = A[:, kslice] @ B[kslice, :] -----------
// A fp32 [M,K] split in-kernel; Bhi/Blo [K,128] bf16 row-major pre-split.
// CTA tile 128x64; split-K partials at P + z*M*128.
__global__ __launch_bounds__(256) void k_wmma_nn(
    const float* __restrict__ A,
    const bf16* __restrict__ Bhi, const bf16* __restrict__ Blo,
    float* __restrict__ P, int M, int K, int ksplit)
{
    __shared__ alignas(32) bf16 Ahi[128][24];
    __shared__ alignas(32) bf16 Alo[128][24];
    __shared__ alignas(32) bf16 Bh[16][72];
    __shared__ alignas(32) bf16 Bl[16][72];
    const int bm = blockIdx.y * 128, bn = blockIdx.x * 64;
    const int tid = threadIdx.x, wid = tid >> 5;
    const int wm = (wid >> 1) * 32, wn = (wid & 1) * 32;
    const int kbase = blockIdx.z * ksplit;

    wmma::fragment<wmma::accumulator, 16, 16, 16, float> acc[2][2];
    #pragma unroll
    for (int i = 0; i < 2; i++)
        #pragma unroll
        for (int j = 0; j < 2; j++) wmma::fill_fragment(acc[i][j], 0.f);

    const int a_m = tid >> 1, a_k = (tid & 1) * 8;
    const int bk_r = tid >> 4, bn_c = (tid & 15) * 4;

    for (int k0 = kbase; k0 < kbase + ksplit; k0 += 16) {
        const float* Ap = A + (size_t)(bm + a_m) * K + k0 + a_k;
        float4 v0 = *(const float4*)Ap;
        float4 v1 = *(const float4*)(Ap + 4);
        float av[8] = {v0.x, v0.y, v0.z, v0.w, v1.x, v1.y, v1.z, v1.w};
        bf16 hb[8], lb[8];
        #pragma unroll
        for (int q = 0; q < 8; q++) {
            bf16 h = __float2bfloat16(av[q]);
            hb[q] = h;
            lb[q] = __float2bfloat16(av[q] - __bfloat162float(h));
        }
        *(uint4*)&Ahi[a_m][a_k] = *(uint4*)hb;
        *(uint4*)&Alo[a_m][a_k] = *(uint4*)lb;
        *(uint2*)&Bh[bk_r][bn_c] =
            *(const uint2*)(Bhi + (size_t)(k0 + bk_r) * HD + bn + bn_c);
        *(uint2*)&Bl[bk_r][bn_c] =
            *(const uint2*)(Blo + (size_t)(k0 + bk_r) * HD + bn + bn_c);
        __syncthreads();

        wmma::fragment<wmma::matrix_a, 16, 16, 16, bf16, wmma::row_major> af[2];
        wmma::fragment<wmma::matrix_b, 16, 16, 16, bf16, wmma::row_major> bf[2];
        wmma::load_matrix_sync(af[0], &Ahi[wm][0], 24);
        wmma::load_matrix_sync(af[1], &Ahi[wm + 16][0], 24);
        wmma::load_matrix_sync(bf[0], &Bh[0][wn], 72);
        wmma::load_matrix_sync(bf[1], &Bh[0][wn + 16], 72);
        #pragma unroll
        for (int i = 0; i < 2; i++)
            #pragma unroll
            for (int j = 0; j < 2; j++)
                wmma::mma_sync(acc[i][j], af[i], bf[j], acc[i][j]);
        wmma::load_matrix_sync(bf[0], &Bl[0][wn], 72);
        wmma::load_matrix_sync(bf[1], &Bl[0][wn + 16], 72);
        #pragma unroll
        for (int i = 0; i < 2; i++)
            #pragma unroll
            for (int j = 0; j < 2; j++)
                wmma::mma_sync(acc[i][j], af[i], bf[j], acc[i][j]);
        wmma::load_matrix_sync(af[0], &Alo[wm][0], 24);
        wmma::load_matrix_sync(af[1], &Alo[wm + 16][0], 24);
        wmma::load_matrix_sync(bf[0], &Bh[0][wn], 72);
        wmma::load_matrix_sync(bf[1], &Bh[0][wn + 16], 72);
        #pragma unroll
        for (int i = 0; i < 2; i++)
            #pragma unroll
            for (int j = 0; j < 2; j++)
                wmma::mma_sync(acc[i][j], af[i], bf[j], acc[i][j]);
        __syncthreads();
    }

    float* Pw = P + (size_t)blockIdx.z * ((size_t)M * HD);
    #pragma unroll
    for (int i = 0; i < 2; i++)
        #pragma unroll
        for (int j = 0; j < 2; j++)
            wmma::store_matrix_sync(
                Pw + (size_t)(bm + wm + 16 * i) * HD + bn + wn + 16 * j,
                acc[i][j], HD, wmma::mem_row_major);
}

// ---------------- persistent GRU recurrent kernel ---------------------------
template<bool WRITE_SEQ>
__global__ __launch_bounds__(384, 1) void k_gru(
    const float* __restrict__ gi, const float* __restrict__ Whh,
    const float* __restrict__ bhh, const float* __restrict__ bih,
    float* __restrict__ hout)
{
    extern __shared__ float sm[];
    float* h_sh = sm;
    float* ghA  = sm + GRROWS * HD;
    float* ghB  = ghA + GRROWS * GD;
    float* gi_sh = ghB + GRROWS * GD;
    __shared__ float bih_sh[GD];
    const int tid = threadIdx.x;
    const int o = tid % 192;
    const int half = tid / 192;
    const int o2 = o + 192;
    const int base = blockIdx.x * GRROWS;
    const int rows = (NS - base < GRROWS) ? (NS - base) : GRROWS;
    float* ghOut = half ? ghB : ghA;

    ull wq[64];
    {
        const ulonglong2* wg0 =
            (const ulonglong2*)(Whh + (size_t)o * HD + half * 64);
        const ulonglong2* wg1 =
            (const ulonglong2*)(Whh + (size_t)o2 * HD + half * 64);
        #pragma unroll
        for (int q = 0; q < 16; q++) {
            ulonglong2 t0 = wg0[q];
            wq[2 * q] = t0.x; wq[2 * q + 1] = t0.y;
        }
        #pragma unroll
        for (int q = 0; q < 16; q++) {
            ulonglong2 t1 = wg1[q];
            wq[32 + 2 * q] = t1.x; wq[32 + 2 * q + 1] = t1.y;
        }
    }
    const float bo0 = half ? 0.f : bhh[o];
    const float bo1 = half ? 0.f : bhh[o2];
    bih_sh[tid] = bih[tid];
    for (int idx = tid; idx < rows * HD; idx += 384) h_sh[idx] = 0.f;

    const int pr = tid / 12, pc = tid % 12;
    const bool pact = (pr < rows);
    {
        const float* src = gi + ((size_t)(base + pr) * TS + 0) * GD;
        if (pact) {
            #pragma unroll
            for (int i = 0; i < 8; i++) {
                int f = pc + 12 * i;
                cp16(gi_sh + pr * GD + f * 4, src + f * 4);
            }
        }
        cp_commit();
    }
    __syncthreads();

    for (int t = 0; t < TS; t++) {
        #pragma unroll 1
        for (int r = 0; r < rows; r += 2) {
            const ulonglong2* hp0 =
                (const ulonglong2*)(h_sh + r * HD + half * 64);
            const ulonglong2* hp1 =
                (const ulonglong2*)(h_sh + (r + 1) * HD + half * 64);
            ull a0 = 0ull, b0 = 0ull, a1 = 0ull, b1 = 0ull;
            #pragma unroll
            for (int q = 0; q < 16; q++) {
                ulonglong2 x0 = hp0[q];
                ulonglong2 x1 = hp1[q];
                ffma2(a0, x0.x, wq[2 * q]);
                ffma2(b0, x0.x, wq[32 + 2 * q]);
                ffma2(a1, x1.x, wq[2 * q]);
                ffma2(b1, x1.x, wq[32 + 2 * q]);
                ffma2(a0, x0.y, wq[2 * q + 1]);
                ffma2(b0, x0.y, wq[32 + 2 * q + 1]);
                ffma2(a1, x1.y, wq[2 * q + 1]);
                ffma2(b1, x1.y, wq[32 + 2 * q + 1]);
            }
            float2 pa0 = unpack2(a0), pb0 = unpack2(b0);
            float2 pa1 = unpack2(a1), pb1 = unpack2(b1);
            ghOut[r * GD + o]        = (pa0.x + pa0.y) + bo0;
            ghOut[r * GD + o2]       = (pb0.x + pb0.y) + bo1;
            ghOut[(r + 1) * GD + o]  = (pa1.x + pa1.y) + bo0;
            ghOut[(r + 1) * GD + o2] = (pb1.x + pb1.y) + bo1;
        }
        cp_wait_all();
        __syncthreads();
        #pragma unroll 1
        for (int idx = tid; idx < rows * HD; idx += 384) {
            int r = idx >> 7, j = idx & 127;
            float gir = gi_sh[r * GD + j]       + bih_sh[j];
            float giz = gi_sh[r * GD + j + 128] + bih_sh[j + 128];
            float gin = gi_sh[r * GD + j + 256] + bih_sh[j + 256];
            float ghr = ghA[r * GD + j]       + ghB[r * GD + j];
            float ghz = ghA[r * GD + j + 128] + ghB[r * GD + j + 128];
            float ghn = ghA[r * GD + j + 256] + ghB[r * GD + j + 256];
            float rg = __fdividef(1.f, 1.f + __expf(-(gir + ghr)));
            float zg = __fdividef(1.f, 1.f + __expf(-(giz + ghz)));
            float a2 = gin + rg * ghn;
            float ng = 1.f - __fdividef(2.f, __expf(2.f * a2) + 1.f);
            float hprev = h_sh[idx];
            float hn = (1.f - zg) * ng + zg * hprev;
            h_sh[idx] = hn;
            if (WRITE_SEQ)
                hout[((size_t)(base + r) * TS + t) * HD + j] = hn;
            else if (t == TS - 1)
                hout[(size_t)(base + r) * HD + j] = hn;
        }
        __syncthreads();
        if (t + 1 < TS) {
            const float* src = gi + ((size_t)(base + pr) * TS + (t + 1)) * GD;
            if (pact) {
                #pragma unroll
                for (int i = 0; i < 8; i++) {
                    int f = pc + 12 * i;
                    cp16(gi_sh + pr * GD + f * 4, src + f * 4);
                }
            }
            cp_commit();
        }
    }
}

// ---------------- small helpers --------------------------------------------
__global__ void k_zero(float* p, int n) {
    int i = blockIdx.x * blockDim.x + threadIdx.x;
    if (i < n) p[i] = 0.f;
}

// row L2-normalize; also emit bf16 hi/lo split of the normalized row
__global__ void k_rownorm(const float* __restrict__ src, float* __restrict__ dst,
                          bf16* __restrict__ hi, bf16* __restrict__ lo)
{
    int row = blockIdx.x * 8 + (threadIdx.x >> 5);
    int lane = threadIdx.x & 31;
    const float4* s4 = (const float4*)(src + (size_t)row * HD);
    float4 v = s4[lane];
    float ss = v.x*v.x + v.y*v.y + v.z*v.z + v.w*v.w;
    #pragma unroll
    for (int off = 16; off; off >>= 1) ss += __shfl_xor_sync(0xffffffffu, ss, off);
    float n = sqrtf(ss);
    float inv = (n > 0.f) ? 1.f / n : 0.f;
    float4 r = make_float4(v.x*inv, v.y*inv, v.z*inv, v.w*inv);
    ((float4*)(dst + (size_t)row * HD))[lane] = r;
    float rv[4] = {r.x, r.y, r.z, r.w};
    bf16 hb[4], lb[4];
    #pragma unroll
    for (int q = 0; q < 4; q++) {
        bf16 h = __float2bfloat16(rv[q]);
        hb[q] = h;
        lb[q] = __float2bfloat16(rv[q] - __bfloat162float(h));
    }
    *(uint2*)(hi + (size_t)row * HD + lane * 4) = *(uint2*)hb;
    *(uint2*)(lo + (size_t)row * HD + lane * 4) = *(uint2*)lb;
}

// cf2 = cf / colZ (row-wise), emitted as bf16 hi/lo
__global__ void k_cfscale(const float* __restrict__ cf,
                          const float* __restrict__ colZ,
                          bf16* __restrict__ hi, bf16* __restrict__ lo)
{
    int row = blockIdx.x * 8 + (threadIdx.x >> 5);
    int lane = threadIdx.x & 31;
    float rz = __fdividef(1.f, colZ[row]);
    float4 v = ((const float4*)(cf + (size_t)row * HD))[lane];
    float rv[4] = {v.x * rz, v.y * rz, v.z * rz, v.w * rz};
    bf16 hb[4], lb[4];
    #pragma unroll
    for (int q = 0; q < 4; q++) {
        bf16 h = __float2bfloat16(rv[q]);
        hb[q] = h;
        lb[q] = __float2bfloat16(rv[q] - __bfloat162float(h));
    }
    *(uint2*)(hi + (size_t)row * HD + lane * 4) = *(uint2*)hb;
    *(uint2*)(lo + (size_t)row * HD + lane * 4) = *(uint2*)lb;
}

// top-K=20 per row of |sim| (diag excluded), jax-stable ties (lowest index).
__global__ __launch_bounds__(256) void k_topk(
    const float* __restrict__ sim, int* __restrict__ tidx,
    float* __restrict__ tval, float* __restrict__ colsum)
{
    int i = blockIdx.x;
    __shared__ float sabs[NS];
    __shared__ float segv[128];
    __shared__ int   segi[128];
    __shared__ float bcv[4];
    __shared__ int   bci[4];
    const int tid = threadIdx.x;
    const float* row = sim + (size_t)i * NS;

    for (int c4 = tid; c4 < NS / 4; c4 += 256) {
        float4 v = *(const float4*)(row + c4 * 4);
        float4 a = make_float4(fabsf(v.x), fabsf(v.y), fabsf(v.z), fabsf(v.w));
        *(float4*)&sabs[c4 * 4] = a;
    }
    __syncthreads();
    if (tid == 0) sabs[i] = -1.f;
    __syncthreads();

    if (tid < 128) {
        float bv = -2.f; int bi = tid * 32;
        #pragma unroll 4
        for (int j = 0; j < 32; j++) {
            float v = sabs[tid * 32 + j];
            if (v > bv) { bv = v; bi = tid * 32 + j; }
        }
        segv[tid] = bv; segi[tid] = bi;
    }
    __syncthreads();

    for (int k = 0; k < NK; k++) {
        if (tid < 128) {
            float bv = segv[tid]; int bi = segi[tid];
            #pragma unroll
            for (int off = 16; off; off >>= 1) {
                float ov = __shfl_down_sync(0xffffffffu, bv, off);
                int   oi = __shfl_down_sync(0xffffffffu, bi, off);
                if (ov > bv || (ov == bv && oi < bi)) { bv = ov; bi = oi; }
            }
            if ((tid & 31) == 0) { bcv[tid >> 5] = bv; bci[tid >> 5] = bi; }
        }
        __syncthreads();
        if (tid < 32) {
            int bi = 0;
            if (tid == 0) {
                float bv = bcv[0]; bi = bci[0];
                #pragma unroll
                for (int w = 1; w < 4; w++)
                    if (bcv[w] > bv || (bcv[w] == bv && bci[w] < bi)) {
                        bv = bcv[w]; bi = bci[w];
                    }
                tidx[i * NK + k] = bi;
                float sv = row[bi];
                tval[i * NK + k] = sv;
                atomicAdd(&colsum[bi], sv);
                sabs[bi] = -2.f;
            }
            bi = __shfl_sync(0xffffffffu, bi, 0);
            __syncwarp();
            int s = bi >> 5;
            int idx = s * 32 + tid;
            float bv2 = sabs[idx]; int bi2 = idx;
            #pragma unroll
            for (int off = 16; off; off >>= 1) {
                float ov = __shfl_down_sync(0xffffffffu, bv2, off);
                int   oi = __shfl_down_sync(0xffffffffu, bi2, off);
                if (ov > bv2 || (ov == bv2 && oi < bi2)) { bv2 = ov; bi2 = oi; }
            }
            if (tid == 0) { segv[s] = bv2; segi[s] = bi2; }
        }
        __syncthreads();
    }
}

__global__ void k_scatter(const int* __restrict__ tidx, const float* __restrict__ tval,
                          const float* __restrict__ g, float* __restrict__ concept)
{
    int i = blockIdx.x, d = threadIdx.x;
    float gv = g[(size_t)i * HD + d];
    #pragma unroll
    for (int k = 0; k < NK; k++) {
        int c = __ldg(&tidx[i * NK + k]);
        float v = __ldg(&tval[i * NK + k]);
        atomicAdd(&concept[(size_t)c * HD + d], v * gv);
    }
}

__global__ void k_diag_valid(const float* __restrict__ colsum, const float* __restrict__ sim,
                             const float* __restrict__ g, float* __restrict__ concept,
                             float* __restrict__ valid)
{
    int j = blockIdx.x, t = threadIdx.x;
    float cs = colsum[j];
    float v = concept[(size_t)j * HD + t];
    if (cs != 0.f) {
        float dg = sim[(size_t)j * NS + j];
        v += dg * g[(size_t)j * HD + t];
        concept[(size_t)j * HD + t] = v;
    }
    float s = v;
    #pragma unroll
    for (int off = 16; off; off >>= 1) s += __shfl_xor_sync(0xffffffffu, s, off);
    __shared__ float ws[4];
    if ((t & 31) == 0) ws[t >> 5] = s;
    __syncthreads();
    if (t == 0) {
        float tot = ws[0] + ws[1] + ws[2] + ws[3];
        valid[j] = (tot != 0.f) ? 1.f : 0.f;
    }
}

__global__ void k_final(const float* __restrict__ fore, const float* __restrict__ indi,
                        const float* __restrict__ Wout, const float* __restrict__ bout,
                        float* __restrict__ out)
{
    int row = blockIdx.x * 8 + (threadIdx.x >> 5);
    int lane = threadIdx.x & 31;
    float4 a = ((const float4*)(fore + (size_t)row * HD))[lane];
    float4 b = ((const float4*)(indi + (size_t)row * HD))[lane];
    float4 w = ((const float4*)Wout)[lane];
    float s = (a.x+b.x)*w.x + (a.y+b.y)*w.y + (a.z+b.z)*w.z + (a.w+b.w)*w.w;
    #pragma unroll
    for (int off = 16; off; off >>= 1) s += __shfl_xor_sync(0xffffffffu, s, off);
    if (lane == 0) out[row] = s + bout[0];
}

// ---------------- driver -----------------------------------------------------
extern "C" void kernel_launch(void* const* d_in, const int* in_sizes, int n_in,
                              void* d_out, int out_size)
{
    const float* x     = (const float*)d_in[0];
    const float* Wih0  = (const float*)d_in[1];
    const float* Whh0  = (const float*)d_in[2];
    const float* bih0  = (const float*)d_in[3];
    const float* bhh0  = (const float*)d_in[4];
    const float* Wih1  = (const float*)d_in[5];
    const float* Whh1  = (const float*)d_in[6];
    const float* bih1  = (const float*)d_in[7];
    const float* bhh1  = (const float*)d_in[8];
    const float* W_hc  = (const float*)d_in[9];
    const float* b_hc  = (const float*)d_in[10];
    const float* W_hs  = (const float*)d_in[11];
    const float* b_hs  = (const float*)d_in[12];
    const float* W_fore= (const float*)d_in[13];
    const float* b_fore= (const float*)d_in[14];
    const float* W_back= (const float*)d_in[15];
    const float* b_back= (const float*)d_in[16];
    const float* W_indi= (const float*)d_in[17];
    const float* b_indi= (const float*)d_in[18];
    const float* W_out = (const float*)d_in[19];
    const float* b_out = (const float*)d_in[20];
    float* out = (float*)d_out;

    float *gi, *h0, *g, *gn, *sim, *colsum, *colZ, *valid, *concept;
    float *cf, *cfn, *hs, *t1, *t2, *t3, *t4, *tval;
    int* tidx;
    bf16 *whi, *wlo, *gnhi, *gnlo, *cfnhi, *cfnlo, *cf2hi, *cf2lo;
    cudaGetSymbolAddress((void**)&gi,      d_gi);
    cudaGetSymbolAddress((void**)&h0,      d_h0);
    cudaGetSymbolAddress((void**)&g,       d_g);
    cudaGetSymbolAddress((void**)&gn,      d_gn);
    cudaGetSymbolAddress((void**)&sim,     d_sim);
    cudaGetSymbolAddress((void**)&tidx,    d_tidx);
    cudaGetSymbolAddress((void**)&tval,    d_tval);
    cudaGetSymbolAddress((void**)&colsum,  d_colsum);
    cudaGetSymbolAddress((void**)&colZ,    d_colZ);
    cudaGetSymbolAddress((void**)&valid,   d_valid);
    cudaGetSymbolAddress((void**)&concept, d_concept);
    cudaGetSymbolAddress((void**)&cf,      d_cf);
    cudaGetSymbolAddress((void**)&cfn,     d_cfn);
    cudaGetSymbolAddress((void**)&hs,      d_hsb);
    cudaGetSymbolAddress((void**)&t1,      d_t1);
    cudaGetSymbolAddress((void**)&t2,      d_t2);
    cudaGetSymbolAddress((void**)&t3,      d_t3);
    cudaGetSymbolAddress((void**)&t4,      d_t4);
    cudaGetSymbolAddress((void**)&whi,     d_Whi);
    cudaGetSymbolAddress((void**)&wlo,     d_Wlo);
    cudaGetSymbolAddress((void**)&gnhi,    d_gnhi);
    cudaGetSymbolAddress((void**)&gnlo,    d_gnlo);
    cudaGetSymbolAddress((void**)&cfnhi,   d_cfnhi);
    cudaGetSymbolAddress((void**)&cfnlo,   d_cfnlo);
    cudaGetSymbolAddress((void**)&cf2hi,   d_cf2hi);
    cudaGetSymbolAddress((void**)&cf2lo,   d_cf2lo);

    const int GRU_SMEM = (GRROWS * HD + 3 * GRROWS * GD) * 4;
    cudaFuncSetAttribute((const void*)k_gru<true>,
                         cudaFuncAttributeMaxDynamicSharedMemorySize, GRU_SMEM);
    cudaFuncSetAttribute((const void*)k_gru<false>,
                         cudaFuncAttributeMaxDynamicSharedMemorySize, GRU_SMEM);

    const int MT = NS * TS;         // 262144
    const int GRU_GRID = (NS + GRROWS - 1) / GRROWS;  // 147

    // Launch order: gru0 is our 4th launch so ncu (-s 5 -c 1, one harness
    // pre-launch) captures the GRU kernel.
    // #1 gi0 = x @ Wih0^T (bias folded into GRU gate phase)
    k_gemm<true><<<dim3(GD / 64, MT / 128), 256>>>(x, Wih0, gi, MT, GD, FI);
    // #2, #3 tiny zeros (needed later)
    k_zero<<<(NS + 255) / 256, 256>>>(colsum, NS);
    k_zero<<<(NS + 255) / 256, 256>>>(colZ, NS);
    // #4 GRU layer 0 (writes full sequence)  <- ncu capture target
    k_gru<true><<<GRU_GRID, 384, GRU_SMEM>>>(gi, Whh0, bhh0, bih0, h0);
    // Wih1 hi/lo split, then gi1 = h0 @ Wih1^T via wmma bf16x3
    k_wsplit<<<(GD * HD + 255) / 256, 256>>>(Wih1, whi, wlo, GD * HD);
    k_wmma_nt<false><<<dim3(GD / 64, MT / 128), 256>>>(
        h0, whi, wlo, nullptr, gi, GD);
    // GRU layer 1 (writes final hidden only -> g)
    k_gru<false><<<GRU_GRID, 384, GRU_SMEM>>>(gi, Whh1, bhh1, bih1, g);

    // concept accumulator zero (before scatter)
    k_zero<<<(NS * HD + 255) / 256, 256>>>(concept, NS * HD);

    // normalized g (fp32 + bf16 hi/lo); sim = gn @ gn^T via wmma bf16x3
    k_rownorm<<<NS / 8, 256>>>(g, gn, gnhi, gnlo);
    k_wmma_nt<false><<<dim3(NS / 64, NS / 128), 256>>>(
        gn, gnhi, gnlo, nullptr, sim, NS);

    // top-K selection + concept aggregation
    k_topk<<<NS, 256>>>(sim, tidx, tval, colsum);
    k_scatter<<<NS, 128>>>(tidx, tval, g, concept);
    k_diag_valid<<<NS, 128>>>(colsum, sim, g, concept, valid);

    // cf = lrelu(concept @ W_hc^T + b_hc) * valid
    k_gemm64<true, false><<<dim3(HD / 64, NS / 64), 256>>>(
        concept, W_hc, b_hc, valid, nullptr, cf, NS, HD, HD);
    k_rownorm<<<NS / 8, 256>>>(cf, cfn, cfnhi, cfnlo);

    // E = exp(gn @ cfn^T) with fused column sums (wmma bf16x3)
    k_wmma_nt<true><<<dim3(NS / 64, NS / 128), 256>>>(
        gn, cfnhi, cfnlo, colZ, sim, NS);

    // cf2 = cf / colZ (bf16 hi/lo); t1 = E @ cf2 (wmma, split-K=8) + reduce
    k_cfscale<<<NS / 8, 256>>>(cf, colZ, cf2hi, cf2lo);
    k_wmma_nn<<<dim3(HD / 64, NS / 128, 8), 256>>>(
        sim, cf2hi, cf2lo, gi, NS, NS, NS / 8);
    k_reduce<<<(NS * HD / 4 + 255) / 256, 256>>>(gi, t1, 8, NS * HD / 4);

    // hs = lrelu(t1 @ W_hs^T + b_hs)
    k_gemm64<true, false><<<dim3(HD / 64, NS / 64), 256>>>(
        t1, W_hs, b_hs, nullptr, nullptr, hs, NS, HD, HD);

    // t3 = g - lrelu(hs @ W_back^T + b_back)
    k_gemm64<true, true><<<dim3(HD / 64, NS / 64), 256>>>(
        hs, W_back, b_back, nullptr, g, t3, NS, HD, HD);
    // t2 = lrelu(hs @ W_fore^T + b_fore)
    k_gemm64<true, false><<<dim3(HD / 64, NS / 64), 256>>>(
        hs, W_fore, b_fore, nullptr, nullptr, t2, NS, HD, HD);
    // t4 = lrelu(t3 @ W_indi^T + b_indi)
    k_gemm64<true, false><<<dim3(HD / 64, NS / 64), 256>>>(
        t3, W_indi, b_indi, nullptr, nullptr, t4, NS, HD, HD);
    k_final<<<NS / 8, 256>>>(t2, t4, W_out, b_out, out);
}

// round 14
// speedup vs baseline: 1.3604x; 1.0035x over previous
#include <cuda_runtime.h>
#include <cuda_bf16.h>
#include <mma.h>
#include <math.h>
#include <stdint.h>
#include <stddef.h>

using namespace nvcuda;

// Problem dims (fixed by the dataset)
#define NS   4096      // batch
#define TS   64        // timesteps
#define FI   32        // input features
#define HD   128       // hidden
#define GD   384       // 3*H
#define NK   20        // top-k
#define SLOPE_F 0.2f
#define GRROWS 28      // batch rows per GRU CTA (147 CTAs -> all 148 SMs)

typedef unsigned long long ull;
typedef __nv_bfloat16 bf16;

// ---------------- f32x2 packed helpers (Blackwell FFMA2) --------------------
__device__ __forceinline__ ull pack2(float lo, float hi) {
    ull r;
    asm("mov.b64 %0, {%1, %2};" : "=l"(r) : "f"(lo), "f"(hi));
    return r;
}
__device__ __forceinline__ float2 unpack2(ull v) {
    float2 r;
    asm("mov.b64 {%0, %1}, %2;" : "=f"(r.x), "=f"(r.y) : "l"(v));
    return r;
}
__device__ __forceinline__ void ffma2(ull& d, ull a, ull b) {
    asm("fma.rn.f32x2 %0, %1, %2, %0;" : "+l"(d) : "l"(a), "l"(b));
}

// ---------------- cp.async helpers -----------------------------------------
__device__ __forceinline__ void cp16(float* dst_sh, const float* src_g) {
    uint32_t d = (uint32_t)__cvta_generic_to_shared(dst_sh);
    asm volatile("cp.async.ca.shared.global [%0], [%1], 16;" :: "r"(d), "l"(src_g));
}
__device__ __forceinline__ void cp_commit() {
    asm volatile("cp.async.commit_group;");
}
__device__ __forceinline__ void cp_wait_all() {
    asm volatile("cp.async.wait_all;");
}

// ---------------- scratch (device globals; no runtime allocation) ----------
__device__ float d_gi[(size_t)NS * TS * GD];
__device__ float d_h0[(size_t)NS * TS * HD];
__device__ float d_g  [NS * HD];
__device__ float d_gn [NS * HD];
__device__ float d_sim[(size_t)NS * NS];
__device__ int   d_tidx[NS * NK];
__device__ float d_tval[NS * NK];
__device__ float d_colsum[NS];
__device__ float d_colZ[NS];
__device__ float d_valid[NS];
__device__ float d_concept[NS * HD];
__device__ float d_cf [NS * HD];
__device__ float d_cfn[NS * HD];
__device__ float d_hsb[NS * HD];
__device__ float d_t1 [NS * HD];
__device__ float d_t2 [NS * HD];
__device__ float d_t3 [NS * HD];
__device__ float d_t4 [NS * HD];
__device__ bf16 d_W0hi[GD * FI];    // Wih0 split
__device__ bf16 d_W0lo[GD * FI];
__device__ bf16 d_Whi[GD * HD];     // Wih1 split
__device__ bf16 d_Wlo[GD * HD];
__device__ bf16 d_gnhi[NS * HD];
__device__ bf16 d_gnlo[NS * HD];
__device__ bf16 d_cfnhi[NS * HD];
__device__ bf16 d_cfnlo[NS * HD];
__device__ bf16 d_cf2hi[NS * HD];
__device__ bf16 d_cf2lo[NS * HD];

// ---------------- fp32 GEMM: 64x64 tile (NS x 128 x 128 head GEMMs) ---------
template<bool ACT, bool SUBPRE>
__global__ __launch_bounds__(256) void k_gemm64(
    const float* __restrict__ A, const float* __restrict__ B,
    const float* __restrict__ bias, const float* __restrict__ rs,
    const float* __restrict__ pre, float* __restrict__ C,
    int M, int N, int K)
{
    __shared__ alignas(16) float As[16][68];
    __shared__ alignas(16) float Bs[16][68];
    const int bm = blockIdx.y * 64, bn = blockIdx.x * 64;
    const int tid = threadIdx.x;
    const int a_m = tid >> 2, a_k = (tid & 3) * 4;
    const int ty = tid >> 4, tx = tid & 15;
    const int m0 = ty * 4, n0 = tx * 4;

    ull acc2[2][4];
    #pragma unroll
    for (int p = 0; p < 2; p++)
        #pragma unroll
        for (int j = 0; j < 4; j++) acc2[p][j] = 0ull;

    float4 ra, rb;
    ra = *(const float4*)(A + (size_t)(bm + a_m) * K + a_k);
    rb = *(const float4*)(B + (size_t)(bn + a_m) * K + a_k);

    for (int k0 = 0; k0 < K; k0 += 16) {
        As[a_k + 0][a_m] = ra.x; As[a_k + 1][a_m] = ra.y;
        As[a_k + 2][a_m] = ra.z; As[a_k + 3][a_m] = ra.w;
        Bs[a_k + 0][a_m] = rb.x; Bs[a_k + 1][a_m] = rb.y;
        Bs[a_k + 2][a_m] = rb.z; Bs[a_k + 3][a_m] = rb.w;
        __syncthreads();
        if (k0 + 16 < K) {
            ra = *(const float4*)(A + (size_t)(bm + a_m) * K + k0 + 16 + a_k);
            rb = *(const float4*)(B + (size_t)(bn + a_m) * K + k0 + 16 + a_k);
        }
        #pragma unroll
        for (int kk = 0; kk < 16; kk++) {
            ulonglong2 aP = *(const ulonglong2*)&As[kk][m0];
            float4 b = *(const float4*)&Bs[kk][n0];
            ull bd0 = pack2(b.x, b.x), bd1 = pack2(b.y, b.y);
            ull bd2 = pack2(b.z, b.z), bd3 = pack2(b.w, b.w);
            ffma2(acc2[0][0], aP.x, bd0); ffma2(acc2[0][1], aP.x, bd1);
            ffma2(acc2[0][2], aP.x, bd2); ffma2(acc2[0][3], aP.x, bd3);
            ffma2(acc2[1][0], aP.y, bd0); ffma2(acc2[1][1], aP.y, bd1);
            ffma2(acc2[1][2], aP.y, bd2); ffma2(acc2[1][3], aP.y, bd3);
        }
        __syncthreads();
    }

    #pragma unroll
    for (int p = 0; p < 2; p++) {
        int rowA = bm + m0 + 2 * p;
        int rowB = rowA + 1;
        float rsA = rs ? rs[rowA] : 1.f;
        float rsB = rs ? rs[rowB] : 1.f;
        float va[4], vb[4];
        #pragma unroll
        for (int j = 0; j < 4; j++) {
            float2 v = unpack2(acc2[p][j]);
            float a = v.x, b = v.y;
            if (bias) { float bj = bias[bn + n0 + j]; a += bj; b += bj; }
            if (ACT) {
                a = a > 0.f ? a : SLOPE_F * a;
                b = b > 0.f ? b : SLOPE_F * b;
            }
            a *= rsA; b *= rsB;
            if (SUBPRE) {
                a = pre[(size_t)rowA * N + bn + n0 + j] - a;
                b = pre[(size_t)rowB * N + bn + n0 + j] - b;
            }
            va[j] = a; vb[j] = b;
        }
        *(float4*)(C + (size_t)rowA * N + bn + n0) =
            make_float4(va[0], va[1], va[2], va[3]);
        *(float4*)(C + (size_t)rowB * N + bn + n0) =
            make_float4(vb[0], vb[1], vb[2], vb[3]);
    }
}

// ---------------- dual fp32 GEMM: fore + back from shared A (hs) ------------
// t2 = lrelu(A @ Wf^T + bf);  t3 = pre - lrelu(A @ Wb^T + bb)
__global__ __launch_bounds__(256) void k_gemm64_dual(
    const float* __restrict__ A,
    const float* __restrict__ Wf, const float* __restrict__ bfv,
    const float* __restrict__ Wb, const float* __restrict__ bbv,
    const float* __restrict__ pre,
    float* __restrict__ Cf, float* __restrict__ Cb,
    int M, int N, int K)
{
    __shared__ alignas(16) float As[16][68];
    __shared__ alignas(16) float BsF[16][68];
    __shared__ alignas(16) float BsB[16][68];
    const int bm = blockIdx.y * 64, bn = blockIdx.x * 64;
    const int tid = threadIdx.x;
    const int a_m = tid >> 2, a_k = (tid & 3) * 4;
    const int ty = tid >> 4, tx = tid & 15;
    const int m0 = ty * 4, n0 = tx * 4;

    ull accF[2][4], accB[2][4];
    #pragma unroll
    for (int p = 0; p < 2; p++)
        #pragma unroll
        for (int j = 0; j < 4; j++) { accF[p][j] = 0ull; accB[p][j] = 0ull; }

    float4 ra, rbf, rbb;
    ra  = *(const float4*)(A  + (size_t)(bm + a_m) * K + a_k);
    rbf = *(const float4*)(Wf + (size_t)(bn + a_m) * K + a_k);
    rbb = *(const float4*)(Wb + (size_t)(bn + a_m) * K + a_k);

    for (int k0 = 0; k0 < K; k0 += 16) {
        As[a_k + 0][a_m] = ra.x; As[a_k + 1][a_m] = ra.y;
        As[a_k + 2][a_m] = ra.z; As[a_k + 3][a_m] = ra.w;
        BsF[a_k + 0][a_m] = rbf.x; BsF[a_k + 1][a_m] = rbf.y;
        BsF[a_k + 2][a_m] = rbf.z; BsF[a_k + 3][a_m] = rbf.w;
        BsB[a_k + 0][a_m] = rbb.x; BsB[a_k + 1][a_m] = rbb.y;
        BsB[a_k + 2][a_m] = rbb.z; BsB[a_k + 3][a_m] = rbb.w;
        __syncthreads();
        if (k0 + 16 < K) {
            ra  = *(const float4*)(A  + (size_t)(bm + a_m) * K + k0 + 16 + a_k);
            rbf = *(const float4*)(Wf + (size_t)(bn + a_m) * K + k0 + 16 + a_k);
            rbb = *(const float4*)(Wb + (size_t)(bn + a_m) * K + k0 + 16 + a_k);
        }
        #pragma unroll
        for (int kk = 0; kk < 16; kk++) {
            ulonglong2 aP = *(const ulonglong2*)&As[kk][m0];
            float4 bf = *(const float4*)&BsF[kk][n0];
            float4 bb = *(const float4*)&BsB[kk][n0];
            ull f0 = pack2(bf.x, bf.x), f1 = pack2(bf.y, bf.y);
            ull f2 = pack2(bf.z, bf.z), f3 = pack2(bf.w, bf.w);
            ull g0 = pack2(bb.x, bb.x), g1 = pack2(bb.y, bb.y);
            ull g2 = pack2(bb.z, bb.z), g3 = pack2(bb.w, bb.w);
            ffma2(accF[0][0], aP.x, f0); ffma2(accF[0][1], aP.x, f1);
            ffma2(accF[0][2], aP.x, f2); ffma2(accF[0][3], aP.x, f3);
            ffma2(accF[1][0], aP.y, f0); ffma2(accF[1][1], aP.y, f1);
            ffma2(accF[1][2], aP.y, f2); ffma2(accF[1][3], aP.y, f3);
            ffma2(accB[0][0], aP.x, g0); ffma2(accB[0][1], aP.x, g1);
            ffma2(accB[0][2], aP.x, g2); ffma2(accB[0][3], aP.x, g3);
            ffma2(accB[1][0], aP.y, g0); ffma2(accB[1][1], aP.y, g1);
            ffma2(accB[1][2], aP.y, g2); ffma2(accB[1][3], aP.y, g3);
        }
        __syncthreads();
    }

    #pragma unroll
    for (int p = 0; p < 2; p++) {
        int rowA = bm + m0 + 2 * p;
        int rowB = rowA + 1;
        float vfA[4], vfB[4], vbA[4], vbB[4];
        #pragma unroll
        for (int j = 0; j < 4; j++) {
            float2 vf = unpack2(accF[p][j]);
            float2 vb = unpack2(accB[p][j]);
            float fa = vf.x + bfv[bn + n0 + j];
            float fb = vf.y + bfv[bn + n0 + j];
            float ba = vb.x + bbv[bn + n0 + j];
            float bb2 = vb.y + bbv[bn + n0 + j];
            fa = fa > 0.f ? fa : SLOPE_F * fa;
            fb = fb > 0.f ? fb : SLOPE_F * fb;
            ba = ba > 0.f ? ba : SLOPE_F * ba;
            bb2 = bb2 > 0.f ? bb2 : SLOPE_F * bb2;
            vfA[j] = fa; vfB[j] = fb;
            vbA[j] = pre[(size_t)rowA * N + bn + n0 + j] - ba;
            vbB[j] = pre[(size_t)rowB * N + bn + n0 + j] - bb2;
        }
        *(float4*)(Cf + (size_t)rowA * N + bn + n0) =
            make_float4(vfA[0], vfA[1], vfA[2], vfA[3]);
        *(float4*)(Cf + (size_t)rowB * N + bn + n0) =
            make_float4(vfB[0], vfB[1], vfB[2], vfB[3]);
        *(float4*)(Cb + (size_t)rowA * N + bn + n0) =
            make_float4(vbA[0], vbA[1], vbA[2], vbA[3]);
        *(float4*)(Cb + (size_t)rowB * N + bn + n0) =
            make_float4(vbB[0], vbB[1], vbB[2], vbB[3]);
    }
}

// reduce over split-K partial slices: C = sum_z P[z]
__global__ void k_reduce(const float* __restrict__ P, float* __restrict__ C,
                         int nslice, int total4)
{
    int i = blockIdx.x * blockDim.x + threadIdx.x;
    if (i >= total4) return;
    size_t b = (size_t)i * 4;
    float4 s = make_float4(0.f, 0.f, 0.f, 0.f);
    for (int z = 0; z < nslice; z++) {
        float4 v = *(const float4*)(P + (size_t)z * total4 * 4 + b);
        s.x += v.x; s.y += v.y; s.z += v.z; s.w += v.w;
    }
    *(float4*)(C + b) = s;
}

// ---------------- bf16 hi/lo split of TWO weight matrices (one launch) ------
__global__ void k_wsplit2(const float* __restrict__ W0,
                          bf16* __restrict__ h0, bf16* __restrict__ l0, int n0,
                          const float* __restrict__ W1,
                          bf16* __restrict__ h1, bf16* __restrict__ l1, int n1)
{
    int i = blockIdx.x * 256 + threadIdx.x;
    if (i < n0) {
        float v = W0[i];
        bf16 h = __float2bfloat16(v);
        h0[i] = h;
        l0[i] = __float2bfloat16(v - __bfloat162float(h));
    } else if (i < n0 + n1) {
        int j = i - n0;
        float v = W1[j];
        bf16 h = __float2bfloat16(v);
        h1[j] = h;
        l1[j] = __float2bfloat16(v - __bfloat162float(h));
    }
}

// ---------------- generic wmma bf16x3:  C = A @ B^T (runtime K) --------------
// A fp32 [M,K] split in-kernel; Bhi/Blo [N,K] bf16 pre-split. Register
// double-buffered global loads. CTA tile 128x64, 8 warps each 32x32.
// EXPCS: C = exp(raw); column sums accumulated into colZacc.
template<bool EXPCS>
__global__ __launch_bounds__(256) void k_wmma_nt(
    const float* __restrict__ A,
    const bf16* __restrict__ Bhi, const bf16* __restrict__ Blo,
    float* __restrict__ colZacc, float* __restrict__ C, int N, int K)
{
    __shared__ alignas(32) bf16 Ahi[128][24];
    __shared__ alignas(32) bf16 Alo[128][24];
    __shared__ alignas(32) bf16 Bh[64][24];
    __shared__ alignas(32) bf16 Bl[64][24];
    __shared__ float colsh[64];
    __shared__ float stag[8][16][16];
    const int bm = blockIdx.y * 128, bn = blockIdx.x * 64;
    const int tid = threadIdx.x, wid = tid >> 5;
    const int lane = tid & 31;
    const int wm = (wid >> 1) * 32, wn = (wid & 1) * 32;

    if (EXPCS && tid < 64) colsh[tid] = 0.f;

    wmma::fragment<wmma::accumulator, 16, 16, 16, float> acc[2][2];
    #pragma unroll
    for (int i = 0; i < 2; i++)
        #pragma unroll
        for (int j = 0; j < 2; j++) wmma::fill_fragment(acc[i][j], 0.f);

    const int a_m = tid >> 1, a_k = (tid & 1) * 8;
    const int b_n = tid >> 2, b_k = (tid & 3) * 4;

    float4 v0, v1;
    uint2 rbh, rbl;
    {
        const float* Ap = A + (size_t)(bm + a_m) * K + a_k;
        v0 = *(const float4*)Ap;
        v1 = *(const float4*)(Ap + 4);
        rbh = *(const uint2*)(Bhi + (size_t)(bn + b_n) * K + b_k);
        rbl = *(const uint2*)(Blo + (size_t)(bn + b_n) * K + b_k);
    }

    for (int k0 = 0; k0 < K; k0 += 16) {
        float av[8] = {v0.x, v0.y, v0.z, v0.w, v1.x, v1.y, v1.z, v1.w};
        bf16 hb[8], lb[8];
        #pragma unroll
        for (int q = 0; q < 8; q++) {
            bf16 h = __float2bfloat16(av[q]);
            hb[q] = h;
            lb[q] = __float2bfloat16(av[q] - __bfloat162float(h));
        }
        *(uint4*)&Ahi[a_m][a_k] = *(uint4*)hb;
        *(uint4*)&Alo[a_m][a_k] = *(uint4*)lb;
        *(uint2*)&Bh[b_n][b_k] = rbh;
        *(uint2*)&Bl[b_n][b_k] = rbl;
        __syncthreads();
        if (k0 + 16 < K) {
            const float* Ap = A + (size_t)(bm + a_m) * K + (k0 + 16) + a_k;
            v0 = *(const float4*)Ap;
            v1 = *(const float4*)(Ap + 4);
            rbh = *(const uint2*)(Bhi + (size_t)(bn + b_n) * K + (k0 + 16) + b_k);
            rbl = *(const uint2*)(Blo + (size_t)(bn + b_n) * K + (k0 + 16) + b_k);
        }

        wmma::fragment<wmma::matrix_a, 16, 16, 16, bf16, wmma::row_major> af[2];
        wmma::fragment<wmma::matrix_b, 16, 16, 16, bf16, wmma::col_major> bfr[2];
        wmma::load_matrix_sync(af[0], &Ahi[wm][0], 24);
        wmma::load_matrix_sync(af[1], &Ahi[wm + 16][0], 24);
        wmma::load_matrix_sync(bfr[0], &Bh[wn][0], 24);
        wmma::load_matrix_sync(bfr[1], &Bh[wn + 16][0], 24);
        #pragma unroll
        for (int i = 0; i < 2; i++)
            #pragma unroll
            for (int j = 0; j < 2; j++)
                wmma::mma_sync(acc[i][j], af[i], bfr[j], acc[i][j]);
        wmma::load_matrix_sync(bfr[0], &Bl[wn][0], 24);
        wmma::load_matrix_sync(bfr[1], &Bl[wn + 16][0], 24);
        #pragma unroll
        for (int i = 0; i < 2; i++)
            #pragma unroll
            for (int j = 0; j < 2; j++)
                wmma::mma_sync(acc[i][j], af[i], bfr[j], acc[i][j]);
        wmma::load_matrix_sync(af[0], &Alo[wm][0], 24);
        wmma::load_matrix_sync(af[1], &Alo[wm + 16][0], 24);
        wmma::load_matrix_sync(bfr[0], &Bh[wn][0], 24);
        wmma::load_matrix_sync(bfr[1], &Bh[wn + 16][0], 24);
        #pragma unroll
        for (int i = 0; i < 2; i++)
            #pragma unroll
            for (int j = 0; j < 2; j++)
                wmma::mma_sync(acc[i][j], af[i], bfr[j], acc[i][j]);
        __syncthreads();
    }

    #pragma unroll
    for (int i = 0; i < 2; i++)
        #pragma unroll
        for (int j = 0; j < 2; j++) {
            if (EXPCS) {
                #pragma unroll
                for (int e = 0; e < acc[i][j].num_elements; e++)
                    acc[i][j].x[e] = __expf(acc[i][j].x[e]);
                wmma::store_matrix_sync(&stag[wid][0][0], acc[i][j], 16,
                                        wmma::mem_row_major);
                __syncwarp();
                if (lane < 16) {
                    float s = 0.f;
                    #pragma unroll
                    for (int r = 0; r < 16; r++) s += stag[wid][r][lane];
                    atomicAdd(&colsh[wn + 16 * j + lane], s);
                }
                __syncwarp();
            }
            wmma::store_matrix_sync(
                C + (size_t)(bm + wm + 16 * i) * N + bn + wn + 16 * j,
                acc[i][j], N, wmma::mem_row_major);
        }

    if (EXPCS) {
        __syncthreads();
        if (tid < 64) atomicAdd(&colZacc[bn + tid], colsh[tid]);
    }
}

// ---------------- wmma bf16x3:  P[z] = A[:, kslice] @ B[kslice, :] -----------
// A fp32 [M,K] split in-kernel; Bhi/Blo [K,128] bf16 row-major pre-split.
// Register double-buffered. CTA tile 128x64; partials at P + z*M*128.
__global__ __launch_bounds__(256) void k_wmma_nn(
    const float* __restrict__ A,
    const bf16* __restrict__ Bhi, const bf16* __restrict__ Blo,
    float* __restrict__ P, int M, int K, int ksplit)
{
    __shared__ alignas(32) bf16 Ahi[128][24];
    __shared__ alignas(32) bf16 Alo[128][24];
    __shared__ alignas(32) bf16 Bh[16][72];
    __shared__ alignas(32) bf16 Bl[16][72];
    const int bm = blockIdx.y * 128, bn = blockIdx.x * 64;
    const int tid = threadIdx.x, wid = tid >> 5;
    const int wm = (wid >> 1) * 32, wn = (wid & 1) * 32;
    const int kbase = blockIdx.z * ksplit;
    const int kend = kbase + ksplit;

    wmma::fragment<wmma::accumulator, 16, 16, 16, float> acc[2][2];
    #pragma unroll
    for (int i = 0; i < 2; i++)
        #pragma unroll
        for (int j = 0; j < 2; j++) wmma::fill_fragment(acc[i][j], 0.f);

    const int a_m = tid >> 1, a_k = (tid & 1) * 8;
    const int bk_r = tid >> 4, bn_c = (tid & 15) * 4;

    float4 v0, v1;
    uint2 rbh, rbl;
    {
        const float* Ap = A + (size_t)(bm + a_m) * K + kbase + a_k;
        v0 = *(const float4*)Ap;
        v1 = *(const float4*)(Ap + 4);
        rbh = *(const uint2*)(Bhi + (size_t)(kbase + bk_r) * HD + bn + bn_c);
        rbl = *(const uint2*)(Blo + (size_t)(kbase + bk_r) * HD + bn + bn_c);
    }

    for (int k0 = kbase; k0 < kend; k0 += 16) {
        float av[8] = {v0.x, v0.y, v0.z, v0.w, v1.x, v1.y, v1.z, v1.w};
        bf16 hb[8], lb[8];
        #pragma unroll
        for (int q = 0; q < 8; q++) {
            bf16 h = __float2bfloat16(av[q]);
            hb[q] = h;
            lb[q] = __float2bfloat16(av[q] - __bfloat162float(h));
        }
        *(uint4*)&Ahi[a_m][a_k] = *(uint4*)hb;
        *(uint4*)&Alo[a_m][a_k] = *(uint4*)lb;
        *(uint2*)&Bh[bk_r][bn_c] = rbh;
        *(uint2*)&Bl[bk_r][bn_c] = rbl;
        __syncthreads();
        if (k0 + 16 < kend) {
            const float* Ap = A + (size_t)(bm + a_m) * K + (k0 + 16) + a_k;
            v0 = *(const float4*)Ap;
            v1 = *(const float4*)(Ap + 4);
            rbh = *(const uint2*)(Bhi + (size_t)(k0 + 16 + bk_r) * HD + bn + bn_c);
            rbl = *(const uint2*)(Blo + (size_t)(k0 + 16 + bk_r) * HD + bn + bn_c);
        }

        wmma::fragment<wmma::matrix_a, 16, 16, 16, bf16, wmma::row_major> af[2];
        wmma::fragment<wmma::matrix_b, 16, 16, 16, bf16, wmma::row_major> bfr[2];
        wmma::load_matrix_sync(af[0], &Ahi[wm][0], 24);
        wmma::load_matrix_sync(af[1], &Ahi[wm + 16][0], 24);
        wmma::load_matrix_sync(bfr[0], &Bh[0][wn], 72);
        wmma::load_matrix_sync(bfr[1], &Bh[0][wn + 16], 72);
        #pragma unroll
        for (int i = 0; i < 2; i++)
            #pragma unroll
            for (int j = 0; j < 2; j++)
                wmma::mma_sync(acc[i][j], af[i], bfr[j], acc[i][j]);
        wmma::load_matrix_sync(bfr[0], &Bl[0][wn], 72);
        wmma::load_matrix_sync(bfr[1], &Bl[0][wn + 16], 72);
        #pragma unroll
        for (int i = 0; i < 2; i++)
            #pragma unroll
            for (int j = 0; j < 2; j++)
                wmma::mma_sync(acc[i][j], af[i], bfr[j], acc[i][j]);
        wmma::load_matrix_sync(af[0], &Alo[wm][0], 24);
        wmma::load_matrix_sync(af[1], &Alo[wm + 16][0], 24);
        wmma::load_matrix_sync(bfr[0], &Bh[0][wn], 72);
        wmma::load_matrix_sync(bfr[1], &Bh[0][wn + 16], 72);
        #pragma unroll
        for (int i = 0; i < 2; i++)
            #pragma unroll
            for (int j = 0; j < 2; j++)
                wmma::mma_sync(acc[i][j], af[i], bfr[j], acc[i][j]);
        __syncthreads();
    }

    float* Pw = P + (size_t)blockIdx.z * ((size_t)M * HD);
    #pragma unroll
    for (int i = 0; i < 2; i++)
        #pragma unroll
        for (int j = 0; j < 2; j++)
            wmma::store_matrix_sync(
                Pw + (size_t)(bm + wm + 16 * i) * HD + bn + wn + 16 * j,
                acc[i][j], HD, wmma::mem_row_major);
}

// ---------------- persistent GRU recurrent kernel ---------------------------
template<bool WRITE_SEQ>
__global__ __launch_bounds__(384, 1) void k_gru(
    const float* __restrict__ gi, const float* __restrict__ Whh,
    const float* __restrict__ bhh, const float* __restrict__ bih,
    float* __restrict__ hout)
{
    extern __shared__ float sm[];
    float* h_sh = sm;
    float* ghA  = sm + GRROWS * HD;
    float* ghB  = ghA + GRROWS * GD;
    float* gi_sh = ghB + GRROWS * GD;
    __shared__ float bih_sh[GD];
    const int tid = threadIdx.x;
    const int o = tid % 192;
    const int half = tid / 192;
    const int o2 = o + 192;
    const int base = blockIdx.x * GRROWS;
    const int rows = (NS - base < GRROWS) ? (NS - base) : GRROWS;
    float* ghOut = half ? ghB : ghA;

    ull wq[64];
    {
        const ulonglong2* wg0 =
            (const ulonglong2*)(Whh + (size_t)o * HD + half * 64);
        const ulonglong2* wg1 =
            (const ulonglong2*)(Whh + (size_t)o2 * HD + half * 64);
        #pragma unroll
        for (int q = 0; q < 16; q++) {
            ulonglong2 t0 = wg0[q];
            wq[2 * q] = t0.x; wq[2 * q + 1] = t0.y;
        }
        #pragma unroll
        for (int q = 0; q < 16; q++) {
            ulonglong2 t1 = wg1[q];
            wq[32 + 2 * q] = t1.x; wq[32 + 2 * q + 1] = t1.y;
        }
    }
    const float bo0 = half ? 0.f : bhh[o];
    const float bo1 = half ? 0.f : bhh[o2];
    bih_sh[tid] = bih[tid];
    for (int idx = tid; idx < rows * HD; idx += 384) h_sh[idx] = 0.f;

    const int pr = tid / 12, pc = tid % 12;
    const bool pact = (pr < rows);
    {
        const float* src = gi + ((size_t)(base + pr) * TS + 0) * GD;
        if (pact) {
            #pragma unroll
            for (int i = 0; i < 8; i++) {
                int f = pc + 12 * i;
                cp16(gi_sh + pr * GD + f * 4, src + f * 4);
            }
        }
        cp_commit();
    }
    __syncthreads();

    for (int t = 0; t < TS; t++) {
        #pragma unroll 1
        for (int r = 0; r < rows; r += 2) {
            const ulonglong2* hp0 =
                (const ulonglong2*)(h_sh + r * HD + half * 64);
            const ulonglong2* hp1 =
                (const ulonglong2*)(h_sh + (r + 1) * HD + half * 64);
            ull a0 = 0ull, b0 = 0ull, a1 = 0ull, b1 = 0ull;
            #pragma unroll
            for (int q = 0; q < 16; q++) {
                ulonglong2 x0 = hp0[q];
                ulonglong2 x1 = hp1[q];
                ffma2(a0, x0.x, wq[2 * q]);
                ffma2(b0, x0.x, wq[32 + 2 * q]);
                ffma2(a1, x1.x, wq[2 * q]);
                ffma2(b1, x1.x, wq[32 + 2 * q]);
                ffma2(a0, x0.y, wq[2 * q + 1]);
                ffma2(b0, x0.y, wq[32 + 2 * q + 1]);
                ffma2(a1, x1.y, wq[2 * q + 1]);
                ffma2(b1, x1.y, wq[32 + 2 * q + 1]);
            }
            float2 pa0 = unpack2(a0), pb0 = unpack2(b0);
            float2 pa1 = unpack2(a1), pb1 = unpack2(b1);
            ghOut[r * GD + o]        = (pa0.x + pa0.y) + bo0;
            ghOut[r * GD + o2]       = (pb0.x + pb0.y) + bo1;
            ghOut[(r + 1) * GD + o]  = (pa1.x + pa1.y) + bo0;
            ghOut[(r + 1) * GD + o2] = (pb1.x + pb1.y) + bo1;
        }
        cp_wait_all();
        __syncthreads();
        #pragma unroll 1
        for (int idx = tid; idx < rows * HD; idx += 384) {
            int r = idx >> 7, j = idx & 127;
            float gir = gi_sh[r * GD + j]       + bih_sh[j];
            float giz = gi_sh[r * GD + j + 128] + bih_sh[j + 128];
            float gin = gi_sh[r * GD + j + 256] + bih_sh[j + 256];
            float ghr = ghA[r * GD + j]       + ghB[r * GD + j];
            float ghz = ghA[r * GD + j + 128] + ghB[r * GD + j + 128];
            float ghn = ghA[r * GD + j + 256] + ghB[r * GD + j + 256];
            float rg = __fdividef(1.f, 1.f + __expf(-(gir + ghr)));
            float zg = __fdividef(1.f, 1.f + __expf(-(giz + ghz)));
            float a2 = gin + rg * ghn;
            float ng = 1.f - __fdividef(2.f, __expf(2.f * a2) + 1.f);
            float hprev = h_sh[idx];
            float hn = (1.f - zg) * ng + zg * hprev;
            h_sh[idx] = hn;
            if (WRITE_SEQ)
                hout[((size_t)(base + r) * TS + t) * HD + j] = hn;
            else if (t == TS - 1)
                hout[(size_t)(base + r) * HD + j] = hn;
        }
        __syncthreads();
        if (t + 1 < TS) {
            const float* src = gi + ((size_t)(base + pr) * TS + (t + 1)) * GD;
            if (pact) {
                #pragma unroll
                for (int i = 0; i < 8; i++) {
                    int f = pc + 12 * i;
                    cp16(gi_sh + pr * GD + f * 4, src + f * 4);
                }
            }
            cp_commit();
        }
    }
}

// ---------------- small helpers --------------------------------------------
__global__ void k_zero(float* p, int n) {
    int i = blockIdx.x * blockDim.x + threadIdx.x;
    if (i < n) p[i] = 0.f;
}

// row L2-normalize; also emit bf16 hi/lo split of the normalized row
__global__ void k_rownorm(const float* __restrict__ src, float* __restrict__ dst,
                          bf16* __restrict__ hi, bf16* __restrict__ lo)
{
    int row = blockIdx.x * 8 + (threadIdx.x >> 5);
    int lane = threadIdx.x & 31;
    const float4* s4 = (const float4*)(src + (size_t)row * HD);
    float4 v = s4[lane];
    float ss = v.x*v.x + v.y*v.y + v.z*v.z + v.w*v.w;
    #pragma unroll
    for (int off = 16; off; off >>= 1) ss += __shfl_xor_sync(0xffffffffu, ss, off);
    float n = sqrtf(ss);
    float inv = (n > 0.f) ? 1.f / n : 0.f;
    float4 r = make_float4(v.x*inv, v.y*inv, v.z*inv, v.w*inv);
    ((float4*)(dst + (size_t)row * HD))[lane] = r;
    float rv[4] = {r.x, r.y, r.z, r.w};
    bf16 hb[4], lb[4];
    #pragma unroll
    for (int q = 0; q < 4; q++) {
        bf16 h = __float2bfloat16(rv[q]);
        hb[q] = h;
        lb[q] = __float2bfloat16(rv[q] - __bfloat162float(h));
    }
    *(uint2*)(hi + (size_t)row * HD + lane * 4) = *(uint2*)hb;
    *(uint2*)(lo + (size_t)row * HD + lane * 4) = *(uint2*)lb;
}

// cf2 = cf / colZ (row-wise), emitted as bf16 hi/lo
__global__ void k_cfscale(const float* __restrict__ cf,
                          const float* __restrict__ colZ,
                          bf16* __restrict__ hi, bf16* __restrict__ lo)
{
    int row = blockIdx.x * 8 + (threadIdx.x >> 5);
    int lane = threadIdx.x & 31;
    float rz = __fdividef(1.f, colZ[row]);
    float4 v = ((const float4*)(cf + (size_t)row * HD))[lane];
    float rv[4] = {v.x * rz, v.y * rz, v.z * rz, v.w * rz};
    bf16 hb[4], lb[4];
    #pragma unroll
    for (int q = 0; q < 4; q++) {
        bf16 h = __float2bfloat16(rv[q]);
        hb[q] = h;
        lb[q] = __float2bfloat16(rv[q] - __bfloat162float(h));
    }
    *(uint2*)(hi + (size_t)row * HD + lane * 4) = *(uint2*)hb;
    *(uint2*)(lo + (size_t)row * HD + lane * 4) = *(uint2*)lb;
}

// top-K=20 per row of |sim| (diag excluded), jax-stable ties (lowest index).
__global__ __launch_bounds__(256) void k_topk(
    const float* __restrict__ sim, int* __restrict__ tidx,
    float* __restrict__ tval, float* __restrict__ colsum)
{
    int i = blockIdx.x;
    __shared__ float sabs[NS];
    __shared__ float segv[128];
    __shared__ int   segi[128];
    __shared__ float bcv[4];
    __shared__ int   bci[4];
    const int tid = threadIdx.x;
    const float* row = sim + (size_t)i * NS;

    for (int c4 = tid; c4 < NS / 4; c4 += 256) {
        float4 v = *(const float4*)(row + c4 * 4);
        float4 a = make_float4(fabsf(v.x), fabsf(v.y), fabsf(v.z), fabsf(v.w));
        *(float4*)&sabs[c4 * 4] = a;
    }
    __syncthreads();
    if (tid == 0) sabs[i] = -1.f;
    __syncthreads();

    if (tid < 128) {
        float bv = -2.f; int bi = tid * 32;
        #pragma unroll 4
        for (int j = 0; j < 32; j++) {
            float v = sabs[tid * 32 + j];
            if (v > bv) { bv = v; bi = tid * 32 + j; }
        }
        segv[tid] = bv; segi[tid] = bi;
    }
    __syncthreads();

    for (int k = 0; k < NK; k++) {
        if (tid < 128) {
            float bv = segv[tid]; int bi = segi[tid];
            #pragma unroll
            for (int off = 16; off; off >>= 1) {
                float ov = __shfl_down_sync(0xffffffffu, bv, off);
                int   oi = __shfl_down_sync(0xffffffffu, bi, off);
                if (ov > bv || (ov == bv && oi < bi)) { bv = ov; bi = oi; }
            }
            if ((tid & 31) == 0) { bcv[tid >> 5] = bv; bci[tid >> 5] = bi; }
        }
        __syncthreads();
        if (tid < 32) {
            int bi = 0;
            if (tid == 0) {
                float bv = bcv[0]; bi = bci[0];
                #pragma unroll
                for (int w = 1; w < 4; w++)
                    if (bcv[w] > bv || (bcv[w] == bv && bci[w] < bi)) {
                        bv = bcv[w]; bi = bci[w];
                    }
                tidx[i * NK + k] = bi;
                float sv = row[bi];
                tval[i * NK + k] = sv;
                atomicAdd(&colsum[bi], sv);
                sabs[bi] = -2.f;
            }
            bi = __shfl_sync(0xffffffffu, bi, 0);
            __syncwarp();
            int s = bi >> 5;
            int idx = s * 32 + tid;
            float bv2 = sabs[idx]; int bi2 = idx;
            #pragma unroll
            for (int off = 16; off; off >>= 1) {
                float ov = __shfl_down_sync(0xffffffffu, bv2, off);
                int   oi = __shfl_down_sync(0xffffffffu, bi2, off);
                if (ov > bv2 || (ov == bv2 && oi < bi2)) { bv2 = ov; bi2 = oi; }
            }
            if (tid == 0) { segv[s] = bv2; segi[s] = bi2; }
        }
        __syncthreads();
    }
}

__global__ void k_scatter(const int* __restrict__ tidx, const float* __restrict__ tval,
                          const float* __restrict__ g, float* __restrict__ concept)
{
    int i = blockIdx.x, d = threadIdx.x;
    float gv = g[(size_t)i * HD + d];
    #pragma unroll
    for (int k = 0; k < NK; k++) {
        int c = __ldg(&tidx[i * NK + k]);
        float v = __ldg(&tval[i * NK + k]);
        atomicAdd(&concept[(size_t)c * HD + d], v * gv);
    }
}

__global__ void k_diag_valid(const float* __restrict__ colsum, const float* __restrict__ sim,
                             const float* __restrict__ g, float* __restrict__ concept,
                             float* __restrict__ valid)
{
    int j = blockIdx.x, t = threadIdx.x;
    float cs = colsum[j];
    float v = concept[(size_t)j * HD + t];
    if (cs != 0.f) {
        float dg = sim[(size_t)j * NS + j];
        v += dg * g[(size_t)j * HD + t];
        concept[(size_t)j * HD + t] = v;
    }
    float s = v;
    #pragma unroll
    for (int off = 16; off; off >>= 1) s += __shfl_xor_sync(0xffffffffu, s, off);
    __shared__ float ws[4];
    if ((t & 31) == 0) ws[t >> 5] = s;
    __syncthreads();
    if (t == 0) {
        float tot = ws[0] + ws[1] + ws[2] + ws[3];
        valid[j] = (tot != 0.f) ? 1.f : 0.f;
    }
}

__global__ void k_final(const float* __restrict__ fore, const float* __restrict__ indi,
                        const float* __restrict__ Wout, const float* __restrict__ bout,
                        float* __restrict__ out)
{
    int row = blockIdx.x * 8 + (threadIdx.x >> 5);
    int lane = threadIdx.x & 31;
    float4 a = ((const float4*)(fore + (size_t)row * HD))[lane];
    float4 b = ((const float4*)(indi + (size_t)row * HD))[lane];
    float4 w = ((const float4*)Wout)[lane];
    float s = (a.x+b.x)*w.x + (a.y+b.y)*w.y + (a.z+b.z)*w.z + (a.w+b.w)*w.w;
    #pragma unroll
    for (int off = 16; off; off >>= 1) s += __shfl_xor_sync(0xffffffffu, s, off);
    if (lane == 0) out[row] = s + bout[0];
}

// ---------------- driver -----------------------------------------------------
extern "C" void kernel_launch(void* const* d_in, const int* in_sizes, int n_in,
                              void* d_out, int out_size)
{
    const float* x     = (const float*)d_in[0];
    const float* Wih0  = (const float*)d_in[1];
    const float* Whh0  = (const float*)d_in[2];
    const float* bih0  = (const float*)d_in[3];
    const float* bhh0  = (const float*)d_in[4];
    const float* Wih1  = (const float*)d_in[5];
    const float* Whh1  = (const float*)d_in[6];
    const float* bih1  = (const float*)d_in[7];
    const float* bhh1  = (const float*)d_in[8];
    const float* W_hc  = (const float*)d_in[9];
    const float* b_hc  = (const float*)d_in[10];
    const float* W_hs  = (const float*)d_in[11];
    const float* b_hs  = (const float*)d_in[12];
    const float* W_fore= (const float*)d_in[13];
    const float* b_fore= (const float*)d_in[14];
    const float* W_back= (const float*)d_in[15];
    const float* b_back= (const float*)d_in[16];
    const float* W_indi= (const float*)d_in[17];
    const float* b_indi= (const float*)d_in[18];
    const float* W_out = (const float*)d_in[19];
    const float* b_out = (const float*)d_in[20];
    float* out = (float*)d_out;

    float *gi, *h0, *g, *gn, *sim, *colsum, *colZ, *valid, *concept;
    float *cf, *cfn, *hs, *t1, *t2, *t3, *t4, *tval;
    int* tidx;
    bf16 *w0hi, *w0lo, *whi, *wlo, *gnhi, *gnlo, *cfnhi, *cfnlo, *cf2hi, *cf2lo;
    cudaGetSymbolAddress((void**)&gi,      d_gi);
    cudaGetSymbolAddress((void**)&h0,      d_h0);
    cudaGetSymbolAddress((void**)&g,       d_g);
    cudaGetSymbolAddress((void**)&gn,      d_gn);
    cudaGetSymbolAddress((void**)&sim,     d_sim);
    cudaGetSymbolAddress((void**)&tidx,    d_tidx);
    cudaGetSymbolAddress((void**)&tval,    d_tval);
    cudaGetSymbolAddress((void**)&colsum,  d_colsum);
    cudaGetSymbolAddress((void**)&colZ,    d_colZ);
    cudaGetSymbolAddress((void**)&valid,   d_valid);
    cudaGetSymbolAddress((void**)&concept, d_concept);
    cudaGetSymbolAddress((void**)&cf,      d_cf);
    cudaGetSymbolAddress((void**)&cfn,     d_cfn);
    cudaGetSymbolAddress((void**)&hs,      d_hsb);
    cudaGetSymbolAddress((void**)&t1,      d_t1);
    cudaGetSymbolAddress((void**)&t2,      d_t2);
    cudaGetSymbolAddress((void**)&t3,      d_t3);
    cudaGetSymbolAddress((void**)&t4,      d_t4);
    cudaGetSymbolAddress((void**)&w0hi,    d_W0hi);
    cudaGetSymbolAddress((void**)&w0lo,    d_W0lo);
    cudaGetSymbolAddress((void**)&whi,     d_Whi);
    cudaGetSymbolAddress((void**)&wlo,     d_Wlo);
    cudaGetSymbolAddress((void**)&gnhi,    d_gnhi);
    cudaGetSymbolAddress((void**)&gnlo,    d_gnlo);
    cudaGetSymbolAddress((void**)&cfnhi,   d_cfnhi);
    cudaGetSymbolAddress((void**)&cfnlo,   d_cfnlo);
    cudaGetSymbolAddress((void**)&cf2hi,   d_cf2hi);
    cudaGetSymbolAddress((void**)&cf2lo,   d_cf2lo);

    const int GRU_SMEM = (GRROWS * HD + 3 * GRROWS * GD) * 4;
    cudaFuncSetAttribute((const void*)k_gru<true>,
                         cudaFuncAttributeMaxDynamicSharedMemorySize, GRU_SMEM);
    cudaFuncSetAttribute((const void*)k_gru<false>,
                         cudaFuncAttributeMaxDynamicSharedMemorySize, GRU_SMEM);

    const int MT = NS * TS;         // 262144
    const int GRU_GRID = (NS + GRROWS - 1) / GRROWS;  // 147

    // Launch order: gru0 is our 4th launch so ncu (-s 5 -c 1, one harness
    // pre-launch) captures the GRU kernel.
    // #1 split both input-weight matrices (one launch)
    k_wsplit2<<<(GD * FI + GD * HD + 255) / 256, 256>>>(
        Wih0, w0hi, w0lo, GD * FI, Wih1, whi, wlo, GD * HD);
    // #2 gi0 = x @ Wih0^T via wmma bf16x3 (K=32)
    k_wmma_nt<false><<<dim3(GD / 64, MT / 128), 256>>>(
        x, w0hi, w0lo, nullptr, gi, GD, FI);
    // #3 zero colsum
    k_zero<<<(NS + 255) / 256, 256>>>(colsum, NS);
    // #4 GRU layer 0 (writes full sequence)  <- ncu capture target
    k_gru<true><<<GRU_GRID, 384, GRU_SMEM>>>(gi, Whh0, bhh0, bih0, h0);
    // gi1 = h0 @ Wih1^T via wmma bf16x3 (K=128)
    k_wmma_nt<false><<<dim3(GD / 64, MT / 128), 256>>>(
        h0, whi, wlo, nullptr, gi, GD, HD);
    // GRU layer 1 (writes final hidden only -> g)
    k_gru<false><<<GRU_GRID, 384, GRU_SMEM>>>(gi, Whh1, bhh1, bih1, g);

    // zeros for later accumulators
    k_zero<<<(NS * HD + 255) / 256, 256>>>(concept, NS * HD);
    k_zero<<<(NS + 255) / 256, 256>>>(colZ, NS);

    // normalized g (fp32 + bf16 hi/lo); sim = gn @ gn^T via wmma bf16x3
    k_rownorm<<<NS / 8, 256>>>(g, gn, gnhi, gnlo);
    k_wmma_nt<false><<<dim3(NS / 64, NS / 128), 256>>>(
        gn, gnhi, gnlo, nullptr, sim, NS, HD);

    // top-K selection + concept aggregation
    k_topk<<<NS, 256>>>(sim, tidx, tval, colsum);
    k_scatter<<<NS, 128>>>(tidx, tval, g, concept);
    k_diag_valid<<<NS, 128>>>(colsum, sim, g, concept, valid);

    // cf = lrelu(concept @ W_hc^T + b_hc) * valid
    k_gemm64<true, false><<<dim3(HD / 64, NS / 64), 256>>>(
        concept, W_hc, b_hc, valid, nullptr, cf, NS, HD, HD);
    k_rownorm<<<NS / 8, 256>>>(cf, cfn, cfnhi, cfnlo);

    // E = exp(gn @ cfn^T) with fused column sums (wmma bf16x3)
    k_wmma_nt<true><<<dim3(NS / 64, NS / 128), 256>>>(
        gn, cfnhi, cfnlo, colZ, sim, NS, HD);

    // cf2 = cf / colZ (bf16 hi/lo); t1 = E @ cf2 (wmma, split-K=8) + reduce
    k_cfscale<<<NS / 8, 256>>>(cf, colZ, cf2hi, cf2lo);
    k_wmma_nn<<<dim3(HD / 64, NS / 128, 8), 256>>>(
        sim, cf2hi, cf2lo, gi, NS, NS, NS / 8);
    k_reduce<<<(NS * HD / 4 + 255) / 256, 256>>>(gi, t1, 8, NS * HD / 4);

    // hs = lrelu(t1 @ W_hs^T + b_hs)
    k_gemm64<true, false><<<dim3(HD / 64, NS / 64), 256>>>(
        t1, W_hs, b_hs, nullptr, nullptr, hs, NS, HD, HD);

    // fused: t2 = lrelu(hs@W_fore^T+b_fore); t3 = g - lrelu(hs@W_back^T+b_back)
    k_gemm64_dual<<<dim3(HD / 64, NS / 64), 256>>>(
        hs, W_fore, b_fore, W_back, b_back, g, t2, t3, NS, HD, HD);
    // t4 = lrelu(t3 @ W_indi^T + b_indi)
    k_gemm64<true, false><<<dim3(HD / 64, NS / 64), 256>>>(
        t3, W_indi, b_indi, nullptr, nullptr, t4, NS, HD, HD);
    k_final<<<NS / 8, 256>>>(t2, t4, W_out, b_out, out);
}